// round 2
// baseline (speedup 1.0000x reference)
#include <cuda_runtime.h>
#include <math.h>
#include <stdint.h>

#define BB 2
#define LL 1024
#define DD 1024
#define HH 6
#define DK 128
#define DV 256
#define KD 768
#define VD 1536
#define TOK (BB*LL)

// ---------------- device scratch (no allocations allowed) ----------------
__device__ __align__(16) float g_q[TOK*KD];
__device__ __align__(16) float g_k[TOK*KD];
__device__ __align__(16) float g_v[TOK*VD];
__device__ __align__(16) float g_gate[TOK*VD];
__device__ __align__(16) float g_qn[BB*HH*LL*DK];
__device__ __align__(16) float g_kn[BB*HH*LL*DK];
__device__ __align__(16) float g_vc[BB*HH*LL*DV];
__device__ __align__(16) float g_eg[BB*HH*LL];
__device__ __align__(16) float g_beta[BB*HH*LL];
__device__ __align__(16) float g_o[TOK*VD];

// ---------------- fp32 SIMT GEMM: C[M,N] = A[M,K] @ B[K,N] ----------------
// Tile 128x64, BK=16, 256 threads, 8x4 per thread.
__global__ void __launch_bounds__(256) sgemm_kernel(
    const float* __restrict__ A, const float* __restrict__ B,
    float* __restrict__ C, int M, int N, int K)
{
    __shared__ float As[16*132];  // [k][m], padded
    __shared__ float Bs[16*68];   // [k][n], padded

    int tid = threadIdx.x;
    int bm = blockIdx.y * 128;
    int bn = blockIdx.x * 64;
    int ty = tid >> 4;   // 0..15 -> rows bm+ty*8..+7
    int tx = tid & 15;   // cols bn+tx*4..+3

    float acc[8][4];
#pragma unroll
    for (int i = 0; i < 8; i++)
#pragma unroll
        for (int j = 0; j < 4; j++) acc[i][j] = 0.f;

    for (int k0 = 0; k0 < K; k0 += 16) {
#pragma unroll
        for (int i = 0; i < 2; i++) {
            int f4 = tid + i*256;          // 0..511
            int r  = f4 >> 2;              // 0..127
            int c4 = (f4 & 3) << 2;        // 0,4,8,12
            float4 a = *(const float4*)(A + (size_t)(bm + r)*K + k0 + c4);
            As[(c4+0)*132 + r] = a.x;
            As[(c4+1)*132 + r] = a.y;
            As[(c4+2)*132 + r] = a.z;
            As[(c4+3)*132 + r] = a.w;
        }
        {
            int kr = tid >> 4;             // 0..15
            int c  = (tid & 15) << 2;      // 0..60
            *(float4*)(Bs + kr*68 + c) =
                *(const float4*)(B + (size_t)(k0 + kr)*N + bn + c);
        }
        __syncthreads();
#pragma unroll
        for (int kk = 0; kk < 16; kk++) {
            float a0[4], a1[4], bv[4];
            *(float4*)a0 = *(const float4*)(As + kk*132 + ty*8);
            *(float4*)a1 = *(const float4*)(As + kk*132 + ty*8 + 4);
            *(float4*)bv = *(const float4*)(Bs + kk*68 + tx*4);
#pragma unroll
            for (int i = 0; i < 4; i++)
#pragma unroll
                for (int j = 0; j < 4; j++) {
                    acc[i][j]   += a0[i]*bv[j];
                    acc[i+4][j] += a1[i]*bv[j];
                }
        }
        __syncthreads();
    }
#pragma unroll
    for (int i = 0; i < 8; i++) {
        float4 o = make_float4(acc[i][0], acc[i][1], acc[i][2], acc[i][3]);
        *(float4*)(C + (size_t)(bm + ty*8 + i)*N + bn + tx*4) = o;
    }
}

// ---------------- beta = sigmoid(x@Wb), eg = exp(-exp(A_log)*softplus(x@Wa+dt_bias))
__global__ void __launch_bounds__(256) betag_kernel(
    const float* __restrict__ x, const float* __restrict__ Wb,
    const float* __restrict__ Wa, const float* __restrict__ A_log,
    const float* __restrict__ dt_bias)
{
    int gw   = blockIdx.x*8 + (threadIdx.x >> 5);  // 0..TOK*HH-1
    int lane = threadIdx.x & 31;
    int row  = gw / HH;
    int h    = gw % HH;
    const float* xr = x + (size_t)row*DD;
    float sb = 0.f, sa = 0.f;
#pragma unroll 4
    for (int d = lane; d < DD; d += 32) {
        float xv = xr[d];
        sb += xv * Wb[d*HH + h];
        sa += xv * Wa[d*HH + h];
    }
#pragma unroll
    for (int off = 16; off; off >>= 1) {
        sb += __shfl_xor_sync(0xffffffffu, sb, off);
        sa += __shfl_xor_sync(0xffffffffu, sa, off);
    }
    if (lane == 0) {
        int b = row >> 10, t = row & 1023;
        float beta = 1.f / (1.f + expf(-sb));
        float z = sa + dt_bias[h];
        float sp = (z > 20.f) ? z : log1pf(expf(z));
        float eg = expf(-expf(A_log[h]) * sp);
        int idx = (b*HH + h)*LL + t;
        g_beta[idx] = beta;
        g_eg[idx]   = eg;
    }
}

// ---------------- causal depthwise conv(4) + SiLU + L2norm for q/k ----------
// One warp per (b,h,t). Lane handles 4 channels. Output layout [B,H,L,DK].
__global__ void __launch_bounds__(256) convqk_kernel(
    const float* __restrict__ P, const float* __restrict__ W,
    float* __restrict__ Out, float qscale)
{
    int gw   = blockIdx.x*8 + (threadIdx.x >> 5);  // b*HH*LL + h*LL + t
    int lane = threadIdx.x & 31;
    int b   = gw / (HH*LL);
    int rem = gw % (HH*LL);
    int h   = rem / LL;
    int t   = rem % LL;
    int c0  = h*DK + lane*4;

    float w0[4], w1[4], w2[4], w3[4];
    *(float4*)w0 = *(const float4*)(W + (c0+0)*4);
    *(float4*)w1 = *(const float4*)(W + (c0+1)*4);
    *(float4*)w2 = *(const float4*)(W + (c0+2)*4);
    *(float4*)w3 = *(const float4*)(W + (c0+3)*4);

    float a[4] = {0.f, 0.f, 0.f, 0.f};
#pragma unroll
    for (int j = 0; j < 4; j++) {
        int tt = t - 3 + j;
        if (tt >= 0) {
            float4 xv = *(const float4*)(P + (size_t)(b*LL + tt)*KD + c0);
            a[0] += xv.x * w0[j];
            a[1] += xv.y * w1[j];
            a[2] += xv.z * w2[j];
            a[3] += xv.w * w3[j];
        }
    }
#pragma unroll
    for (int i = 0; i < 4; i++) { float z = a[i]; a[i] = z / (1.f + expf(-z)); }
    float ss = a[0]*a[0] + a[1]*a[1] + a[2]*a[2] + a[3]*a[3];
#pragma unroll
    for (int off = 16; off; off >>= 1) ss += __shfl_xor_sync(0xffffffffu, ss, off);
    float r = rsqrtf(ss + 1e-12f) * qscale;
    float4 o = make_float4(a[0]*r, a[1]*r, a[2]*r, a[3]*r);
    *(float4*)(Out + ((size_t)(b*HH + h)*LL + t)*DK + lane*4) = o;
}

// ---------------- causal depthwise conv(4) + SiLU for v -> [B,H,L,DV] ------
__global__ void __launch_bounds__(256) convv_kernel(
    const float* __restrict__ P, const float* __restrict__ W)
{
    int idx = blockIdx.x*256 + threadIdx.x;     // 0 .. TOK*(VD/4)-1
    int c4i = idx % (VD/4);                     // 0..383   (FIXED)
    int row = idx / (VD/4);                     // token 0..TOK-1
    int c0  = c4i*4;
    int b = row >> 10, t = row & 1023;

    float w0[4], w1[4], w2[4], w3[4];
    *(float4*)w0 = *(const float4*)(W + (c0+0)*4);
    *(float4*)w1 = *(const float4*)(W + (c0+1)*4);
    *(float4*)w2 = *(const float4*)(W + (c0+2)*4);
    *(float4*)w3 = *(const float4*)(W + (c0+3)*4);

    float a[4] = {0.f, 0.f, 0.f, 0.f};
#pragma unroll
    for (int j = 0; j < 4; j++) {
        int tt = t - 3 + j;
        if (tt >= 0) {
            float4 xv = *(const float4*)(P + (size_t)(b*LL + tt)*VD + c0);
            a[0] += xv.x * w0[j];
            a[1] += xv.y * w1[j];
            a[2] += xv.z * w2[j];
            a[3] += xv.w * w3[j];
        }
    }
#pragma unroll
    for (int i = 0; i < 4; i++) { float z = a[i]; a[i] = z / (1.f + expf(-z)); }
    int h  = c0 / DV;
    int dv = c0 % DV;
    float4 o = make_float4(a[0], a[1], a[2], a[3]);
    *(float4*)(g_vc + ((size_t)(b*HH + h)*LL + t)*DV + dv) = o;
}

// ---------------- delta-rule scan: one warp per (b,h,v) column --------------
// Lane owns 4 consecutive k entries of S[:,v]. Writes o to [B,L,H*DV].
__global__ void __launch_bounds__(256) scan_kernel(float* __restrict__ sOut)
{
    int gw   = blockIdx.x*8 + (threadIdx.x >> 5);  // 0..BB*HH*DV-1
    int lane = threadIdx.x & 31;
    int b   = gw / (HH*DV);
    int rem = gw % (HH*DV);
    int h   = rem / DV;
    int v   = rem % DV;
    size_t bh = (size_t)(b*HH + h);

    const float4* q4 = (const float4*)(g_qn + bh*LL*DK) + lane;
    const float4* k4 = (const float4*)(g_kn + bh*LL*DK) + lane;
    const float* vb  = g_vc + bh*LL*DV + v;
    const float* egb = g_eg + bh*LL;
    const float* btb = g_beta + bh*LL;
    float* ob = g_o + (size_t)b*LL*VD + h*DV + v;

    float4 s = make_float4(0.f, 0.f, 0.f, 0.f);
    for (int t = 0; t < LL; t++) {
        float4 kt = k4[(size_t)t*32];
        float4 qt = q4[(size_t)t*32];
        float eg = egb[t];
        float bt = btb[t];
        float vt = vb[(size_t)t*DV];
        s.x *= eg; s.y *= eg; s.z *= eg; s.w *= eg;
        float corr = kt.x*s.x + kt.y*s.y + kt.z*s.z + kt.w*s.w;
#pragma unroll
        for (int off = 16; off; off >>= 1) corr += __shfl_xor_sync(0xffffffffu, corr, off);
        float u = (vt - corr) * bt;
        s.x += kt.x*u; s.y += kt.y*u; s.z += kt.z*u; s.w += kt.w*u;
        float o = qt.x*s.x + qt.y*s.y + qt.z*s.z + qt.w*s.w;
#pragma unroll
        for (int off = 16; off; off >>= 1) o += __shfl_xor_sync(0xffffffffu, o, off);
        if (lane == 0) ob[(size_t)t*VD] = o;
    }
    if (sOut) {
        int k0 = lane*4;
        size_t base = bh*DK*DV + v;
        sOut[base + (size_t)(k0+0)*DV] = s.x;
        sOut[base + (size_t)(k0+1)*DV] = s.y;
        sOut[base + (size_t)(k0+2)*DV] = s.z;
        sOut[base + (size_t)(k0+3)*DV] = s.w;
    }
}

// ---------------- gated RMS norm epilogue (in-place on g_o) -----------------
__global__ void __launch_bounds__(256) gate_kernel(const float* __restrict__ norm_w)
{
    int gw   = blockIdx.x*8 + (threadIdx.x >> 5);  // 0..TOK*HH-1
    int lane = threadIdx.x & 31;
    int row  = gw / HH;
    int h    = gw % HH;
    size_t base = (size_t)row*VD + h*DV;

    float4 o0 = *(float4*)(g_o + base + lane*4);
    float4 o1 = *(float4*)(g_o + base + 128 + lane*4);
    float ss = o0.x*o0.x + o0.y*o0.y + o0.z*o0.z + o0.w*o0.w
             + o1.x*o1.x + o1.y*o1.y + o1.z*o1.z + o1.w*o1.w;
#pragma unroll
    for (int off = 16; off; off >>= 1) ss += __shfl_xor_sync(0xffffffffu, ss, off);
    float r = rsqrtf(ss * (1.f/DV) + 1e-5f);

    float4 gt0 = *(const float4*)(g_gate + base + lane*4);
    float4 gt1 = *(const float4*)(g_gate + base + 128 + lane*4);
    float4 nw0 = *(const float4*)(norm_w + lane*4);
    float4 nw1 = *(const float4*)(norm_w + 128 + lane*4);

    o0.x = o0.x * r * nw0.x * (gt0.x / (1.f + expf(-gt0.x)));
    o0.y = o0.y * r * nw0.y * (gt0.y / (1.f + expf(-gt0.y)));
    o0.z = o0.z * r * nw0.z * (gt0.z / (1.f + expf(-gt0.z)));
    o0.w = o0.w * r * nw0.w * (gt0.w / (1.f + expf(-gt0.w)));
    o1.x = o1.x * r * nw1.x * (gt1.x / (1.f + expf(-gt1.x)));
    o1.y = o1.y * r * nw1.y * (gt1.y / (1.f + expf(-gt1.y)));
    o1.z = o1.z * r * nw1.z * (gt1.z / (1.f + expf(-gt1.z)));
    o1.w = o1.w * r * nw1.w * (gt1.w / (1.f + expf(-gt1.w)));

    *(float4*)(g_o + base + lane*4)       = o0;
    *(float4*)(g_o + base + 128 + lane*4) = o1;
}

// ---------------- launcher ---------------------------------------------------
extern "C" void kernel_launch(void* const* d_in, const int* in_sizes, int n_in,
                              void* d_out, int out_size)
{
    const float* x       = (const float*)d_in[0];
    const float* Wq      = (const float*)d_in[1];
    const float* Wk      = (const float*)d_in[2];
    const float* Wv      = (const float*)d_in[3];
    const float* Wb      = (const float*)d_in[4];
    const float* Wa      = (const float*)d_in[5];
    const float* A_log   = (const float*)d_in[6];
    const float* dt_bias = (const float*)d_in[7];
    const float* conv_q  = (const float*)d_in[8];
    const float* conv_k  = (const float*)d_in[9];
    const float* conv_v  = (const float*)d_in[10];
    const float* Wg      = (const float*)d_in[11];
    const float* norm_w  = (const float*)d_in[12];
    const float* Wo      = (const float*)d_in[13];
    float* out = (float*)d_out;

    float *pq, *pk, *pv, *pg, *pqn, *pkn, *po;
    cudaGetSymbolAddress((void**)&pq,  g_q);
    cudaGetSymbolAddress((void**)&pk,  g_k);
    cudaGetSymbolAddress((void**)&pv,  g_v);
    cudaGetSymbolAddress((void**)&pg,  g_gate);
    cudaGetSymbolAddress((void**)&pqn, g_qn);
    cudaGetSymbolAddress((void**)&pkn, g_kn);
    cudaGetSymbolAddress((void**)&po,  g_o);

    dim3 blk(256);
    // projections
    sgemm_kernel<<<dim3(KD/64, TOK/128), blk>>>(x, Wq, pq, TOK, KD, DD);
    sgemm_kernel<<<dim3(KD/64, TOK/128), blk>>>(x, Wk, pk, TOK, KD, DD);
    sgemm_kernel<<<dim3(VD/64, TOK/128), blk>>>(x, Wv, pv, TOK, VD, DD);
    sgemm_kernel<<<dim3(VD/64, TOK/128), blk>>>(x, Wg, pg, TOK, VD, DD);
    // beta / decay
    betag_kernel<<<TOK*HH/8, blk>>>(x, Wb, Wa, A_log, dt_bias);
    // conv + silu (+ l2norm for q/k)
    convqk_kernel<<<BB*HH*LL/8, blk>>>(pq, conv_q, pqn, 0.08838834764831845f);
    convqk_kernel<<<BB*HH*LL/8, blk>>>(pk, conv_k, pkn, 1.0f);
    convv_kernel<<<TOK*(VD/4)/256, blk>>>(pv, conv_v);
    // scan (also writes final state S if out buffer covers it)
    float* sOut = (out_size >= TOK*DD + BB*HH*DK*DV) ? (out + (size_t)TOK*DD) : nullptr;
    scan_kernel<<<BB*HH*DV/8, blk>>>(sOut);
    // gated rms-norm epilogue
    gate_kernel<<<TOK*HH/8, blk>>>(norm_w);
    // output projection directly into d_out
    sgemm_kernel<<<dim3(DD/64, TOK/128), blk>>>(po, Wo, out, TOK, DD, VD);
}

// round 4
// speedup vs baseline: 1.4056x; 1.4056x over previous
#include <cuda_runtime.h>
#include <cuda_bf16.h>
#include <math.h>
#include <stdint.h>

#define BB 2
#define LL 1024
#define DD 1024
#define HH 6
#define DK 128
#define DV 256
#define KD 768
#define VD 1536
#define TOK (BB*LL)

// ---------------- device scratch ----------------
__device__ __align__(16) float g_q[TOK*KD];
__device__ __align__(16) float g_k[TOK*KD];
__device__ __align__(16) float g_v[TOK*VD];
__device__ __align__(16) float g_gate[TOK*VD];
__device__ __align__(16) float g_qn[BB*HH*LL*DK];
__device__ __align__(16) float g_kn[BB*HH*LL*DK];
__device__ __align__(16) float g_vc[BB*HH*LL*DV];
__device__ __align__(16) float g_eg[BB*HH*LL];
__device__ __align__(16) float g_beta[BB*HH*LL];
__device__ __align__(16) float g_o[TOK*VD];

// bf16 split buffers
__device__ __align__(16) __nv_bfloat16 g_xh[TOK*DD],  g_xl[TOK*DD];
__device__ __align__(16) __nv_bfloat16 g_wqh[KD*DD],  g_wql[KD*DD];
__device__ __align__(16) __nv_bfloat16 g_wkh[KD*DD],  g_wkl[KD*DD];
__device__ __align__(16) __nv_bfloat16 g_wvh[VD*DD],  g_wvl[VD*DD];
__device__ __align__(16) __nv_bfloat16 g_wgh[VD*DD],  g_wgl[VD*DD];
__device__ __align__(16) __nv_bfloat16 g_woh[DD*VD],  g_wol[DD*VD];
__device__ __align__(16) __nv_bfloat16 g_oh[TOK*VD],  g_ol[TOK*VD];

// ---------------- helpers ----------------
__device__ __forceinline__ uint32_t smem_u32(const void* p) {
    uint32_t a;
    asm("{ .reg .u64 t; cvta.to.shared.u64 t, %1; cvt.u32.u64 %0, t; }" : "=r"(a) : "l"(p));
    return a;
}

#define MMA_BF16(d, a, b0v, b1v) \
    asm volatile("mma.sync.aligned.m16n8k16.row.col.f32.bf16.bf16.f32 " \
        "{%0,%1,%2,%3},{%4,%5,%6,%7},{%8,%9},{%0,%1,%2,%3};" \
        : "+f"(d[0]), "+f"(d[1]), "+f"(d[2]), "+f"(d[3]) \
        : "r"(a[0]), "r"(a[1]), "r"(a[2]), "r"(a[3]), "r"(b0v), "r"(b1v))

#define LDMATRIX_X4(r0, r1, r2, r3, addr) \
    asm volatile("ldmatrix.sync.aligned.m8n8.x4.shared.b16 {%0,%1,%2,%3}, [%4];" \
        : "=r"(r0), "=r"(r1), "=r"(r2), "=r"(r3) : "r"(addr))

// Issue cp.async for one K-chunk (BK=32) of all 4 operand tiles.
// smem layout per buffer: [Ah 8KB][Al 8KB][Bh 8KB][Bl 8KB], 64B rows,
// 16B-chunk XOR swizzle: phys_chunk = chunk ^ (row & 3).
__device__ __forceinline__ void issue_chunk(
    int tid, int m0, int n0, int K, int c, uint32_t sb,
    const __nv_bfloat16* Ah, const __nv_bfloat16* Al,
    const __nv_bfloat16* Bh, const __nv_bfloat16* Bl)
{
    int k0 = c << 5;
    uint32_t bufo = (uint32_t)(c & 1) * 32768u;
#pragma unroll
    for (int it = 0; it < 8; it++) {
        const int buf = it >> 1;
        int idx = tid + (it << 8);
        int r   = (idx >> 2) & 127;
        int cc  = idx & 3;
        const __nv_bfloat16* s = (buf == 0) ? Ah : (buf == 1) ? Al : (buf == 2) ? Bh : Bl;
        int rowg = ((buf < 2) ? m0 : n0) + r;
        const void* g = s + (size_t)rowg * K + k0 + (cc << 3);
        uint32_t sa = sb + bufo + ((uint32_t)buf << 13)
                    + (uint32_t)(r * 64 + ((cc ^ (r & 3)) << 4));
        asm volatile("cp.async.cg.shared.global [%0], [%1], 16;" :: "r"(sa), "l"(g));
    }
    asm volatile("cp.async.commit_group;");
}

// ---------------- bf16x3 mma.sync GEMM: C[M,N] = A[M,K] @ Bt[N,K]^T ---------
// Grid (N/128, M/128), 256 threads, dyn smem = 2*32KB.
__global__ void __launch_bounds__(256) gemm_mma_bf16x3(
    const __nv_bfloat16* __restrict__ Ah, const __nv_bfloat16* __restrict__ Al,
    const __nv_bfloat16* __restrict__ Bh, const __nv_bfloat16* __restrict__ Bl,
    float* __restrict__ C, int M, int N, int K)
{
    extern __shared__ char smem[];
    uint32_t sb = smem_u32(smem);
    int tid = threadIdx.x, lane = tid & 31, wid = tid >> 5;
    int m0 = blockIdx.y * 128, n0 = blockIdx.x * 128;
    int wm = (wid >> 2) * 64, wn = (wid & 3) * 32;

    float acc[4][4][4];
#pragma unroll
    for (int i = 0; i < 4; i++)
#pragma unroll
        for (int j = 0; j < 4; j++)
#pragma unroll
            for (int r = 0; r < 4; r++) acc[i][j][r] = 0.f;

    const int nch = K >> 5;
    issue_chunk(tid, m0, n0, K, 0, sb, Ah, Al, Bh, Bl);

    // ldmatrix lane address components (within a buffer)
    int a_row_l = lane & 15;           // + wm + 16*mf
    int a_kh    = lane >> 4;           // k-half select
    int b_row_l = ((lane >> 4) << 3) + (lane & 7);  // + wn + 16*npair
    int b_kh    = (lane >> 3) & 1;

    for (int c = 0; c < nch; c++) {
        if (c + 1 < nch) {
            issue_chunk(tid, m0, n0, K, c + 1, sb, Ah, Al, Bh, Bl);
            asm volatile("cp.async.wait_group 1;");
        } else {
            asm volatile("cp.async.wait_group 0;");
        }
        __syncthreads();

        uint32_t bufo = sb + (uint32_t)(c & 1) * 32768u;
#pragma unroll 1
        for (int ks = 0; ks < 2; ks++) {
            uint32_t ah[4][4], al[4][4], bh[2][4], bl[2][4];
#pragma unroll
            for (int mf = 0; mf < 4; mf++) {
                int row = wm + mf * 16 + a_row_l;
                int ch  = (ks * 2 + a_kh) ^ (row & 3);
                uint32_t ad = bufo + (uint32_t)(row * 64 + ch * 16);
                LDMATRIX_X4(ah[mf][0], ah[mf][1], ah[mf][2], ah[mf][3], ad);
                LDMATRIX_X4(al[mf][0], al[mf][1], al[mf][2], al[mf][3], ad + 8192u);
            }
#pragma unroll
            for (int np = 0; np < 2; np++) {
                int row = wn + np * 16 + b_row_l;
                int ch  = (ks * 2 + b_kh) ^ (row & 3);
                uint32_t bd = bufo + 16384u + (uint32_t)(row * 64 + ch * 16);
                LDMATRIX_X4(bh[np][0], bh[np][1], bh[np][2], bh[np][3], bd);
                LDMATRIX_X4(bl[np][0], bl[np][1], bl[np][2], bl[np][3], bd + 8192u);
            }
#pragma unroll
            for (int mf = 0; mf < 4; mf++)
#pragma unroll
                for (int nf = 0; nf < 4; nf++) {
                    int np = nf >> 1, wh = (nf & 1) * 2;
                    MMA_BF16(acc[mf][nf], ah[mf], bh[np][wh], bh[np][wh + 1]);
                    MMA_BF16(acc[mf][nf], ah[mf], bl[np][wh], bl[np][wh + 1]);
                    MMA_BF16(acc[mf][nf], al[mf], bh[np][wh], bh[np][wh + 1]);
                }
        }
        __syncthreads();
    }

    // epilogue
#pragma unroll
    for (int mf = 0; mf < 4; mf++) {
        int row = m0 + wm + mf * 16 + (lane >> 2);
#pragma unroll
        for (int nf = 0; nf < 4; nf++) {
            int col = n0 + wn + nf * 8 + (lane & 3) * 2;
            *(float2*)(C + (size_t)row * N + col) =
                make_float2(acc[mf][nf][0], acc[mf][nf][1]);
            *(float2*)(C + (size_t)(row + 8) * N + col) =
                make_float2(acc[mf][nf][2], acc[mf][nf][3]);
        }
    }
}

// ---------------- split x into bf16 hi/lo -----------------------------------
__global__ void __launch_bounds__(256) splitx_kernel(const float* __restrict__ x)
{
    int i = (blockIdx.x * 256 + threadIdx.x) * 4;
    float4 v = *(const float4*)(x + i);
    __nv_bfloat16 h0 = __float2bfloat16(v.x), h1 = __float2bfloat16(v.y);
    __nv_bfloat16 h2 = __float2bfloat16(v.z), h3 = __float2bfloat16(v.w);
    __nv_bfloat16 l0 = __float2bfloat16(v.x - __bfloat162float(h0));
    __nv_bfloat16 l1 = __float2bfloat16(v.y - __bfloat162float(h1));
    __nv_bfloat16 l2 = __float2bfloat16(v.z - __bfloat162float(h2));
    __nv_bfloat16 l3 = __float2bfloat16(v.w - __bfloat162float(h3));
    *(__nv_bfloat162*)(g_xh + i)     = __nv_bfloat162(h0, h1);
    *(__nv_bfloat162*)(g_xh + i + 2) = __nv_bfloat162(h2, h3);
    *(__nv_bfloat162*)(g_xl + i)     = __nv_bfloat162(l0, l1);
    *(__nv_bfloat162*)(g_xl + i + 2) = __nv_bfloat162(l2, l3);
}

// ---------------- transpose + split weight W[K,N] -> Th/Tl [N,K] ------------
__global__ void __launch_bounds__(256) wsplit_kernel(
    const float* __restrict__ W, __nv_bfloat16* __restrict__ Th,
    __nv_bfloat16* __restrict__ Tl, int Kd, int Nd)
{
    __shared__ float tile[32][33];
    int tx = threadIdx.x & 31, ty = threadIdx.x >> 5;  // 32x8
    int n = blockIdx.x * 32 + tx;
    int k0 = blockIdx.y * 32;
#pragma unroll
    for (int i = ty; i < 32; i += 8)
        tile[i][tx] = W[(size_t)(k0 + i) * Nd + n];
    __syncthreads();
#pragma unroll
    for (int i = ty; i < 32; i += 8) {
        int row = blockIdx.x * 32 + i;
        float v = tile[tx][i];
        __nv_bfloat16 h = __float2bfloat16(v);
        __nv_bfloat16 l = __float2bfloat16(v - __bfloat162float(h));
        Th[(size_t)row * Kd + k0 + tx] = h;
        Tl[(size_t)row * Kd + k0 + tx] = l;
    }
}

// ---------------- beta / decay ----------------------------------------------
__global__ void __launch_bounds__(256) betag_kernel(
    const float* __restrict__ x, const float* __restrict__ Wb,
    const float* __restrict__ Wa, const float* __restrict__ A_log,
    const float* __restrict__ dt_bias)
{
    int gw   = blockIdx.x*8 + (threadIdx.x >> 5);
    int lane = threadIdx.x & 31;
    int row  = gw / HH;
    int h    = gw % HH;
    const float* xr = x + (size_t)row*DD;
    float sb = 0.f, sa = 0.f;
#pragma unroll 4
    for (int d = lane; d < DD; d += 32) {
        float xv = xr[d];
        sb += xv * Wb[d*HH + h];
        sa += xv * Wa[d*HH + h];
    }
#pragma unroll
    for (int off = 16; off; off >>= 1) {
        sb += __shfl_xor_sync(0xffffffffu, sb, off);
        sa += __shfl_xor_sync(0xffffffffu, sa, off);
    }
    if (lane == 0) {
        int b = row >> 10, t = row & 1023;
        float beta = 1.f / (1.f + expf(-sb));
        float z = sa + dt_bias[h];
        float sp = (z > 20.f) ? z : log1pf(expf(z));
        float eg = expf(-expf(A_log[h]) * sp);
        int idx = (b*HH + h)*LL + t;
        g_beta[idx] = beta;
        g_eg[idx]   = eg;
    }
}

// ---------------- conv+silu+l2norm for q/k ----------------------------------
__global__ void __launch_bounds__(256) convqk_kernel(
    const float* __restrict__ P, const float* __restrict__ W,
    float* __restrict__ Out, float qscale)
{
    int gw   = blockIdx.x*8 + (threadIdx.x >> 5);
    int lane = threadIdx.x & 31;
    int b   = gw / (HH*LL);
    int rem = gw % (HH*LL);
    int h   = rem / LL;
    int t   = rem % LL;
    int c0  = h*DK + lane*4;

    float w0[4], w1[4], w2[4], w3[4];
    *(float4*)w0 = *(const float4*)(W + (c0+0)*4);
    *(float4*)w1 = *(const float4*)(W + (c0+1)*4);
    *(float4*)w2 = *(const float4*)(W + (c0+2)*4);
    *(float4*)w3 = *(const float4*)(W + (c0+3)*4);

    float a[4] = {0.f, 0.f, 0.f, 0.f};
#pragma unroll
    for (int j = 0; j < 4; j++) {
        int tt = t - 3 + j;
        if (tt >= 0) {
            float4 xv = *(const float4*)(P + (size_t)(b*LL + tt)*KD + c0);
            a[0] += xv.x * w0[j];
            a[1] += xv.y * w1[j];
            a[2] += xv.z * w2[j];
            a[3] += xv.w * w3[j];
        }
    }
#pragma unroll
    for (int i = 0; i < 4; i++) { float z = a[i]; a[i] = z / (1.f + expf(-z)); }
    float ss = a[0]*a[0] + a[1]*a[1] + a[2]*a[2] + a[3]*a[3];
#pragma unroll
    for (int off = 16; off; off >>= 1) ss += __shfl_xor_sync(0xffffffffu, ss, off);
    float r = rsqrtf(ss + 1e-12f) * qscale;
    float4 o = make_float4(a[0]*r, a[1]*r, a[2]*r, a[3]*r);
    *(float4*)(Out + ((size_t)(b*HH + h)*LL + t)*DK + lane*4) = o;
}

// ---------------- conv+silu for v -------------------------------------------
__global__ void __launch_bounds__(256) convv_kernel(
    const float* __restrict__ P, const float* __restrict__ W)
{
    int idx = blockIdx.x*256 + threadIdx.x;
    int c4i = idx % (VD/4);
    int row = idx / (VD/4);
    int c0  = c4i*4;
    int b = row >> 10, t = row & 1023;

    float w0[4], w1[4], w2[4], w3[4];
    *(float4*)w0 = *(const float4*)(W + (c0+0)*4);
    *(float4*)w1 = *(const float4*)(W + (c0+1)*4);
    *(float4*)w2 = *(const float4*)(W + (c0+2)*4);
    *(float4*)w3 = *(const float4*)(W + (c0+3)*4);

    float a[4] = {0.f, 0.f, 0.f, 0.f};
#pragma unroll
    for (int j = 0; j < 4; j++) {
        int tt = t - 3 + j;
        if (tt >= 0) {
            float4 xv = *(const float4*)(P + (size_t)(b*LL + tt)*VD + c0);
            a[0] += xv.x * w0[j];
            a[1] += xv.y * w1[j];
            a[2] += xv.z * w2[j];
            a[3] += xv.w * w3[j];
        }
    }
#pragma unroll
    for (int i = 0; i < 4; i++) { float z = a[i]; a[i] = z / (1.f + expf(-z)); }
    int h  = c0 / DV;
    int dv = c0 % DV;
    float4 o = make_float4(a[0], a[1], a[2], a[3]);
    *(float4*)(g_vc + ((size_t)(b*HH + h)*LL + t)*DV + dv) = o;
}

// ---------------- delta-rule scan --------------------------------------------
__global__ void __launch_bounds__(256) scan_kernel(float* __restrict__ sOut)
{
    int gw   = blockIdx.x*8 + (threadIdx.x >> 5);
    int lane = threadIdx.x & 31;
    int b   = gw / (HH*DV);
    int rem = gw % (HH*DV);
    int h   = rem / DV;
    int v   = rem % DV;
    size_t bh = (size_t)(b*HH + h);

    const float4* q4 = (const float4*)(g_qn + bh*LL*DK) + lane;
    const float4* k4 = (const float4*)(g_kn + bh*LL*DK) + lane;
    const float* vb  = g_vc + bh*LL*DV + v;
    const float* egb = g_eg + bh*LL;
    const float* btb = g_beta + bh*LL;
    float* ob = g_o + (size_t)b*LL*VD + h*DV + v;

    float4 s = make_float4(0.f, 0.f, 0.f, 0.f);
    for (int t = 0; t < LL; t++) {
        float4 kt = k4[(size_t)t*32];
        float4 qt = q4[(size_t)t*32];
        float eg = egb[t];
        float bt = btb[t];
        float vt = vb[(size_t)t*DV];
        s.x *= eg; s.y *= eg; s.z *= eg; s.w *= eg;
        float corr = kt.x*s.x + kt.y*s.y + kt.z*s.z + kt.w*s.w;
#pragma unroll
        for (int off = 16; off; off >>= 1) corr += __shfl_xor_sync(0xffffffffu, corr, off);
        float u = (vt - corr) * bt;
        s.x += kt.x*u; s.y += kt.y*u; s.z += kt.z*u; s.w += kt.w*u;
        float o = qt.x*s.x + qt.y*s.y + qt.z*s.z + qt.w*s.w;
#pragma unroll
        for (int off = 16; off; off >>= 1) o += __shfl_xor_sync(0xffffffffu, o, off);
        if (lane == 0) ob[(size_t)t*VD] = o;
    }
    if (sOut) {
        int k0 = lane*4;
        size_t base = bh*DK*DV + v;
        sOut[base + (size_t)(k0+0)*DV] = s.x;
        sOut[base + (size_t)(k0+1)*DV] = s.y;
        sOut[base + (size_t)(k0+2)*DV] = s.z;
        sOut[base + (size_t)(k0+3)*DV] = s.w;
    }
}

// ---------------- gated RMS norm -> bf16 hi/lo -------------------------------
__global__ void __launch_bounds__(256) gate_kernel(const float* __restrict__ norm_w)
{
    int gw   = blockIdx.x*8 + (threadIdx.x >> 5);
    int lane = threadIdx.x & 31;
    int row  = gw / HH;
    int h    = gw % HH;
    size_t base = (size_t)row*VD + h*DV;

    float4 o0 = *(float4*)(g_o + base + lane*4);
    float4 o1 = *(float4*)(g_o + base + 128 + lane*4);
    float ss = o0.x*o0.x + o0.y*o0.y + o0.z*o0.z + o0.w*o0.w
             + o1.x*o1.x + o1.y*o1.y + o1.z*o1.z + o1.w*o1.w;
#pragma unroll
    for (int off = 16; off; off >>= 1) ss += __shfl_xor_sync(0xffffffffu, ss, off);
    float r = rsqrtf(ss * (1.f/DV) + 1e-5f);

    float4 gt0 = *(const float4*)(g_gate + base + lane*4);
    float4 gt1 = *(const float4*)(g_gate + base + 128 + lane*4);
    float4 nw0 = *(const float4*)(norm_w + lane*4);
    float4 nw1 = *(const float4*)(norm_w + 128 + lane*4);

    float f[8];
    f[0] = o0.x * r * nw0.x * (gt0.x / (1.f + expf(-gt0.x)));
    f[1] = o0.y * r * nw0.y * (gt0.y / (1.f + expf(-gt0.y)));
    f[2] = o0.z * r * nw0.z * (gt0.z / (1.f + expf(-gt0.z)));
    f[3] = o0.w * r * nw0.w * (gt0.w / (1.f + expf(-gt0.w)));
    f[4] = o1.x * r * nw1.x * (gt1.x / (1.f + expf(-gt1.x)));
    f[5] = o1.y * r * nw1.y * (gt1.y / (1.f + expf(-gt1.y)));
    f[6] = o1.z * r * nw1.z * (gt1.z / (1.f + expf(-gt1.z)));
    f[7] = o1.w * r * nw1.w * (gt1.w / (1.f + expf(-gt1.w)));

#pragma unroll
    for (int half = 0; half < 2; half++) {
        size_t off = base + half*128 + lane*4;
        __nv_bfloat16 h0 = __float2bfloat16(f[half*4+0]);
        __nv_bfloat16 h1 = __float2bfloat16(f[half*4+1]);
        __nv_bfloat16 h2 = __float2bfloat16(f[half*4+2]);
        __nv_bfloat16 h3 = __float2bfloat16(f[half*4+3]);
        *(__nv_bfloat162*)(g_oh + off)     = __nv_bfloat162(h0, h1);
        *(__nv_bfloat162*)(g_oh + off + 2) = __nv_bfloat162(h2, h3);
        __nv_bfloat16 l0 = __float2bfloat16(f[half*4+0] - __bfloat162float(h0));
        __nv_bfloat16 l1 = __float2bfloat16(f[half*4+1] - __bfloat162float(h1));
        __nv_bfloat16 l2 = __float2bfloat16(f[half*4+2] - __bfloat162float(h2));
        __nv_bfloat16 l3 = __float2bfloat16(f[half*4+3] - __bfloat162float(h3));
        *(__nv_bfloat162*)(g_ol + off)     = __nv_bfloat162(l0, l1);
        *(__nv_bfloat162*)(g_ol + off + 2) = __nv_bfloat162(l2, l3);
    }
}

// ---------------- launcher ---------------------------------------------------
extern "C" void kernel_launch(void* const* d_in, const int* in_sizes, int n_in,
                              void* d_out, int out_size)
{
    const float* x       = (const float*)d_in[0];
    const float* Wq      = (const float*)d_in[1];
    const float* Wk      = (const float*)d_in[2];
    const float* Wv      = (const float*)d_in[3];
    const float* Wb      = (const float*)d_in[4];
    const float* Wa      = (const float*)d_in[5];
    const float* A_log   = (const float*)d_in[6];
    const float* dt_bias = (const float*)d_in[7];
    const float* conv_q  = (const float*)d_in[8];
    const float* conv_k  = (const float*)d_in[9];
    const float* conv_v  = (const float*)d_in[10];
    const float* Wg      = (const float*)d_in[11];
    const float* norm_w  = (const float*)d_in[12];
    const float* Wo      = (const float*)d_in[13];
    float* out = (float*)d_out;

    float *pq, *pk, *pv, *pg, *pqn, *pkn;
    cudaGetSymbolAddress((void**)&pq,  g_q);
    cudaGetSymbolAddress((void**)&pk,  g_k);
    cudaGetSymbolAddress((void**)&pv,  g_v);
    cudaGetSymbolAddress((void**)&pg,  g_gate);
    cudaGetSymbolAddress((void**)&pqn, g_qn);
    cudaGetSymbolAddress((void**)&pkn, g_kn);

    __nv_bfloat16 *xh, *xl, *wqh, *wql, *wkh, *wkl, *wvh, *wvl, *wgh, *wgl, *woh, *wol, *oh, *ol;
    cudaGetSymbolAddress((void**)&xh,  g_xh);  cudaGetSymbolAddress((void**)&xl,  g_xl);
    cudaGetSymbolAddress((void**)&wqh, g_wqh); cudaGetSymbolAddress((void**)&wql, g_wql);
    cudaGetSymbolAddress((void**)&wkh, g_wkh); cudaGetSymbolAddress((void**)&wkl, g_wkl);
    cudaGetSymbolAddress((void**)&wvh, g_wvh); cudaGetSymbolAddress((void**)&wvl, g_wvl);
    cudaGetSymbolAddress((void**)&wgh, g_wgh); cudaGetSymbolAddress((void**)&wgl, g_wgl);
    cudaGetSymbolAddress((void**)&woh, g_woh); cudaGetSymbolAddress((void**)&wol, g_wol);
    cudaGetSymbolAddress((void**)&oh,  g_oh);  cudaGetSymbolAddress((void**)&ol,  g_ol);

    const int GEMM_SMEM = 2 * 32768;
    cudaFuncSetAttribute(gemm_mma_bf16x3,
                         cudaFuncAttributeMaxDynamicSharedMemorySize, GEMM_SMEM);

    dim3 blk(256);
    // precision-split prep
    splitx_kernel<<<TOK*DD/(256*4), blk>>>(x);
    wsplit_kernel<<<dim3(KD/32, DD/32), blk>>>(Wq, wqh, wql, DD, KD);
    wsplit_kernel<<<dim3(KD/32, DD/32), blk>>>(Wk, wkh, wkl, DD, KD);
    wsplit_kernel<<<dim3(VD/32, DD/32), blk>>>(Wv, wvh, wvl, DD, VD);
    wsplit_kernel<<<dim3(VD/32, DD/32), blk>>>(Wg, wgh, wgl, DD, VD);
    wsplit_kernel<<<dim3(DD/32, VD/32), blk>>>(Wo, woh, wol, VD, DD);
    // projections (bf16x3 on HMMA)
    gemm_mma_bf16x3<<<dim3(KD/128, TOK/128), blk, GEMM_SMEM>>>(xh, xl, wqh, wql, pq, TOK, KD, DD);
    gemm_mma_bf16x3<<<dim3(KD/128, TOK/128), blk, GEMM_SMEM>>>(xh, xl, wkh, wkl, pk, TOK, KD, DD);
    gemm_mma_bf16x3<<<dim3(VD/128, TOK/128), blk, GEMM_SMEM>>>(xh, xl, wvh, wvl, pv, TOK, VD, DD);
    gemm_mma_bf16x3<<<dim3(VD/128, TOK/128), blk, GEMM_SMEM>>>(xh, xl, wgh, wgl, pg, TOK, VD, DD);
    // beta / decay
    betag_kernel<<<TOK*HH/8, blk>>>(x, Wb, Wa, A_log, dt_bias);
    // conv + silu (+ l2norm)
    convqk_kernel<<<BB*HH*LL/8, blk>>>(pq, conv_q, pqn, 0.08838834764831845f);
    convqk_kernel<<<BB*HH*LL/8, blk>>>(pk, conv_k, pkn, 1.0f);
    convv_kernel<<<TOK*(VD/4)/256, blk>>>(pv, conv_v);
    // scan
    float* sOut = (out_size >= TOK*DD + BB*HH*DK*DV) ? (out + (size_t)TOK*DD) : nullptr;
    scan_kernel<<<BB*HH*DV/8, blk>>>(sOut);
    // gated rms-norm -> bf16 split
    gate_kernel<<<TOK*HH/8, blk>>>(norm_w);
    // output projection
    gemm_mma_bf16x3<<<dim3(DD/128, TOK/128), blk, GEMM_SMEM>>>(oh, ol, woh, wol, out, TOK, DD, VD);
}

// round 5
// speedup vs baseline: 2.0998x; 1.4938x over previous
#include <cuda_runtime.h>
#include <cuda_bf16.h>
#include <math.h>
#include <stdint.h>

#define BB 2
#define LL 1024
#define DD 1024
#define HH 6
#define DK 128
#define DV 256
#define KD 768
#define VD 1536
#define TOK (BB*LL)
#define NP 4608   // fused projection width: KD + KD + VD + VD

// ---------------- device scratch ----------------
__device__ __align__(16) float g_proj[TOK*NP];      // [q | k | v | gate]
__device__ __align__(16) float g_qn[BB*HH*LL*DK];
__device__ __align__(16) float g_kn[BB*HH*LL*DK];
__device__ __align__(16) float g_vc[BB*HH*LL*DV];
__device__ __align__(16) float g_eg[BB*HH*LL];
__device__ __align__(16) float g_beta[BB*HH*LL];
__device__ __align__(16) float g_o[TOK*VD];

// bf16 split buffers
__device__ __align__(16) __nv_bfloat16 g_xh[TOK*DD],  g_xl[TOK*DD];
__device__ __align__(16) __nv_bfloat16 g_wch[NP*DD],  g_wcl[NP*DD];   // fused W^T
__device__ __align__(16) __nv_bfloat16 g_woh[DD*VD],  g_wol[DD*VD];
__device__ __align__(16) __nv_bfloat16 g_oh[TOK*VD],  g_ol[TOK*VD];

// ---------------- helpers ----------------
__device__ __forceinline__ uint32_t smem_u32(const void* p) {
    uint32_t a;
    asm("{ .reg .u64 t; cvta.to.shared.u64 t, %1; cvt.u32.u64 %0, t; }" : "=r"(a) : "l"(p));
    return a;
}

#define MMA_BF16(d, a, b0v, b1v) \
    asm volatile("mma.sync.aligned.m16n8k16.row.col.f32.bf16.bf16.f32 " \
        "{%0,%1,%2,%3},{%4,%5,%6,%7},{%8,%9},{%0,%1,%2,%3};" \
        : "+f"(d[0]), "+f"(d[1]), "+f"(d[2]), "+f"(d[3]) \
        : "r"(a[0]), "r"(a[1]), "r"(a[2]), "r"(a[3]), "r"(b0v), "r"(b1v))

#define LDMATRIX_X4(r0, r1, r2, r3, addr) \
    asm volatile("ldmatrix.sync.aligned.m8n8.x4.shared.b16 {%0,%1,%2,%3}, [%4];" \
        : "=r"(r0), "=r"(r1), "=r"(r2), "=r"(r3) : "r"(addr))

__device__ __forceinline__ void issue_chunk(
    int tid, int m0, int n0, int K, int c, uint32_t sb,
    const __nv_bfloat16* Ah, const __nv_bfloat16* Al,
    const __nv_bfloat16* Bh, const __nv_bfloat16* Bl)
{
    int k0 = c << 5;
    uint32_t bufo = (uint32_t)(c & 1) * 32768u;
#pragma unroll
    for (int it = 0; it < 8; it++) {
        const int buf = it >> 1;
        int idx = tid + (it << 8);
        int r   = (idx >> 2) & 127;
        int cc  = idx & 3;
        const __nv_bfloat16* s = (buf == 0) ? Ah : (buf == 1) ? Al : (buf == 2) ? Bh : Bl;
        int rowg = ((buf < 2) ? m0 : n0) + r;
        const void* g = s + (size_t)rowg * K + k0 + (cc << 3);
        uint32_t sa = sb + bufo + ((uint32_t)buf << 13)
                    + (uint32_t)(r * 64 + ((cc ^ (r & 3)) << 4));
        asm volatile("cp.async.cg.shared.global [%0], [%1], 16;" :: "r"(sa), "l"(g));
    }
    asm volatile("cp.async.commit_group;");
}

// ---------------- bf16x3 mma.sync GEMM: C[M,N] = A[M,K] @ Bt[N,K]^T ---------
__global__ void __launch_bounds__(256) gemm_mma_bf16x3(
    const __nv_bfloat16* __restrict__ Ah, const __nv_bfloat16* __restrict__ Al,
    const __nv_bfloat16* __restrict__ Bh, const __nv_bfloat16* __restrict__ Bl,
    float* __restrict__ C, int M, int N, int K)
{
    extern __shared__ char smem[];
    uint32_t sb = smem_u32(smem);
    int tid = threadIdx.x, lane = tid & 31, wid = tid >> 5;
    int m0 = blockIdx.y * 128, n0 = blockIdx.x * 128;
    int wm = (wid >> 2) * 64, wn = (wid & 3) * 32;

    float acc[4][4][4];
#pragma unroll
    for (int i = 0; i < 4; i++)
#pragma unroll
        for (int j = 0; j < 4; j++)
#pragma unroll
            for (int r = 0; r < 4; r++) acc[i][j][r] = 0.f;

    const int nch = K >> 5;
    issue_chunk(tid, m0, n0, K, 0, sb, Ah, Al, Bh, Bl);

    int a_row_l = lane & 15;
    int a_kh    = lane >> 4;
    int b_row_l = ((lane >> 4) << 3) + (lane & 7);
    int b_kh    = (lane >> 3) & 1;

    for (int c = 0; c < nch; c++) {
        if (c + 1 < nch) {
            issue_chunk(tid, m0, n0, K, c + 1, sb, Ah, Al, Bh, Bl);
            asm volatile("cp.async.wait_group 1;");
        } else {
            asm volatile("cp.async.wait_group 0;");
        }
        __syncthreads();

        uint32_t bufo = sb + (uint32_t)(c & 1) * 32768u;
#pragma unroll 1
        for (int ks = 0; ks < 2; ks++) {
            uint32_t ah[4][4], al[4][4], bh[2][4], bl[2][4];
#pragma unroll
            for (int mf = 0; mf < 4; mf++) {
                int row = wm + mf * 16 + a_row_l;
                int ch  = (ks * 2 + a_kh) ^ (row & 3);
                uint32_t ad = bufo + (uint32_t)(row * 64 + ch * 16);
                LDMATRIX_X4(ah[mf][0], ah[mf][1], ah[mf][2], ah[mf][3], ad);
                LDMATRIX_X4(al[mf][0], al[mf][1], al[mf][2], al[mf][3], ad + 8192u);
            }
#pragma unroll
            for (int np = 0; np < 2; np++) {
                int row = wn + np * 16 + b_row_l;
                int ch  = (ks * 2 + b_kh) ^ (row & 3);
                uint32_t bd = bufo + 16384u + (uint32_t)(row * 64 + ch * 16);
                LDMATRIX_X4(bh[np][0], bh[np][1], bh[np][2], bh[np][3], bd);
                LDMATRIX_X4(bl[np][0], bl[np][1], bl[np][2], bl[np][3], bd + 8192u);
            }
#pragma unroll
            for (int mf = 0; mf < 4; mf++)
#pragma unroll
                for (int nf = 0; nf < 4; nf++) {
                    int np = nf >> 1, wh = (nf & 1) * 2;
                    MMA_BF16(acc[mf][nf], ah[mf], bh[np][wh], bh[np][wh + 1]);
                    MMA_BF16(acc[mf][nf], ah[mf], bl[np][wh], bl[np][wh + 1]);
                    MMA_BF16(acc[mf][nf], al[mf], bh[np][wh], bh[np][wh + 1]);
                }
        }
        __syncthreads();
    }

#pragma unroll
    for (int mf = 0; mf < 4; mf++) {
        int row = m0 + wm + mf * 16 + (lane >> 2);
#pragma unroll
        for (int nf = 0; nf < 4; nf++) {
            int col = n0 + wn + nf * 8 + (lane & 3) * 2;
            *(float2*)(C + (size_t)row * N + col) =
                make_float2(acc[mf][nf][0], acc[mf][nf][1]);
            *(float2*)(C + (size_t)(row + 8) * N + col) =
                make_float2(acc[mf][nf][2], acc[mf][nf][3]);
        }
    }
}

// ---------------- split x into bf16 hi/lo -----------------------------------
__global__ void __launch_bounds__(256) splitx_kernel(const float* __restrict__ x)
{
    int i = (blockIdx.x * 256 + threadIdx.x) * 4;
    float4 v = *(const float4*)(x + i);
    __nv_bfloat16 h0 = __float2bfloat16(v.x), h1 = __float2bfloat16(v.y);
    __nv_bfloat16 h2 = __float2bfloat16(v.z), h3 = __float2bfloat16(v.w);
    __nv_bfloat16 l0 = __float2bfloat16(v.x - __bfloat162float(h0));
    __nv_bfloat16 l1 = __float2bfloat16(v.y - __bfloat162float(h1));
    __nv_bfloat16 l2 = __float2bfloat16(v.z - __bfloat162float(h2));
    __nv_bfloat16 l3 = __float2bfloat16(v.w - __bfloat162float(h3));
    *(__nv_bfloat162*)(g_xh + i)     = __nv_bfloat162(h0, h1);
    *(__nv_bfloat162*)(g_xh + i + 2) = __nv_bfloat162(h2, h3);
    *(__nv_bfloat162*)(g_xl + i)     = __nv_bfloat162(l0, l1);
    *(__nv_bfloat162*)(g_xl + i + 2) = __nv_bfloat162(l2, l3);
}

// ---------------- transpose + split weight W[K,N] -> rows rowOff+n of fused buf
__global__ void __launch_bounds__(256) wsplit_kernel(
    const float* __restrict__ W, __nv_bfloat16* __restrict__ Th,
    __nv_bfloat16* __restrict__ Tl, int Kd, int Nd, int rowOff)
{
    __shared__ float tile[32][33];
    int tx = threadIdx.x & 31, ty = threadIdx.x >> 5;
    int n = blockIdx.x * 32 + tx;
    int k0 = blockIdx.y * 32;
#pragma unroll
    for (int i = ty; i < 32; i += 8)
        tile[i][tx] = W[(size_t)(k0 + i) * Nd + n];
    __syncthreads();
#pragma unroll
    for (int i = ty; i < 32; i += 8) {
        int row = rowOff + blockIdx.x * 32 + i;
        float v = tile[tx][i];
        __nv_bfloat16 h = __float2bfloat16(v);
        __nv_bfloat16 l = __float2bfloat16(v - __bfloat162float(h));
        Th[(size_t)row * Kd + k0 + tx] = h;
        Tl[(size_t)row * Kd + k0 + tx] = l;
    }
}

// ---------------- beta / decay ----------------------------------------------
__global__ void __launch_bounds__(256) betag_kernel(
    const float* __restrict__ x, const float* __restrict__ Wb,
    const float* __restrict__ Wa, const float* __restrict__ A_log,
    const float* __restrict__ dt_bias)
{
    int gw   = blockIdx.x*8 + (threadIdx.x >> 5);
    int lane = threadIdx.x & 31;
    int row  = gw / HH;
    int h    = gw % HH;
    const float* xr = x + (size_t)row*DD;
    float sb = 0.f, sa = 0.f;
#pragma unroll 4
    for (int d = lane; d < DD; d += 32) {
        float xv = xr[d];
        sb += xv * Wb[d*HH + h];
        sa += xv * Wa[d*HH + h];
    }
#pragma unroll
    for (int off = 16; off; off >>= 1) {
        sb += __shfl_xor_sync(0xffffffffu, sb, off);
        sa += __shfl_xor_sync(0xffffffffu, sa, off);
    }
    if (lane == 0) {
        int b = row >> 10, t = row & 1023;
        float beta = 1.f / (1.f + expf(-sb));
        float z = sa + dt_bias[h];
        float sp = (z > 20.f) ? z : log1pf(expf(z));
        float eg = expf(-expf(A_log[h]) * sp);
        int idx = (b*HH + h)*LL + t;
        g_beta[idx] = beta;
        g_eg[idx]   = eg;
    }
}

// ---------------- conv+silu+l2norm for q/k (reads fused proj buffer) --------
__global__ void __launch_bounds__(256) convqk_kernel(
    const float* __restrict__ P, int poff, const float* __restrict__ W,
    float* __restrict__ Out, float qscale)
{
    int gw   = blockIdx.x*8 + (threadIdx.x >> 5);
    int lane = threadIdx.x & 31;
    int b   = gw / (HH*LL);
    int rem = gw % (HH*LL);
    int h   = rem / LL;
    int t   = rem % LL;
    int c0  = h*DK + lane*4;

    float w0[4], w1[4], w2[4], w3[4];
    *(float4*)w0 = *(const float4*)(W + (c0+0)*4);
    *(float4*)w1 = *(const float4*)(W + (c0+1)*4);
    *(float4*)w2 = *(const float4*)(W + (c0+2)*4);
    *(float4*)w3 = *(const float4*)(W + (c0+3)*4);

    float a[4] = {0.f, 0.f, 0.f, 0.f};
#pragma unroll
    for (int j = 0; j < 4; j++) {
        int tt = t - 3 + j;
        if (tt >= 0) {
            float4 xv = *(const float4*)(P + (size_t)(b*LL + tt)*NP + poff + c0);
            a[0] += xv.x * w0[j];
            a[1] += xv.y * w1[j];
            a[2] += xv.z * w2[j];
            a[3] += xv.w * w3[j];
        }
    }
#pragma unroll
    for (int i = 0; i < 4; i++) { float z = a[i]; a[i] = z / (1.f + expf(-z)); }
    float ss = a[0]*a[0] + a[1]*a[1] + a[2]*a[2] + a[3]*a[3];
#pragma unroll
    for (int off = 16; off; off >>= 1) ss += __shfl_xor_sync(0xffffffffu, ss, off);
    float r = rsqrtf(ss + 1e-12f) * qscale;
    float4 o = make_float4(a[0]*r, a[1]*r, a[2]*r, a[3]*r);
    *(float4*)(Out + ((size_t)(b*HH + h)*LL + t)*DK + lane*4) = o;
}

// ---------------- conv+silu for v (reads fused proj buffer) ------------------
__global__ void __launch_bounds__(256) convv_kernel(
    const float* __restrict__ P, const float* __restrict__ W)
{
    int idx = blockIdx.x*256 + threadIdx.x;
    int c4i = idx % (VD/4);
    int row = idx / (VD/4);
    int c0  = c4i*4;
    int b = row >> 10, t = row & 1023;

    float w0[4], w1[4], w2[4], w3[4];
    *(float4*)w0 = *(const float4*)(W + (c0+0)*4);
    *(float4*)w1 = *(const float4*)(W + (c0+1)*4);
    *(float4*)w2 = *(const float4*)(W + (c0+2)*4);
    *(float4*)w3 = *(const float4*)(W + (c0+3)*4);

    float a[4] = {0.f, 0.f, 0.f, 0.f};
#pragma unroll
    for (int j = 0; j < 4; j++) {
        int tt = t - 3 + j;
        if (tt >= 0) {
            float4 xv = *(const float4*)(P + (size_t)(b*LL + tt)*NP + 2*KD + c0);
            a[0] += xv.x * w0[j];
            a[1] += xv.y * w1[j];
            a[2] += xv.z * w2[j];
            a[3] += xv.w * w3[j];
        }
    }
#pragma unroll
    for (int i = 0; i < 4; i++) { float z = a[i]; a[i] = z / (1.f + expf(-z)); }
    int h  = c0 / DV;
    int dv = c0 % DV;
    float4 o = make_float4(a[0], a[1], a[2], a[3]);
    *(float4*)(g_vc + ((size_t)(b*HH + h)*LL + t)*DV + dv) = o;
}

// ---------------- delta-rule scan: CTA-cooperative, smem-staged --------------
// 128 threads = 4 warps; CTA owns 8 v-columns of one (b,h).
// Each warp owns 2 columns (one per 16-lane half); lane owns 8 k-entries.
#define TCH 32
#define VPC 8
__global__ void __launch_bounds__(128) scan_kernel(float* __restrict__ sOut)
{
    __shared__ float sk[TCH][DK];
    __shared__ float sq[TCH][DK];
    __shared__ float sv[TCH][VPC];
    __shared__ float se[TCH], sbt[TCH];

    int tid  = threadIdx.x;
    int wid  = tid >> 5, lane = tid & 31;
    int bh   = blockIdx.x / (DV/VPC);
    int vblk = (blockIdx.x % (DV/VPC)) * VPC;
    int half = lane >> 4;
    int lcol = wid*2 + half;          // 0..7 within CTA
    int col  = vblk + lcol;
    int ko   = (lane & 15) * 8;

    int b = bh / HH, h = bh % HH;
    const float* kb = g_kn + (size_t)bh*LL*DK;
    const float* qb = g_qn + (size_t)bh*LL*DK;
    const float* vb = g_vc + (size_t)bh*LL*DV;
    const float* eb = g_eg + (size_t)bh*LL;
    const float* bb = g_beta + (size_t)bh*LL;
    float* ob = g_o + (size_t)b*LL*VD + h*DV + col;

    float s[8];
#pragma unroll
    for (int j = 0; j < 8; j++) s[j] = 0.f;

    for (int ch = 0; ch < LL/TCH; ch++) {
        int t0 = ch * TCH;
        __syncthreads();
#pragma unroll
        for (int i = tid; i < TCH*DK/4; i += 128) {
            ((float4*)sk)[i] = ((const float4*)(kb + (size_t)t0*DK))[i];
            ((float4*)sq)[i] = ((const float4*)(qb + (size_t)t0*DK))[i];
        }
#pragma unroll
        for (int i = tid; i < TCH*VPC/4; i += 128) {
            int tl = i / (VPC/4), vq = (i % (VPC/4)) * 4;
            *(float4*)&sv[tl][vq] = *(const float4*)(vb + (size_t)(t0+tl)*DV + vblk + vq);
        }
        if (tid < TCH) { se[tid] = eb[t0+tid]; sbt[tid] = bb[t0+tid]; }
        __syncthreads();

#pragma unroll 4
        for (int tl = 0; tl < TCH; tl++) {
            float4 k0 = *(float4*)&sk[tl][ko];
            float4 k1 = *(float4*)&sk[tl][ko+4];
            float eg = se[tl], bt = sbt[tl], vt = sv[tl][lcol];
#pragma unroll
            for (int j = 0; j < 8; j++) s[j] *= eg;
            float corr = k0.x*s[0] + k0.y*s[1] + k0.z*s[2] + k0.w*s[3]
                       + k1.x*s[4] + k1.y*s[5] + k1.z*s[6] + k1.w*s[7];
#pragma unroll
            for (int off = 8; off; off >>= 1) corr += __shfl_xor_sync(0xffffffffu, corr, off);
            float u = (vt - corr) * bt;
            s[0] += k0.x*u; s[1] += k0.y*u; s[2] += k0.z*u; s[3] += k0.w*u;
            s[4] += k1.x*u; s[5] += k1.y*u; s[6] += k1.z*u; s[7] += k1.w*u;
            float4 q0 = *(float4*)&sq[tl][ko];
            float4 q1 = *(float4*)&sq[tl][ko+4];
            float o = q0.x*s[0] + q0.y*s[1] + q0.z*s[2] + q0.w*s[3]
                    + q1.x*s[4] + q1.y*s[5] + q1.z*s[6] + q1.w*s[7];
#pragma unroll
            for (int off = 8; off; off >>= 1) o += __shfl_xor_sync(0xffffffffu, o, off);
            if ((lane & 15) == 0) ob[(size_t)(t0+tl)*VD] = o;
        }
    }

    if (sOut) {
        size_t base = (size_t)bh*DK*DV + col;
#pragma unroll
        for (int j = 0; j < 8; j++)
            sOut[base + (size_t)(ko+j)*DV] = s[j];
    }
}

// ---------------- gated RMS norm -> bf16 hi/lo -------------------------------
__global__ void __launch_bounds__(256) gate_kernel(
    const float* __restrict__ P, const float* __restrict__ norm_w)
{
    int gw   = blockIdx.x*8 + (threadIdx.x >> 5);
    int lane = threadIdx.x & 31;
    int row  = gw / HH;
    int h    = gw % HH;
    size_t base  = (size_t)row*VD + h*DV;
    size_t gbase = (size_t)row*NP + 2*KD + VD + h*DV;

    float4 o0 = *(float4*)(g_o + base + lane*4);
    float4 o1 = *(float4*)(g_o + base + 128 + lane*4);
    float ss = o0.x*o0.x + o0.y*o0.y + o0.z*o0.z + o0.w*o0.w
             + o1.x*o1.x + o1.y*o1.y + o1.z*o1.z + o1.w*o1.w;
#pragma unroll
    for (int off = 16; off; off >>= 1) ss += __shfl_xor_sync(0xffffffffu, ss, off);
    float r = rsqrtf(ss * (1.f/DV) + 1e-5f);

    float4 gt0 = *(const float4*)(P + gbase + lane*4);
    float4 gt1 = *(const float4*)(P + gbase + 128 + lane*4);
    float4 nw0 = *(const float4*)(norm_w + lane*4);
    float4 nw1 = *(const float4*)(norm_w + 128 + lane*4);

    float f[8];
    f[0] = o0.x * r * nw0.x * (gt0.x / (1.f + expf(-gt0.x)));
    f[1] = o0.y * r * nw0.y * (gt0.y / (1.f + expf(-gt0.y)));
    f[2] = o0.z * r * nw0.z * (gt0.z / (1.f + expf(-gt0.z)));
    f[3] = o0.w * r * nw0.w * (gt0.w / (1.f + expf(-gt0.w)));
    f[4] = o1.x * r * nw1.x * (gt1.x / (1.f + expf(-gt1.x)));
    f[5] = o1.y * r * nw1.y * (gt1.y / (1.f + expf(-gt1.y)));
    f[6] = o1.z * r * nw1.z * (gt1.z / (1.f + expf(-gt1.z)));
    f[7] = o1.w * r * nw1.w * (gt1.w / (1.f + expf(-gt1.w)));

#pragma unroll
    for (int hf = 0; hf < 2; hf++) {
        size_t off = base + hf*128 + lane*4;
        __nv_bfloat16 h0 = __float2bfloat16(f[hf*4+0]);
        __nv_bfloat16 h1 = __float2bfloat16(f[hf*4+1]);
        __nv_bfloat16 h2 = __float2bfloat16(f[hf*4+2]);
        __nv_bfloat16 h3 = __float2bfloat16(f[hf*4+3]);
        *(__nv_bfloat162*)(g_oh + off)     = __nv_bfloat162(h0, h1);
        *(__nv_bfloat162*)(g_oh + off + 2) = __nv_bfloat162(h2, h3);
        __nv_bfloat16 l0 = __float2bfloat16(f[hf*4+0] - __bfloat162float(h0));
        __nv_bfloat16 l1 = __float2bfloat16(f[hf*4+1] - __bfloat162float(h1));
        __nv_bfloat16 l2 = __float2bfloat16(f[hf*4+2] - __bfloat162float(h2));
        __nv_bfloat16 l3 = __float2bfloat16(f[hf*4+3] - __bfloat162float(h3));
        *(__nv_bfloat162*)(g_ol + off)     = __nv_bfloat162(l0, l1);
        *(__nv_bfloat162*)(g_ol + off + 2) = __nv_bfloat162(l2, l3);
    }
}

// ---------------- launcher ---------------------------------------------------
extern "C" void kernel_launch(void* const* d_in, const int* in_sizes, int n_in,
                              void* d_out, int out_size)
{
    const float* x       = (const float*)d_in[0];
    const float* Wq      = (const float*)d_in[1];
    const float* Wk      = (const float*)d_in[2];
    const float* Wv      = (const float*)d_in[3];
    const float* Wb      = (const float*)d_in[4];
    const float* Wa      = (const float*)d_in[5];
    const float* A_log   = (const float*)d_in[6];
    const float* dt_bias = (const float*)d_in[7];
    const float* conv_q  = (const float*)d_in[8];
    const float* conv_k  = (const float*)d_in[9];
    const float* conv_v  = (const float*)d_in[10];
    const float* Wg      = (const float*)d_in[11];
    const float* norm_w  = (const float*)d_in[12];
    const float* Wo      = (const float*)d_in[13];
    float* out = (float*)d_out;

    float *pproj, *pqn, *pkn;
    cudaGetSymbolAddress((void**)&pproj, g_proj);
    cudaGetSymbolAddress((void**)&pqn, g_qn);
    cudaGetSymbolAddress((void**)&pkn, g_kn);

    __nv_bfloat16 *xh, *xl, *wch, *wcl, *woh, *wol, *oh, *ol;
    cudaGetSymbolAddress((void**)&xh,  g_xh);  cudaGetSymbolAddress((void**)&xl,  g_xl);
    cudaGetSymbolAddress((void**)&wch, g_wch); cudaGetSymbolAddress((void**)&wcl, g_wcl);
    cudaGetSymbolAddress((void**)&woh, g_woh); cudaGetSymbolAddress((void**)&wol, g_wol);
    cudaGetSymbolAddress((void**)&oh,  g_oh);  cudaGetSymbolAddress((void**)&ol,  g_ol);

    const int GEMM_SMEM = 2 * 32768;
    cudaFuncSetAttribute(gemm_mma_bf16x3,
                         cudaFuncAttributeMaxDynamicSharedMemorySize, GEMM_SMEM);

    dim3 blk(256);
    // precision-split prep (weights fused into one [NP, DD] buffer)
    splitx_kernel<<<TOK*DD/(256*4), blk>>>(x);
    wsplit_kernel<<<dim3(KD/32, DD/32), blk>>>(Wq, wch, wcl, DD, KD, 0);
    wsplit_kernel<<<dim3(KD/32, DD/32), blk>>>(Wk, wch, wcl, DD, KD, KD);
    wsplit_kernel<<<dim3(VD/32, DD/32), blk>>>(Wv, wch, wcl, DD, VD, 2*KD);
    wsplit_kernel<<<dim3(VD/32, DD/32), blk>>>(Wg, wch, wcl, DD, VD, 2*KD+VD);
    wsplit_kernel<<<dim3(DD/32, VD/32), blk>>>(Wo, woh, wol, VD, DD, 0);
    // fused projection GEMM: [TOK, NP]
    gemm_mma_bf16x3<<<dim3(NP/128, TOK/128), blk, GEMM_SMEM>>>(xh, xl, wch, wcl, pproj, TOK, NP, DD);
    // beta / decay
    betag_kernel<<<TOK*HH/8, blk>>>(x, Wb, Wa, A_log, dt_bias);
    // conv + silu (+ l2norm)
    convqk_kernel<<<BB*HH*LL/8, blk>>>(pproj, 0,  conv_q, pqn, 0.08838834764831845f);
    convqk_kernel<<<BB*HH*LL/8, blk>>>(pproj, KD, conv_k, pkn, 1.0f);
    convv_kernel<<<TOK*(VD/4)/256, blk>>>(pproj, conv_v);
    // scan
    float* sOut = (out_size >= TOK*DD + BB*HH*DK*DV) ? (out + (size_t)TOK*DD) : nullptr;
    scan_kernel<<<BB*HH*(DV/VPC), 128>>>(sOut);
    // gated rms-norm -> bf16 split
    gate_kernel<<<TOK*HH/8, blk>>>(pproj, norm_w);
    // output projection
    gemm_mma_bf16x3<<<dim3(DD/128, TOK/128), blk, GEMM_SMEM>>>(oh, ol, woh, wol, out, TOK, DD, VD);
}

// round 6
// speedup vs baseline: 2.3353x; 1.1121x over previous
#include <cuda_runtime.h>
#include <cuda_fp16.h>
#include <math.h>
#include <stdint.h>

#define BB 2
#define LL 1024
#define DD 1024
#define HH 6
#define DK 128
#define DV 256
#define KD 768
#define VD 1536
#define TOK (BB*LL)
#define NP 4608   // fused projection width: KD + KD + VD + VD

// ---------------- device scratch ----------------
__device__ __align__(16) float g_proj[TOK*NP];      // [q | k | v | gate]
__device__ __align__(16) float g_qn[BB*HH*LL*DK];
__device__ __align__(16) float g_kn[BB*HH*LL*DK];
__device__ __align__(16) float g_vc[BB*HH*LL*DV];
__device__ __align__(16) float g_eg[BB*HH*LL];
__device__ __align__(16) float g_beta[BB*HH*LL];
__device__ __align__(16) float g_o[TOK*VD];

// fp16 split buffers (A side: hi+lo; B side: single fp16)
__device__ __align__(16) __half g_xh[TOK*DD], g_xl[TOK*DD];
__device__ __align__(16) __half g_wc[NP*DD];        // fused W^T fp16
__device__ __align__(16) __half g_wo[DD*VD];        // Wo^T fp16
__device__ __align__(16) __half g_oh[TOK*VD], g_ol[TOK*VD];

// ---------------- helpers ----------------
__device__ __forceinline__ uint32_t smem_u32(const void* p) {
    uint32_t a;
    asm("{ .reg .u64 t; cvta.to.shared.u64 t, %1; cvt.u32.u64 %0, t; }" : "=r"(a) : "l"(p));
    return a;
}

#define MMA_FP16(d, a, b0v, b1v) \
    asm volatile("mma.sync.aligned.m16n8k16.row.col.f32.f16.f16.f32 " \
        "{%0,%1,%2,%3},{%4,%5,%6,%7},{%8,%9},{%0,%1,%2,%3};" \
        : "+f"(d[0]), "+f"(d[1]), "+f"(d[2]), "+f"(d[3]) \
        : "r"(a[0]), "r"(a[1]), "r"(a[2]), "r"(a[3]), "r"(b0v), "r"(b1v))

#define LDMATRIX_X4(r0, r1, r2, r3, addr) \
    asm volatile("ldmatrix.sync.aligned.m8n8.x4.shared.b16 {%0,%1,%2,%3}, [%4];" \
        : "=r"(r0), "=r"(r1), "=r"(r2), "=r"(r3) : "r"(addr))

// One K-chunk (BK=32) of Ah/Al/B into stage (c%3). Stage = 3*8KB = 24KB.
__device__ __forceinline__ void issue_chunk3(
    int tid, int m0, int n0, int K, int c, uint32_t sb,
    const __half* Ah, const __half* Al, const __half* B)
{
    int k0 = c << 5;
    uint32_t bufo = (uint32_t)(c % 3) * 24576u;
#pragma unroll
    for (int it = 0; it < 6; it++) {
        const int buf = it >> 1;                 // 0:Ah 1:Al 2:B
        int idx = tid + (it << 8);
        int r   = (idx >> 2) & 127;
        int cc  = idx & 3;
        const __half* s = (buf == 0) ? Ah : (buf == 1) ? Al : B;
        int rowg = ((buf < 2) ? m0 : n0) + r;
        const void* g = s + (size_t)rowg * K + k0 + (cc << 3);
        uint32_t sa = sb + bufo + ((uint32_t)buf << 13)
                    + (uint32_t)(r * 64 + ((cc ^ (r & 3)) << 4));
        asm volatile("cp.async.cg.shared.global [%0], [%1], 16;" :: "r"(sa), "l"(g));
    }
    asm volatile("cp.async.commit_group;");
}

// ---------------- fp16x2 mma.sync GEMM: C[M,N] = A[M,K] @ Bt[N,K]^T ---------
// A = Ah + Al (fp16 split), B single fp16. Grid (N/128, M/128), 256 thr.
// Dyn smem = 3 stages * 24KB = 72KB.
__global__ void __launch_bounds__(256) gemm_mma_fp16x2(
    const __half* __restrict__ Ah, const __half* __restrict__ Al,
    const __half* __restrict__ B, float* __restrict__ C, int M, int N, int K)
{
    extern __shared__ char smem[];
    uint32_t sb = smem_u32(smem);
    int tid = threadIdx.x, lane = tid & 31, wid = tid >> 5;
    int m0 = blockIdx.y * 128, n0 = blockIdx.x * 128;
    int wm = (wid >> 2) * 64, wn = (wid & 3) * 32;

    float acc[4][4][4];
#pragma unroll
    for (int i = 0; i < 4; i++)
#pragma unroll
        for (int j = 0; j < 4; j++)
#pragma unroll
            for (int r = 0; r < 4; r++) acc[i][j][r] = 0.f;

    const int nch = K >> 5;
    issue_chunk3(tid, m0, n0, K, 0, sb, Ah, Al, B);
    issue_chunk3(tid, m0, n0, K, 1, sb, Ah, Al, B);

    int a_row_l = lane & 15;
    int a_kh    = lane >> 4;
    int b_row_l = ((lane >> 4) << 3) + (lane & 7);
    int b_kh    = (lane >> 3) & 1;

    for (int c = 0; c < nch; c++) {
        if (c + 2 < nch) {
            issue_chunk3(tid, m0, n0, K, c + 2, sb, Ah, Al, B);
            asm volatile("cp.async.wait_group 2;");
        } else if (c + 1 < nch) {
            asm volatile("cp.async.wait_group 1;");
        } else {
            asm volatile("cp.async.wait_group 0;");
        }
        __syncthreads();

        uint32_t bufo = sb + (uint32_t)(c % 3) * 24576u;
#pragma unroll 1
        for (int ks = 0; ks < 2; ks++) {
            uint32_t ah[4][4], al[4][4], bf[2][4];
#pragma unroll
            for (int mf = 0; mf < 4; mf++) {
                int row = wm + mf * 16 + a_row_l;
                int ch  = (ks * 2 + a_kh) ^ (row & 3);
                uint32_t ad = bufo + (uint32_t)(row * 64 + ch * 16);
                LDMATRIX_X4(ah[mf][0], ah[mf][1], ah[mf][2], ah[mf][3], ad);
                LDMATRIX_X4(al[mf][0], al[mf][1], al[mf][2], al[mf][3], ad + 8192u);
            }
#pragma unroll
            for (int np = 0; np < 2; np++) {
                int row = wn + np * 16 + b_row_l;
                int ch  = (ks * 2 + b_kh) ^ (row & 3);
                uint32_t bd = bufo + 16384u + (uint32_t)(row * 64 + ch * 16);
                LDMATRIX_X4(bf[np][0], bf[np][1], bf[np][2], bf[np][3], bd);
            }
#pragma unroll
            for (int mf = 0; mf < 4; mf++)
#pragma unroll
                for (int nf = 0; nf < 4; nf++) {
                    int np = nf >> 1, wh = (nf & 1) * 2;
                    MMA_FP16(acc[mf][nf], ah[mf], bf[np][wh], bf[np][wh + 1]);
                    MMA_FP16(acc[mf][nf], al[mf], bf[np][wh], bf[np][wh + 1]);
                }
        }
        __syncthreads();
    }

#pragma unroll
    for (int mf = 0; mf < 4; mf++) {
        int row = m0 + wm + mf * 16 + (lane >> 2);
#pragma unroll
        for (int nf = 0; nf < 4; nf++) {
            int col = n0 + wn + nf * 8 + (lane & 3) * 2;
            *(float2*)(C + (size_t)row * N + col) =
                make_float2(acc[mf][nf][0], acc[mf][nf][1]);
            *(float2*)(C + (size_t)(row + 8) * N + col) =
                make_float2(acc[mf][nf][2], acc[mf][nf][3]);
        }
    }
}

// ---------------- split x into fp16 hi/lo -----------------------------------
__global__ void __launch_bounds__(256) splitx_kernel(const float* __restrict__ x)
{
    int i = (blockIdx.x * 256 + threadIdx.x) * 4;
    float4 v = *(const float4*)(x + i);
    __half h0 = __float2half(v.x), h1 = __float2half(v.y);
    __half h2 = __float2half(v.z), h3 = __float2half(v.w);
    __half l0 = __float2half(v.x - __half2float(h0));
    __half l1 = __float2half(v.y - __half2float(h1));
    __half l2 = __float2half(v.z - __half2float(h2));
    __half l3 = __float2half(v.w - __half2float(h3));
    *(__half2*)(g_xh + i)     = __half2(h0, h1);
    *(__half2*)(g_xh + i + 2) = __half2(h2, h3);
    *(__half2*)(g_xl + i)     = __half2(l0, l1);
    *(__half2*)(g_xl + i + 2) = __half2(l2, l3);
}

// ---------------- transpose weight W[K,N] -> fp16 rows rowOff+n -------------
__global__ void __launch_bounds__(256) wsplit_kernel(
    const float* __restrict__ W, __half* __restrict__ Th,
    int Kd, int Nd, int rowOff)
{
    __shared__ float tile[32][33];
    int tx = threadIdx.x & 31, ty = threadIdx.x >> 5;
    int n = blockIdx.x * 32 + tx;
    int k0 = blockIdx.y * 32;
#pragma unroll
    for (int i = ty; i < 32; i += 8)
        tile[i][tx] = W[(size_t)(k0 + i) * Nd + n];
    __syncthreads();
#pragma unroll
    for (int i = ty; i < 32; i += 8) {
        int row = rowOff + blockIdx.x * 32 + i;
        Th[(size_t)row * Kd + k0 + tx] = __float2half(tile[tx][i]);
    }
}

// ---------------- beta / decay ----------------------------------------------
__global__ void __launch_bounds__(256) betag_kernel(
    const float* __restrict__ x, const float* __restrict__ Wb,
    const float* __restrict__ Wa, const float* __restrict__ A_log,
    const float* __restrict__ dt_bias)
{
    int gw   = blockIdx.x*8 + (threadIdx.x >> 5);
    int lane = threadIdx.x & 31;
    int row  = gw / HH;
    int h    = gw % HH;
    const float* xr = x + (size_t)row*DD;
    float sb = 0.f, sa = 0.f;
#pragma unroll 4
    for (int d = lane; d < DD; d += 32) {
        float xv = xr[d];
        sb += xv * Wb[d*HH + h];
        sa += xv * Wa[d*HH + h];
    }
#pragma unroll
    for (int off = 16; off; off >>= 1) {
        sb += __shfl_xor_sync(0xffffffffu, sb, off);
        sa += __shfl_xor_sync(0xffffffffu, sa, off);
    }
    if (lane == 0) {
        int b = row >> 10, t = row & 1023;
        float beta = 1.f / (1.f + expf(-sb));
        float z = sa + dt_bias[h];
        float sp = (z > 20.f) ? z : log1pf(expf(z));
        float eg = expf(-expf(A_log[h]) * sp);
        int idx = (b*HH + h)*LL + t;
        g_beta[idx] = beta;
        g_eg[idx]   = eg;
    }
}

// ---------------- conv+silu+l2norm for q/k (gridDim.y: 0=q, 1=k) ------------
__global__ void __launch_bounds__(256) convqk_kernel(
    const float* __restrict__ P, const float* __restrict__ Wq,
    const float* __restrict__ Wk, float* __restrict__ Oq,
    float* __restrict__ Ok)
{
    int which = blockIdx.y;
    int poff  = which * KD;
    const float* W = which ? Wk : Wq;
    float* Out = which ? Ok : Oq;
    float qscale = which ? 1.0f : 0.08838834764831845f;

    int gw   = blockIdx.x*8 + (threadIdx.x >> 5);
    int lane = threadIdx.x & 31;
    int b   = gw / (HH*LL);
    int rem = gw % (HH*LL);
    int h   = rem / LL;
    int t   = rem % LL;
    int c0  = h*DK + lane*4;

    float w0[4], w1[4], w2[4], w3[4];
    *(float4*)w0 = *(const float4*)(W + (c0+0)*4);
    *(float4*)w1 = *(const float4*)(W + (c0+1)*4);
    *(float4*)w2 = *(const float4*)(W + (c0+2)*4);
    *(float4*)w3 = *(const float4*)(W + (c0+3)*4);

    float a[4] = {0.f, 0.f, 0.f, 0.f};
#pragma unroll
    for (int j = 0; j < 4; j++) {
        int tt = t - 3 + j;
        if (tt >= 0) {
            float4 xv = *(const float4*)(P + (size_t)(b*LL + tt)*NP + poff + c0);
            a[0] += xv.x * w0[j];
            a[1] += xv.y * w1[j];
            a[2] += xv.z * w2[j];
            a[3] += xv.w * w3[j];
        }
    }
#pragma unroll
    for (int i = 0; i < 4; i++) { float z = a[i]; a[i] = z / (1.f + expf(-z)); }
    float ss = a[0]*a[0] + a[1]*a[1] + a[2]*a[2] + a[3]*a[3];
#pragma unroll
    for (int off = 16; off; off >>= 1) ss += __shfl_xor_sync(0xffffffffu, ss, off);
    float r = rsqrtf(ss + 1e-12f) * qscale;
    float4 o = make_float4(a[0]*r, a[1]*r, a[2]*r, a[3]*r);
    *(float4*)(Out + ((size_t)(b*HH + h)*LL + t)*DK + lane*4) = o;
}

// ---------------- conv+silu for v -------------------------------------------
__global__ void __launch_bounds__(256) convv_kernel(
    const float* __restrict__ P, const float* __restrict__ W)
{
    int idx = blockIdx.x*256 + threadIdx.x;
    int c4i = idx % (VD/4);
    int row = idx / (VD/4);
    int c0  = c4i*4;
    int b = row >> 10, t = row & 1023;

    float w0[4], w1[4], w2[4], w3[4];
    *(float4*)w0 = *(const float4*)(W + (c0+0)*4);
    *(float4*)w1 = *(const float4*)(W + (c0+1)*4);
    *(float4*)w2 = *(const float4*)(W + (c0+2)*4);
    *(float4*)w3 = *(const float4*)(W + (c0+3)*4);

    float a[4] = {0.f, 0.f, 0.f, 0.f};
#pragma unroll
    for (int j = 0; j < 4; j++) {
        int tt = t - 3 + j;
        if (tt >= 0) {
            float4 xv = *(const float4*)(P + (size_t)(b*LL + tt)*NP + 2*KD + c0);
            a[0] += xv.x * w0[j];
            a[1] += xv.y * w1[j];
            a[2] += xv.z * w2[j];
            a[3] += xv.w * w3[j];
        }
    }
#pragma unroll
    for (int i = 0; i < 4; i++) { float z = a[i]; a[i] = z / (1.f + expf(-z)); }
    int h  = c0 / DV;
    int dv = c0 % DV;
    float4 o = make_float4(a[0], a[1], a[2], a[3]);
    *(float4*)(g_vc + ((size_t)(b*HH + h)*LL + t)*DV + dv) = o;
}

// ---------------- delta-rule scan: CTA-cooperative, smem-staged --------------
#define TCH 32
#define VPC 8
__global__ void __launch_bounds__(128) scan_kernel(float* __restrict__ sOut)
{
    __shared__ float sk[TCH][DK];
    __shared__ float sq[TCH][DK];
    __shared__ float sv[TCH][VPC];
    __shared__ float se[TCH], sbt[TCH];

    int tid  = threadIdx.x;
    int wid  = tid >> 5, lane = tid & 31;
    int bh   = blockIdx.x / (DV/VPC);
    int vblk = (blockIdx.x % (DV/VPC)) * VPC;
    int half = lane >> 4;
    int lcol = wid*2 + half;
    int col  = vblk + lcol;
    int ko   = (lane & 15) * 8;

    int b = bh / HH, h = bh % HH;
    const float* kb = g_kn + (size_t)bh*LL*DK;
    const float* qb = g_qn + (size_t)bh*LL*DK;
    const float* vb = g_vc + (size_t)bh*LL*DV;
    const float* eb = g_eg + (size_t)bh*LL;
    const float* bb = g_beta + (size_t)bh*LL;
    float* ob = g_o + (size_t)b*LL*VD + h*DV + col;

    float s[8];
#pragma unroll
    for (int j = 0; j < 8; j++) s[j] = 0.f;

    for (int ch = 0; ch < LL/TCH; ch++) {
        int t0 = ch * TCH;
        __syncthreads();
#pragma unroll
        for (int i = tid; i < TCH*DK/4; i += 128) {
            ((float4*)sk)[i] = ((const float4*)(kb + (size_t)t0*DK))[i];
            ((float4*)sq)[i] = ((const float4*)(qb + (size_t)t0*DK))[i];
        }
#pragma unroll
        for (int i = tid; i < TCH*VPC/4; i += 128) {
            int tl = i / (VPC/4), vq = (i % (VPC/4)) * 4;
            *(float4*)&sv[tl][vq] = *(const float4*)(vb + (size_t)(t0+tl)*DV + vblk + vq);
        }
        if (tid < TCH) { se[tid] = eb[t0+tid]; sbt[tid] = bb[t0+tid]; }
        __syncthreads();

#pragma unroll 4
        for (int tl = 0; tl < TCH; tl++) {
            float4 k0 = *(float4*)&sk[tl][ko];
            float4 k1 = *(float4*)&sk[tl][ko+4];
            float eg = se[tl], bt = sbt[tl], vt = sv[tl][lcol];
#pragma unroll
            for (int j = 0; j < 8; j++) s[j] *= eg;
            float corr = k0.x*s[0] + k0.y*s[1] + k0.z*s[2] + k0.w*s[3]
                       + k1.x*s[4] + k1.y*s[5] + k1.z*s[6] + k1.w*s[7];
#pragma unroll
            for (int off = 8; off; off >>= 1) corr += __shfl_xor_sync(0xffffffffu, corr, off);
            float u = (vt - corr) * bt;
            s[0] += k0.x*u; s[1] += k0.y*u; s[2] += k0.z*u; s[3] += k0.w*u;
            s[4] += k1.x*u; s[5] += k1.y*u; s[6] += k1.z*u; s[7] += k1.w*u;
            float4 q0 = *(float4*)&sq[tl][ko];
            float4 q1 = *(float4*)&sq[tl][ko+4];
            float o = q0.x*s[0] + q0.y*s[1] + q0.z*s[2] + q0.w*s[3]
                    + q1.x*s[4] + q1.y*s[5] + q1.z*s[6] + q1.w*s[7];
#pragma unroll
            for (int off = 8; off; off >>= 1) o += __shfl_xor_sync(0xffffffffu, o, off);
            if ((lane & 15) == 0) ob[(size_t)(t0+tl)*VD] = o;
        }
    }

    if (sOut) {
        size_t base = (size_t)bh*DK*DV + col;
#pragma unroll
        for (int j = 0; j < 8; j++)
            sOut[base + (size_t)(ko+j)*DV] = s[j];
    }
}

// ---------------- gated RMS norm -> fp16 hi/lo -------------------------------
__global__ void __launch_bounds__(256) gate_kernel(
    const float* __restrict__ P, const float* __restrict__ norm_w)
{
    int gw   = blockIdx.x*8 + (threadIdx.x >> 5);
    int lane = threadIdx.x & 31;
    int row  = gw / HH;
    int h    = gw % HH;
    size_t base  = (size_t)row*VD + h*DV;
    size_t gbase = (size_t)row*NP + 2*KD + VD + h*DV;

    float4 o0 = *(float4*)(g_o + base + lane*4);
    float4 o1 = *(float4*)(g_o + base + 128 + lane*4);
    float ss = o0.x*o0.x + o0.y*o0.y + o0.z*o0.z + o0.w*o0.w
             + o1.x*o1.x + o1.y*o1.y + o1.z*o1.z + o1.w*o1.w;
#pragma unroll
    for (int off = 16; off; off >>= 1) ss += __shfl_xor_sync(0xffffffffu, ss, off);
    float r = rsqrtf(ss * (1.f/DV) + 1e-5f);

    float4 gt0 = *(const float4*)(P + gbase + lane*4);
    float4 gt1 = *(const float4*)(P + gbase + 128 + lane*4);
    float4 nw0 = *(const float4*)(norm_w + lane*4);
    float4 nw1 = *(const float4*)(norm_w + 128 + lane*4);

    float f[8];
    f[0] = o0.x * r * nw0.x * (gt0.x / (1.f + expf(-gt0.x)));
    f[1] = o0.y * r * nw0.y * (gt0.y / (1.f + expf(-gt0.y)));
    f[2] = o0.z * r * nw0.z * (gt0.z / (1.f + expf(-gt0.z)));
    f[3] = o0.w * r * nw0.w * (gt0.w / (1.f + expf(-gt0.w)));
    f[4] = o1.x * r * nw1.x * (gt1.x / (1.f + expf(-gt1.x)));
    f[5] = o1.y * r * nw1.y * (gt1.y / (1.f + expf(-gt1.y)));
    f[6] = o1.z * r * nw1.z * (gt1.z / (1.f + expf(-gt1.z)));
    f[7] = o1.w * r * nw1.w * (gt1.w / (1.f + expf(-gt1.w)));

#pragma unroll
    for (int hf = 0; hf < 2; hf++) {
        size_t off = base + hf*128 + lane*4;
        __half h0 = __float2half(f[hf*4+0]);
        __half h1 = __float2half(f[hf*4+1]);
        __half h2 = __float2half(f[hf*4+2]);
        __half h3 = __float2half(f[hf*4+3]);
        *(__half2*)(g_oh + off)     = __half2(h0, h1);
        *(__half2*)(g_oh + off + 2) = __half2(h2, h3);
        __half l0 = __float2half(f[hf*4+0] - __half2float(h0));
        __half l1 = __float2half(f[hf*4+1] - __half2float(h1));
        __half l2 = __float2half(f[hf*4+2] - __half2float(h2));
        __half l3 = __float2half(f[hf*4+3] - __half2float(h3));
        *(__half2*)(g_ol + off)     = __half2(l0, l1);
        *(__half2*)(g_ol + off + 2) = __half2(l2, l3);
    }
}

// ---------------- launcher ---------------------------------------------------
extern "C" void kernel_launch(void* const* d_in, const int* in_sizes, int n_in,
                              void* d_out, int out_size)
{
    const float* x       = (const float*)d_in[0];
    const float* Wq      = (const float*)d_in[1];
    const float* Wk      = (const float*)d_in[2];
    const float* Wv      = (const float*)d_in[3];
    const float* Wb      = (const float*)d_in[4];
    const float* Wa      = (const float*)d_in[5];
    const float* A_log   = (const float*)d_in[6];
    const float* dt_bias = (const float*)d_in[7];
    const float* conv_q  = (const float*)d_in[8];
    const float* conv_k  = (const float*)d_in[9];
    const float* conv_v  = (const float*)d_in[10];
    const float* Wg      = (const float*)d_in[11];
    const float* norm_w  = (const float*)d_in[12];
    const float* Wo      = (const float*)d_in[13];
    float* out = (float*)d_out;

    float *pproj, *pqn, *pkn;
    cudaGetSymbolAddress((void**)&pproj, g_proj);
    cudaGetSymbolAddress((void**)&pqn, g_qn);
    cudaGetSymbolAddress((void**)&pkn, g_kn);

    __half *xh, *xl, *wc, *wo, *oh, *ol;
    cudaGetSymbolAddress((void**)&xh, g_xh);  cudaGetSymbolAddress((void**)&xl, g_xl);
    cudaGetSymbolAddress((void**)&wc, g_wc);  cudaGetSymbolAddress((void**)&wo, g_wo);
    cudaGetSymbolAddress((void**)&oh, g_oh);  cudaGetSymbolAddress((void**)&ol, g_ol);

    const int GEMM_SMEM = 3 * 24576;
    cudaFuncSetAttribute(gemm_mma_fp16x2,
                         cudaFuncAttributeMaxDynamicSharedMemorySize, GEMM_SMEM);

    dim3 blk(256);
    // prep: split x (fp16 hi/lo), transpose+round weights (fp16)
    splitx_kernel<<<TOK*DD/(256*4), blk>>>(x);
    wsplit_kernel<<<dim3(KD/32, DD/32), blk>>>(Wq, wc, DD, KD, 0);
    wsplit_kernel<<<dim3(KD/32, DD/32), blk>>>(Wk, wc, DD, KD, KD);
    wsplit_kernel<<<dim3(VD/32, DD/32), blk>>>(Wv, wc, DD, VD, 2*KD);
    wsplit_kernel<<<dim3(VD/32, DD/32), blk>>>(Wg, wc, DD, VD, 2*KD+VD);
    wsplit_kernel<<<dim3(DD/32, VD/32), blk>>>(Wo, wo, VD, DD, 0);
    // fused projection GEMM: [TOK, NP]
    gemm_mma_fp16x2<<<dim3(NP/128, TOK/128), blk, GEMM_SMEM>>>(xh, xl, wc, pproj, TOK, NP, DD);
    // beta / decay
    betag_kernel<<<TOK*HH/8, blk>>>(x, Wb, Wa, A_log, dt_bias);
    // conv + silu (+ l2norm): q and k in one launch via gridDim.y
    convqk_kernel<<<dim3(BB*HH*LL/8, 2), blk>>>(pproj, conv_q, conv_k, pqn, pkn);
    convv_kernel<<<TOK*(VD/4)/256, blk>>>(pproj, conv_v);
    // scan
    float* sOut = (out_size >= TOK*DD + BB*HH*DK*DV) ? (out + (size_t)TOK*DD) : nullptr;
    scan_kernel<<<BB*HH*(DV/VPC), 128>>>(sOut);
    // gated rms-norm -> fp16 split
    gate_kernel<<<TOK*HH/8, blk>>>(pproj, norm_w);
    // output projection
    gemm_mma_fp16x2<<<dim3(DD/128, TOK/128), blk, GEMM_SMEM>>>(oh, ol, wo, out, TOK, DD, VD);
}

// round 7
// speedup vs baseline: 2.5307x; 1.0837x over previous
#include <cuda_runtime.h>
#include <cuda_fp16.h>
#include <math.h>
#include <stdint.h>

#define BB 2
#define LL 1024
#define DD 1024
#define HH 6
#define DK 128
#define DV 256
#define KD 768
#define VD 1536
#define TOK (BB*LL)
#define NP 4608   // fused projection width: KD + KD + VD + VD

// ---------------- device scratch ----------------
__device__ __align__(16) float g_proj[TOK*NP];      // [q | k | v | gate]
__device__ __align__(16) float g_qn[BB*HH*LL*DK];
__device__ __align__(16) float g_kn[BB*HH*LL*DK];
__device__ __align__(16) float g_vc[BB*HH*LL*DV];
__device__ __align__(16) float g_eg[BB*HH*LL];
__device__ __align__(16) float g_beta[BB*HH*LL];
__device__ __align__(16) float g_o[TOK*VD];

// fp16 buffers (A side: hi+lo split; B side: single fp16)
__device__ __align__(16) __half g_xh[TOK*DD], g_xl[TOK*DD];
__device__ __align__(16) __half g_wc[NP*DD];        // fused W^T fp16
__device__ __align__(16) __half g_wo[DD*VD];        // Wo^T fp16
__device__ __align__(16) __half g_oh[TOK*VD], g_ol[TOK*VD];

// ---------------- helpers ----------------
__device__ __forceinline__ uint32_t smem_u32(const void* p) {
    uint32_t a;
    asm("{ .reg .u64 t; cvta.to.shared.u64 t, %1; cvt.u32.u64 %0, t; }" : "=r"(a) : "l"(p));
    return a;
}

#define MMA_FP16(d, a, b0v, b1v) \
    asm volatile("mma.sync.aligned.m16n8k16.row.col.f32.f16.f16.f32 " \
        "{%0,%1,%2,%3},{%4,%5,%6,%7},{%8,%9},{%0,%1,%2,%3};" \
        : "+f"(d[0]), "+f"(d[1]), "+f"(d[2]), "+f"(d[3]) \
        : "r"(a[0]), "r"(a[1]), "r"(a[2]), "r"(a[3]), "r"(b0v), "r"(b1v))

#define LDMATRIX_X4(r0, r1, r2, r3, addr) \
    asm volatile("ldmatrix.sync.aligned.m8n8.x4.shared.b16 {%0,%1,%2,%3}, [%4];" \
        : "=r"(r0), "=r"(r1), "=r"(r2), "=r"(r3) : "r"(addr))

// One K-chunk (BK=32) of Ah/Al/B into stage (c%3). Stage = 3*8KB = 24KB.
__device__ __forceinline__ void issue_chunk3(
    int tid, int m0, int n0, int K, int c, uint32_t sb,
    const __half* Ah, const __half* Al, const __half* B)
{
    int k0 = c << 5;
    uint32_t bufo = (uint32_t)(c % 3) * 24576u;
#pragma unroll
    for (int it = 0; it < 6; it++) {
        const int buf = it >> 1;                 // 0:Ah 1:Al 2:B
        int idx = tid + (it << 8);
        int r   = (idx >> 2) & 127;
        int cc  = idx & 3;
        const __half* s = (buf == 0) ? Ah : (buf == 1) ? Al : B;
        int rowg = ((buf < 2) ? m0 : n0) + r;
        const void* g = s + (size_t)rowg * K + k0 + (cc << 3);
        uint32_t sa = sb + bufo + ((uint32_t)buf << 13)
                    + (uint32_t)(r * 64 + ((cc ^ (r & 3)) << 4));
        asm volatile("cp.async.cg.shared.global [%0], [%1], 16;" :: "r"(sa), "l"(g));
    }
    asm volatile("cp.async.commit_group;");
}

// ---------------- fp16x2 mma.sync GEMM: C[M,N] = A[M,K] @ Bt[N,K]^T ---------
__global__ void __launch_bounds__(256) gemm_mma_fp16x2(
    const __half* __restrict__ Ah, const __half* __restrict__ Al,
    const __half* __restrict__ B, float* __restrict__ C, int M, int N, int K)
{
    extern __shared__ char smem[];
    uint32_t sb = smem_u32(smem);
    int tid = threadIdx.x, lane = tid & 31, wid = tid >> 5;
    int m0 = blockIdx.y * 128, n0 = blockIdx.x * 128;
    int wm = (wid >> 2) * 64, wn = (wid & 3) * 32;

    float acc[4][4][4];
#pragma unroll
    for (int i = 0; i < 4; i++)
#pragma unroll
        for (int j = 0; j < 4; j++)
#pragma unroll
            for (int r = 0; r < 4; r++) acc[i][j][r] = 0.f;

    const int nch = K >> 5;
    issue_chunk3(tid, m0, n0, K, 0, sb, Ah, Al, B);
    issue_chunk3(tid, m0, n0, K, 1, sb, Ah, Al, B);

    int a_row_l = lane & 15;
    int a_kh    = lane >> 4;
    int b_row_l = ((lane >> 4) << 3) + (lane & 7);
    int b_kh    = (lane >> 3) & 1;

    for (int c = 0; c < nch; c++) {
        if (c + 2 < nch) {
            issue_chunk3(tid, m0, n0, K, c + 2, sb, Ah, Al, B);
            asm volatile("cp.async.wait_group 2;");
        } else if (c + 1 < nch) {
            asm volatile("cp.async.wait_group 1;");
        } else {
            asm volatile("cp.async.wait_group 0;");
        }
        __syncthreads();

        uint32_t bufo = sb + (uint32_t)(c % 3) * 24576u;
#pragma unroll 1
        for (int ks = 0; ks < 2; ks++) {
            uint32_t ah[4][4], al[4][4], bf[2][4];
#pragma unroll
            for (int mf = 0; mf < 4; mf++) {
                int row = wm + mf * 16 + a_row_l;
                int ch  = (ks * 2 + a_kh) ^ (row & 3);
                uint32_t ad = bufo + (uint32_t)(row * 64 + ch * 16);
                LDMATRIX_X4(ah[mf][0], ah[mf][1], ah[mf][2], ah[mf][3], ad);
                LDMATRIX_X4(al[mf][0], al[mf][1], al[mf][2], al[mf][3], ad + 8192u);
            }
#pragma unroll
            for (int np = 0; np < 2; np++) {
                int row = wn + np * 16 + b_row_l;
                int ch  = (ks * 2 + b_kh) ^ (row & 3);
                uint32_t bd = bufo + 16384u + (uint32_t)(row * 64 + ch * 16);
                LDMATRIX_X4(bf[np][0], bf[np][1], bf[np][2], bf[np][3], bd);
            }
#pragma unroll
            for (int mf = 0; mf < 4; mf++)
#pragma unroll
                for (int nf = 0; nf < 4; nf++) {
                    int np = nf >> 1, wh = (nf & 1) * 2;
                    MMA_FP16(acc[mf][nf], ah[mf], bf[np][wh], bf[np][wh + 1]);
                    MMA_FP16(acc[mf][nf], al[mf], bf[np][wh], bf[np][wh + 1]);
                }
        }
        __syncthreads();
    }

#pragma unroll
    for (int mf = 0; mf < 4; mf++) {
        int row = m0 + wm + mf * 16 + (lane >> 2);
#pragma unroll
        for (int nf = 0; nf < 4; nf++) {
            int col = n0 + wn + nf * 8 + (lane & 3) * 2;
            *(float2*)(C + (size_t)row * N + col) =
                make_float2(acc[mf][nf][0], acc[mf][nf][1]);
            *(float2*)(C + (size_t)(row + 8) * N + col) =
                make_float2(acc[mf][nf][2], acc[mf][nf][3]);
        }
    }
}

// ---------------- split x into fp16 hi/lo -----------------------------------
__global__ void __launch_bounds__(256) splitx_kernel(const float* __restrict__ x)
{
    int i = (blockIdx.x * 256 + threadIdx.x) * 4;
    float4 v = *(const float4*)(x + i);
    __half h0 = __float2half(v.x), h1 = __float2half(v.y);
    __half h2 = __float2half(v.z), h3 = __float2half(v.w);
    __half l0 = __float2half(v.x - __half2float(h0));
    __half l1 = __float2half(v.y - __half2float(h1));
    __half l2 = __float2half(v.z - __half2float(h2));
    __half l3 = __float2half(v.w - __half2float(h3));
    *(__half2*)(g_xh + i)     = __half2(h0, h1);
    *(__half2*)(g_xh + i + 2) = __half2(h2, h3);
    *(__half2*)(g_xl + i)     = __half2(l0, l1);
    *(__half2*)(g_xl + i + 2) = __half2(l2, l3);
}

// ---------------- fused transpose of all 5 weights -> fp16 ------------------
// Tile map: Wq[0,768) Wk[768,1536) Wv[1536,3072) Wg[3072,4608) Wo[4608,6144)
__global__ void __launch_bounds__(256) wsplit_all(
    const float* __restrict__ Wq, const float* __restrict__ Wk,
    const float* __restrict__ Wv, const float* __restrict__ Wg,
    const float* __restrict__ Wo)
{
    int bid = blockIdx.x;
    const float* W; __half* T; int Kd, Nd, rowOff, lt;
    if (bid < 768)       { W = Wq; T = g_wc; Kd = 1024; Nd = 768;  rowOff = 0;        lt = bid; }
    else if (bid < 1536) { W = Wk; T = g_wc; Kd = 1024; Nd = 768;  rowOff = KD;       lt = bid - 768; }
    else if (bid < 3072) { W = Wv; T = g_wc; Kd = 1024; Nd = 1536; rowOff = 2*KD;     lt = bid - 1536; }
    else if (bid < 4608) { W = Wg; T = g_wc; Kd = 1024; Nd = 1536; rowOff = 2*KD+VD;  lt = bid - 3072; }
    else                 { W = Wo; T = g_wo; Kd = 1536; Nd = 1024; rowOff = 0;        lt = bid - 4608; }
    int ntx = Nd >> 5;
    int bx = lt % ntx, by = lt / ntx;

    __shared__ float tile[32][33];
    int tx = threadIdx.x & 31, ty = threadIdx.x >> 5;
    int n = bx*32 + tx;
    int k0 = by*32;
#pragma unroll
    for (int i = ty; i < 32; i += 8)
        tile[i][tx] = W[(size_t)(k0 + i) * Nd + n];
    __syncthreads();
#pragma unroll
    for (int i = ty; i < 32; i += 8) {
        int row = rowOff + bx*32 + i;
        T[(size_t)row * Kd + k0 + tx] = __float2half(tile[tx][i]);
    }
}

// ---------------- beta / decay ----------------------------------------------
__global__ void __launch_bounds__(256) betag_kernel(
    const float* __restrict__ x, const float* __restrict__ Wb,
    const float* __restrict__ Wa, const float* __restrict__ A_log,
    const float* __restrict__ dt_bias)
{
    int gw   = blockIdx.x*8 + (threadIdx.x >> 5);
    int lane = threadIdx.x & 31;
    int row  = gw / HH;
    int h    = gw % HH;
    const float* xr = x + (size_t)row*DD;
    float sb = 0.f, sa = 0.f;
#pragma unroll 4
    for (int d = lane; d < DD; d += 32) {
        float xv = xr[d];
        sb += xv * Wb[d*HH + h];
        sa += xv * Wa[d*HH + h];
    }
#pragma unroll
    for (int off = 16; off; off >>= 1) {
        sb += __shfl_xor_sync(0xffffffffu, sb, off);
        sa += __shfl_xor_sync(0xffffffffu, sa, off);
    }
    if (lane == 0) {
        int b = row >> 10, t = row & 1023;
        float beta = 1.f / (1.f + expf(-sb));
        float z = sa + dt_bias[h];
        float sp = (z > 20.f) ? z : log1pf(expf(z));
        float eg = expf(-expf(A_log[h]) * sp);
        int idx = (b*HH + h)*LL + t;
        g_beta[idx] = beta;
        g_eg[idx]   = eg;
    }
}

// ---------------- fused conv: y=0 q, y=1 k, y=2/3 v --------------------------
__global__ void __launch_bounds__(256) conv_all(
    const float* __restrict__ P, const float* __restrict__ Wq,
    const float* __restrict__ Wk, const float* __restrict__ Wv,
    float* __restrict__ Oq, float* __restrict__ Ok)
{
    int y = blockIdx.y;
    if (y < 2) {
        int poff  = y * KD;
        const float* W = y ? Wk : Wq;
        float* Out = y ? Ok : Oq;
        float qscale = y ? 1.0f : 0.08838834764831845f;

        int gw   = blockIdx.x*8 + (threadIdx.x >> 5);
        int lane = threadIdx.x & 31;
        int b   = gw / (HH*LL);
        int rem = gw % (HH*LL);
        int h   = rem / LL;
        int t   = rem % LL;
        int c0  = h*DK + lane*4;

        float w0[4], w1[4], w2[4], w3[4];
        *(float4*)w0 = *(const float4*)(W + (c0+0)*4);
        *(float4*)w1 = *(const float4*)(W + (c0+1)*4);
        *(float4*)w2 = *(const float4*)(W + (c0+2)*4);
        *(float4*)w3 = *(const float4*)(W + (c0+3)*4);

        float a[4] = {0.f, 0.f, 0.f, 0.f};
#pragma unroll
        for (int j = 0; j < 4; j++) {
            int tt = t - 3 + j;
            if (tt >= 0) {
                float4 xv = *(const float4*)(P + (size_t)(b*LL + tt)*NP + poff + c0);
                a[0] += xv.x * w0[j];
                a[1] += xv.y * w1[j];
                a[2] += xv.z * w2[j];
                a[3] += xv.w * w3[j];
            }
        }
#pragma unroll
        for (int i = 0; i < 4; i++) { float z = a[i]; a[i] = z / (1.f + expf(-z)); }
        float ss = a[0]*a[0] + a[1]*a[1] + a[2]*a[2] + a[3]*a[3];
#pragma unroll
        for (int off = 16; off; off >>= 1) ss += __shfl_xor_sync(0xffffffffu, ss, off);
        float r = rsqrtf(ss + 1e-12f) * qscale;
        float4 o = make_float4(a[0]*r, a[1]*r, a[2]*r, a[3]*r);
        *(float4*)(Out + ((size_t)(b*HH + h)*LL + t)*DK + lane*4) = o;
    } else {
        int idx = ((y - 2) * 1536 + blockIdx.x)*256 + threadIdx.x;
        int c4i = idx % (VD/4);
        int row = idx / (VD/4);
        int c0  = c4i*4;
        int b = row >> 10, t = row & 1023;

        float w0[4], w1[4], w2[4], w3[4];
        *(float4*)w0 = *(const float4*)(Wv + (c0+0)*4);
        *(float4*)w1 = *(const float4*)(Wv + (c0+1)*4);
        *(float4*)w2 = *(const float4*)(Wv + (c0+2)*4);
        *(float4*)w3 = *(const float4*)(Wv + (c0+3)*4);

        float a[4] = {0.f, 0.f, 0.f, 0.f};
#pragma unroll
        for (int j = 0; j < 4; j++) {
            int tt = t - 3 + j;
            if (tt >= 0) {
                float4 xv = *(const float4*)(P + (size_t)(b*LL + tt)*NP + 2*KD + c0);
                a[0] += xv.x * w0[j];
                a[1] += xv.y * w1[j];
                a[2] += xv.z * w2[j];
                a[3] += xv.w * w3[j];
            }
        }
#pragma unroll
        for (int i = 0; i < 4; i++) { float z = a[i]; a[i] = z / (1.f + expf(-z)); }
        int h  = c0 / DV;
        int dv = c0 % DV;
        float4 o = make_float4(a[0], a[1], a[2], a[3]);
        *(float4*)(g_vc + ((size_t)(b*HH + h)*LL + t)*DV + dv) = o;
    }
}

// ---------------- delta-rule scan: 2 interleaved columns per thread ----------
// 128 thr = 4 warps; each 16-lane half owns 2 adjacent v-columns (VPC=16/CTA).
#define TCH 32
#define VPC 16
__global__ void __launch_bounds__(128) scan_kernel(float* __restrict__ sOut)
{
    __shared__ float sk[TCH][DK];
    __shared__ float sq[TCH][DK];
    __shared__ float sv[TCH][VPC];
    __shared__ float se[TCH], sbt[TCH];

    int tid  = threadIdx.x;
    int wid  = tid >> 5, lane = tid & 31;
    int bh   = blockIdx.x / (DV/VPC);
    int vblk = (blockIdx.x % (DV/VPC)) * VPC;
    int half = lane >> 4, l16 = lane & 15;
    int lpair = wid*4 + half*2;       // 0,2,..,14 within CTA
    int ko   = l16 * 8;

    int b = bh / HH, h = bh % HH;
    const float* kb = g_kn + (size_t)bh*LL*DK;
    const float* qb = g_qn + (size_t)bh*LL*DK;
    const float* vb = g_vc + (size_t)bh*LL*DV;
    const float* eb = g_eg + (size_t)bh*LL;
    const float* bb = g_beta + (size_t)bh*LL;
    float* ob = g_o + (size_t)b*LL*VD + h*DV + vblk + lpair;

    float sA[8], sB[8];
#pragma unroll
    for (int j = 0; j < 8; j++) { sA[j] = 0.f; sB[j] = 0.f; }

    for (int ch = 0; ch < LL/TCH; ch++) {
        int t0 = ch * TCH;
        __syncthreads();
#pragma unroll
        for (int i = tid; i < TCH*DK/4; i += 128) {
            ((float4*)sk)[i] = ((const float4*)(kb + (size_t)t0*DK))[i];
            ((float4*)sq)[i] = ((const float4*)(qb + (size_t)t0*DK))[i];
        }
        {
            int i = tid;                       // TCH*VPC/4 == 128
            int tl = i / (VPC/4), vq = (i % (VPC/4)) * 4;
            *(float4*)&sv[tl][vq] = *(const float4*)(vb + (size_t)(t0+tl)*DV + vblk + vq);
        }
        if (tid < TCH) { se[tid] = eb[t0+tid]; sbt[tid] = bb[t0+tid]; }
        __syncthreads();

#pragma unroll 4
        for (int tl = 0; tl < TCH; tl++) {
            float4 k0 = *(float4*)&sk[tl][ko];
            float4 k1 = *(float4*)&sk[tl][ko+4];
            float eg = se[tl], bt = sbt[tl];
            float vA = sv[tl][lpair], vB = sv[tl][lpair+1];
#pragma unroll
            for (int j = 0; j < 8; j++) { sA[j] *= eg; sB[j] *= eg; }
            float cA = k0.x*sA[0] + k0.y*sA[1] + k0.z*sA[2] + k0.w*sA[3]
                     + k1.x*sA[4] + k1.y*sA[5] + k1.z*sA[6] + k1.w*sA[7];
            float cB = k0.x*sB[0] + k0.y*sB[1] + k0.z*sB[2] + k0.w*sB[3]
                     + k1.x*sB[4] + k1.y*sB[5] + k1.z*sB[6] + k1.w*sB[7];
#pragma unroll
            for (int off = 8; off; off >>= 1) {
                cA += __shfl_xor_sync(0xffffffffu, cA, off);
                cB += __shfl_xor_sync(0xffffffffu, cB, off);
            }
            float uA = (vA - cA) * bt;
            float uB = (vB - cB) * bt;
            sA[0] += k0.x*uA; sA[1] += k0.y*uA; sA[2] += k0.z*uA; sA[3] += k0.w*uA;
            sA[4] += k1.x*uA; sA[5] += k1.y*uA; sA[6] += k1.z*uA; sA[7] += k1.w*uA;
            sB[0] += k0.x*uB; sB[1] += k0.y*uB; sB[2] += k0.z*uB; sB[3] += k0.w*uB;
            sB[4] += k1.x*uB; sB[5] += k1.y*uB; sB[6] += k1.z*uB; sB[7] += k1.w*uB;
            float4 q0 = *(float4*)&sq[tl][ko];
            float4 q1 = *(float4*)&sq[tl][ko+4];
            float oA = q0.x*sA[0] + q0.y*sA[1] + q0.z*sA[2] + q0.w*sA[3]
                     + q1.x*sA[4] + q1.y*sA[5] + q1.z*sA[6] + q1.w*sA[7];
            float oB = q0.x*sB[0] + q0.y*sB[1] + q0.z*sB[2] + q0.w*sB[3]
                     + q1.x*sB[4] + q1.y*sB[5] + q1.z*sB[6] + q1.w*sB[7];
#pragma unroll
            for (int off = 8; off; off >>= 1) {
                oA += __shfl_xor_sync(0xffffffffu, oA, off);
                oB += __shfl_xor_sync(0xffffffffu, oB, off);
            }
            if (l16 == 0) {
                ob[(size_t)(t0+tl)*VD]     = oA;
                ob[(size_t)(t0+tl)*VD + 1] = oB;
            }
        }
    }

    if (sOut) {
        size_t base = (size_t)bh*DK*DV + vblk + lpair;
#pragma unroll
        for (int j = 0; j < 8; j++) {
            sOut[base + (size_t)(ko+j)*DV]     = sA[j];
            sOut[base + (size_t)(ko+j)*DV + 1] = sB[j];
        }
    }
}

// ---------------- gated RMS norm -> fp16 hi/lo -------------------------------
__global__ void __launch_bounds__(256) gate_kernel(
    const float* __restrict__ P, const float* __restrict__ norm_w)
{
    int gw   = blockIdx.x*8 + (threadIdx.x >> 5);
    int lane = threadIdx.x & 31;
    int row  = gw / HH;
    int h    = gw % HH;
    size_t base  = (size_t)row*VD + h*DV;
    size_t gbase = (size_t)row*NP + 2*KD + VD + h*DV;

    float4 o0 = *(float4*)(g_o + base + lane*4);
    float4 o1 = *(float4*)(g_o + base + 128 + lane*4);
    float ss = o0.x*o0.x + o0.y*o0.y + o0.z*o0.z + o0.w*o0.w
             + o1.x*o1.x + o1.y*o1.y + o1.z*o1.z + o1.w*o1.w;
#pragma unroll
    for (int off = 16; off; off >>= 1) ss += __shfl_xor_sync(0xffffffffu, ss, off);
    float r = rsqrtf(ss * (1.f/DV) + 1e-5f);

    float4 gt0 = *(const float4*)(P + gbase + lane*4);
    float4 gt1 = *(const float4*)(P + gbase + 128 + lane*4);
    float4 nw0 = *(const float4*)(norm_w + lane*4);
    float4 nw1 = *(const float4*)(norm_w + 128 + lane*4);

    float f[8];
    f[0] = o0.x * r * nw0.x * (gt0.x / (1.f + expf(-gt0.x)));
    f[1] = o0.y * r * nw0.y * (gt0.y / (1.f + expf(-gt0.y)));
    f[2] = o0.z * r * nw0.z * (gt0.z / (1.f + expf(-gt0.z)));
    f[3] = o0.w * r * nw0.w * (gt0.w / (1.f + expf(-gt0.w)));
    f[4] = o1.x * r * nw1.x * (gt1.x / (1.f + expf(-gt1.x)));
    f[5] = o1.y * r * nw1.y * (gt1.y / (1.f + expf(-gt1.y)));
    f[6] = o1.z * r * nw1.z * (gt1.z / (1.f + expf(-gt1.z)));
    f[7] = o1.w * r * nw1.w * (gt1.w / (1.f + expf(-gt1.w)));

#pragma unroll
    for (int hf = 0; hf < 2; hf++) {
        size_t off = base + hf*128 + lane*4;
        __half h0 = __float2half(f[hf*4+0]);
        __half h1 = __float2half(f[hf*4+1]);
        __half h2 = __float2half(f[hf*4+2]);
        __half h3 = __float2half(f[hf*4+3]);
        *(__half2*)(g_oh + off)     = __half2(h0, h1);
        *(__half2*)(g_oh + off + 2) = __half2(h2, h3);
        __half l0 = __float2half(f[hf*4+0] - __half2float(h0));
        __half l1 = __float2half(f[hf*4+1] - __half2float(h1));
        __half l2 = __float2half(f[hf*4+2] - __half2float(h2));
        __half l3 = __float2half(f[hf*4+3] - __half2float(h3));
        *(__half2*)(g_ol + off)     = __half2(l0, l1);
        *(__half2*)(g_ol + off + 2) = __half2(l2, l3);
    }
}

// ---------------- launcher ---------------------------------------------------
extern "C" void kernel_launch(void* const* d_in, const int* in_sizes, int n_in,
                              void* d_out, int out_size)
{
    const float* x       = (const float*)d_in[0];
    const float* Wq      = (const float*)d_in[1];
    const float* Wk      = (const float*)d_in[2];
    const float* Wv      = (const float*)d_in[3];
    const float* Wb      = (const float*)d_in[4];
    const float* Wa      = (const float*)d_in[5];
    const float* A_log   = (const float*)d_in[6];
    const float* dt_bias = (const float*)d_in[7];
    const float* conv_q  = (const float*)d_in[8];
    const float* conv_k  = (const float*)d_in[9];
    const float* conv_v  = (const float*)d_in[10];
    const float* Wg      = (const float*)d_in[11];
    const float* norm_w  = (const float*)d_in[12];
    const float* Wo      = (const float*)d_in[13];
    float* out = (float*)d_out;

    float *pproj, *pqn, *pkn;
    cudaGetSymbolAddress((void**)&pproj, g_proj);
    cudaGetSymbolAddress((void**)&pqn, g_qn);
    cudaGetSymbolAddress((void**)&pkn, g_kn);

    __half *xh, *xl, *wc, *wo, *oh, *ol;
    cudaGetSymbolAddress((void**)&xh, g_xh);  cudaGetSymbolAddress((void**)&xl, g_xl);
    cudaGetSymbolAddress((void**)&wc, g_wc);  cudaGetSymbolAddress((void**)&wo, g_wo);
    cudaGetSymbolAddress((void**)&oh, g_oh);  cudaGetSymbolAddress((void**)&ol, g_ol);

    const int GEMM_SMEM = 3 * 24576;
    cudaFuncSetAttribute(gemm_mma_fp16x2,
                         cudaFuncAttributeMaxDynamicSharedMemorySize, GEMM_SMEM);

    dim3 blk(256);
    // prep: split x (fp16 hi/lo), fused transpose+round of all weights
    splitx_kernel<<<TOK*DD/(256*4), blk>>>(x);
    wsplit_all<<<6144, blk>>>(Wq, Wk, Wv, Wg, Wo);
    // fused projection GEMM: [TOK, NP]
    gemm_mma_fp16x2<<<dim3(NP/128, TOK/128), blk, GEMM_SMEM>>>(xh, xl, wc, pproj, TOK, NP, DD);
    // beta / decay
    betag_kernel<<<TOK*HH/8, blk>>>(x, Wb, Wa, A_log, dt_bias);
    // fused conv + silu (+ l2norm for q/k)
    conv_all<<<dim3(1536, 4), blk>>>(pproj, conv_q, conv_k, conv_v, pqn, pkn);
    // scan
    float* sOut = (out_size >= TOK*DD + BB*HH*DK*DV) ? (out + (size_t)TOK*DD) : nullptr;
    scan_kernel<<<BB*HH*(DV/VPC), 128>>>(sOut);
    // gated rms-norm -> fp16 split
    gate_kernel<<<TOK*HH/8, blk>>>(pproj, norm_w);
    // output projection
    gemm_mma_fp16x2<<<dim3(DD/128, TOK/128), blk, GEMM_SMEM>>>(oh, ol, wo, out, TOK, DD, VD);
}

// round 8
// speedup vs baseline: 2.5436x; 1.0051x over previous
#include <cuda_runtime.h>
#include <cuda_fp16.h>
#include <math.h>
#include <stdint.h>

#define BB 2
#define LL 1024
#define DD 1024
#define HH 6
#define DK 128
#define DV 256
#define KD 768
#define VD 1536
#define TOK (BB*LL)
#define NP 4608   // fused projection width: KD + KD + VD + VD

// ---------------- device scratch ----------------
__device__ __align__(16) float g_proj[TOK*NP];      // [q | k | v | gate]
__device__ __align__(16) float g_qn[BB*HH*LL*DK];
__device__ __align__(16) float g_kn[BB*HH*LL*DK];
__device__ __align__(16) float g_vc[BB*HH*LL*DV];
__device__ __align__(16) float g_eg[BB*HH*LL];
__device__ __align__(16) float g_beta[BB*HH*LL];
__device__ __align__(16) float g_o[TOK*VD];

// fp16 buffers (A side: hi+lo split; B side: single fp16)
__device__ __align__(16) __half g_xh[TOK*DD], g_xl[TOK*DD];
__device__ __align__(16) __half g_wc[NP*DD];        // fused W^T fp16
__device__ __align__(16) __half g_wo[DD*VD];        // Wo^T fp16
__device__ __align__(16) __half g_oh[TOK*VD], g_ol[TOK*VD];

// ---------------- helpers ----------------
__device__ __forceinline__ uint32_t smem_u32(const void* p) {
    uint32_t a;
    asm("{ .reg .u64 t; cvta.to.shared.u64 t, %1; cvt.u32.u64 %0, t; }" : "=r"(a) : "l"(p));
    return a;
}

#define MMA_FP16(d, a, b0v, b1v) \
    asm volatile("mma.sync.aligned.m16n8k16.row.col.f32.f16.f16.f32 " \
        "{%0,%1,%2,%3},{%4,%5,%6,%7},{%8,%9},{%0,%1,%2,%3};" \
        : "+f"(d[0]), "+f"(d[1]), "+f"(d[2]), "+f"(d[3]) \
        : "r"(a[0]), "r"(a[1]), "r"(a[2]), "r"(a[3]), "r"(b0v), "r"(b1v))

#define LDMATRIX_X4(r0, r1, r2, r3, addr) \
    asm volatile("ldmatrix.sync.aligned.m8n8.x4.shared.b16 {%0,%1,%2,%3}, [%4];" \
        : "=r"(r0), "=r"(r1), "=r"(r2), "=r"(r3) : "r"(addr))

// One K-chunk (BK=32) of Ah/Al/B into stage (c%3). Stage = 3*8KB = 24KB.
__device__ __forceinline__ void issue_chunk3(
    int tid, int m0, int n0, int K, int c, uint32_t sb,
    const __half* Ah, const __half* Al, const __half* B)
{
    int k0 = c << 5;
    uint32_t bufo = (uint32_t)(c % 3) * 24576u;
#pragma unroll
    for (int it = 0; it < 6; it++) {
        const int buf = it >> 1;                 // 0:Ah 1:Al 2:B
        int idx = tid + (it << 8);
        int r   = (idx >> 2) & 127;
        int cc  = idx & 3;
        const __half* s = (buf == 0) ? Ah : (buf == 1) ? Al : B;
        int rowg = ((buf < 2) ? m0 : n0) + r;
        const void* g = s + (size_t)rowg * K + k0 + (cc << 3);
        uint32_t sa = sb + bufo + ((uint32_t)buf << 13)
                    + (uint32_t)(r * 64 + ((cc ^ (r & 3)) << 4));
        asm volatile("cp.async.cg.shared.global [%0], [%1], 16;" :: "r"(sa), "l"(g));
    }
    asm volatile("cp.async.commit_group;");
}

// ---------------- fp16x2 mma.sync GEMM: C[M,N] = A[M,K] @ Bt[N,K]^T ---------
__global__ void __launch_bounds__(256, 2) gemm_mma_fp16x2(
    const __half* __restrict__ Ah, const __half* __restrict__ Al,
    const __half* __restrict__ B, float* __restrict__ C, int M, int N, int K)
{
    extern __shared__ char smem[];
    uint32_t sb = smem_u32(smem);
    int tid = threadIdx.x, lane = tid & 31, wid = tid >> 5;
    int m0 = blockIdx.y * 128, n0 = blockIdx.x * 128;
    int wm = (wid >> 2) * 64, wn = (wid & 3) * 32;

    float acc[4][4][4];
#pragma unroll
    for (int i = 0; i < 4; i++)
#pragma unroll
        for (int j = 0; j < 4; j++)
#pragma unroll
            for (int r = 0; r < 4; r++) acc[i][j][r] = 0.f;

    const int nch = K >> 5;
    issue_chunk3(tid, m0, n0, K, 0, sb, Ah, Al, B);
    issue_chunk3(tid, m0, n0, K, 1, sb, Ah, Al, B);

    int a_row_l = lane & 15;
    int a_kh    = lane >> 4;
    int b_row_l = ((lane >> 4) << 3) + (lane & 7);
    int b_kh    = (lane >> 3) & 1;

    for (int c = 0; c < nch; c++) {
        if (c + 2 < nch) {
            issue_chunk3(tid, m0, n0, K, c + 2, sb, Ah, Al, B);
            asm volatile("cp.async.wait_group 2;");
        } else if (c + 1 < nch) {
            asm volatile("cp.async.wait_group 1;");
        } else {
            asm volatile("cp.async.wait_group 0;");
        }
        __syncthreads();

        uint32_t bufo = sb + (uint32_t)(c % 3) * 24576u;
#pragma unroll 1
        for (int ks = 0; ks < 2; ks++) {
            uint32_t ah[4][4], al[4][4], bf[2][4];
#pragma unroll
            for (int mf = 0; mf < 4; mf++) {
                int row = wm + mf * 16 + a_row_l;
                int ch  = (ks * 2 + a_kh) ^ (row & 3);
                uint32_t ad = bufo + (uint32_t)(row * 64 + ch * 16);
                LDMATRIX_X4(ah[mf][0], ah[mf][1], ah[mf][2], ah[mf][3], ad);
                LDMATRIX_X4(al[mf][0], al[mf][1], al[mf][2], al[mf][3], ad + 8192u);
            }
#pragma unroll
            for (int np = 0; np < 2; np++) {
                int row = wn + np * 16 + b_row_l;
                int ch  = (ks * 2 + b_kh) ^ (row & 3);
                uint32_t bd = bufo + 16384u + (uint32_t)(row * 64 + ch * 16);
                LDMATRIX_X4(bf[np][0], bf[np][1], bf[np][2], bf[np][3], bd);
            }
#pragma unroll
            for (int mf = 0; mf < 4; mf++)
#pragma unroll
                for (int nf = 0; nf < 4; nf++) {
                    int np = nf >> 1, wh = (nf & 1) * 2;
                    MMA_FP16(acc[mf][nf], ah[mf], bf[np][wh], bf[np][wh + 1]);
                    MMA_FP16(acc[mf][nf], al[mf], bf[np][wh], bf[np][wh + 1]);
                }
        }
        __syncthreads();
    }

#pragma unroll
    for (int mf = 0; mf < 4; mf++) {
        int row = m0 + wm + mf * 16 + (lane >> 2);
#pragma unroll
        for (int nf = 0; nf < 4; nf++) {
            int col = n0 + wn + nf * 8 + (lane & 3) * 2;
            *(float2*)(C + (size_t)row * N + col) =
                make_float2(acc[mf][nf][0], acc[mf][nf][1]);
            *(float2*)(C + (size_t)(row + 8) * N + col) =
                make_float2(acc[mf][nf][2], acc[mf][nf][3]);
        }
    }
}

// ---------------- split x into fp16 hi/lo -----------------------------------
__global__ void __launch_bounds__(256) splitx_kernel(const float* __restrict__ x)
{
    int i = (blockIdx.x * 256 + threadIdx.x) * 4;
    float4 v = *(const float4*)(x + i);
    __half h0 = __float2half(v.x), h1 = __float2half(v.y);
    __half h2 = __float2half(v.z), h3 = __float2half(v.w);
    __half l0 = __float2half(v.x - __half2float(h0));
    __half l1 = __float2half(v.y - __half2float(h1));
    __half l2 = __float2half(v.z - __half2float(h2));
    __half l3 = __float2half(v.w - __half2float(h3));
    *(__half2*)(g_xh + i)     = __half2(h0, h1);
    *(__half2*)(g_xh + i + 2) = __half2(h2, h3);
    *(__half2*)(g_xl + i)     = __half2(l0, l1);
    *(__half2*)(g_xl + i + 2) = __half2(l2, l3);
}

// ---------------- fused transpose of all 5 weights -> fp16 ------------------
__global__ void __launch_bounds__(256) wsplit_all(
    const float* __restrict__ Wq, const float* __restrict__ Wk,
    const float* __restrict__ Wv, const float* __restrict__ Wg,
    const float* __restrict__ Wo)
{
    int bid = blockIdx.x;
    const float* W; __half* T; int Kd, Nd, rowOff, lt;
    if (bid < 768)       { W = Wq; T = g_wc; Kd = 1024; Nd = 768;  rowOff = 0;        lt = bid; }
    else if (bid < 1536) { W = Wk; T = g_wc; Kd = 1024; Nd = 768;  rowOff = KD;       lt = bid - 768; }
    else if (bid < 3072) { W = Wv; T = g_wc; Kd = 1024; Nd = 1536; rowOff = 2*KD;     lt = bid - 1536; }
    else if (bid < 4608) { W = Wg; T = g_wc; Kd = 1024; Nd = 1536; rowOff = 2*KD+VD;  lt = bid - 3072; }
    else                 { W = Wo; T = g_wo; Kd = 1536; Nd = 1024; rowOff = 0;        lt = bid - 4608; }
    int ntx = Nd >> 5;
    int bx = lt % ntx, by = lt / ntx;

    __shared__ float tile[32][33];
    int tx = threadIdx.x & 31, ty = threadIdx.x >> 5;
    int n = bx*32 + tx;
    int k0 = by*32;
#pragma unroll
    for (int i = ty; i < 32; i += 8)
        tile[i][tx] = W[(size_t)(k0 + i) * Nd + n];
    __syncthreads();
#pragma unroll
    for (int i = ty; i < 32; i += 8) {
        int row = rowOff + bx*32 + i;
        T[(size_t)row * Kd + k0 + tx] = __float2half(tile[tx][i]);
    }
}

// ---------------- beta / decay: one warp per token, all 6 heads --------------
__global__ void __launch_bounds__(256) betag_kernel(
    const float* __restrict__ x, const float* __restrict__ Wb,
    const float* __restrict__ Wa, const float* __restrict__ A_log,
    const float* __restrict__ dt_bias)
{
    int row  = blockIdx.x*8 + (threadIdx.x >> 5);   // token 0..TOK-1
    int lane = threadIdx.x & 31;
    const float* xr = x + (size_t)row*DD;

    float sb[HH], sa[HH];
#pragma unroll
    for (int h = 0; h < HH; h++) { sb[h] = 0.f; sa[h] = 0.f; }

#pragma unroll 2
    for (int d = lane; d < DD; d += 32) {
        float xv = xr[d];
        float2 b01 = *(const float2*)(Wb + d*HH);
        float2 b23 = *(const float2*)(Wb + d*HH + 2);
        float2 b45 = *(const float2*)(Wb + d*HH + 4);
        float2 a01 = *(const float2*)(Wa + d*HH);
        float2 a23 = *(const float2*)(Wa + d*HH + 2);
        float2 a45 = *(const float2*)(Wa + d*HH + 4);
        sb[0] += xv*b01.x; sb[1] += xv*b01.y; sb[2] += xv*b23.x;
        sb[3] += xv*b23.y; sb[4] += xv*b45.x; sb[5] += xv*b45.y;
        sa[0] += xv*a01.x; sa[1] += xv*a01.y; sa[2] += xv*a23.x;
        sa[3] += xv*a23.y; sa[4] += xv*a45.x; sa[5] += xv*a45.y;
    }
#pragma unroll
    for (int off = 16; off; off >>= 1) {
#pragma unroll
        for (int h = 0; h < HH; h++) {
            sb[h] += __shfl_xor_sync(0xffffffffu, sb[h], off);
            sa[h] += __shfl_xor_sync(0xffffffffu, sa[h], off);
        }
    }
    if (lane < HH) {
        int h = lane;
        int b = row >> 10, t = row & 1023;
        float beta = 1.f / (1.f + expf(-sb[h]));
        float z = sa[h] + dt_bias[h];
        float sp = (z > 20.f) ? z : log1pf(expf(z));
        float eg = expf(-expf(A_log[h]) * sp);
        int idx = (b*HH + h)*LL + t;
        g_beta[idx] = beta;
        g_eg[idx]   = eg;
    }
}

// ---------------- fused conv: y=0 q, y=1 k, y=2/3 v --------------------------
__global__ void __launch_bounds__(256) conv_all(
    const float* __restrict__ P, const float* __restrict__ Wq,
    const float* __restrict__ Wk, const float* __restrict__ Wv,
    float* __restrict__ Oq, float* __restrict__ Ok)
{
    int y = blockIdx.y;
    if (y < 2) {
        int poff  = y * KD;
        const float* W = y ? Wk : Wq;
        float* Out = y ? Ok : Oq;
        float qscale = y ? 1.0f : 0.08838834764831845f;

        int gw   = blockIdx.x*8 + (threadIdx.x >> 5);
        int lane = threadIdx.x & 31;
        int b   = gw / (HH*LL);
        int rem = gw % (HH*LL);
        int h   = rem / LL;
        int t   = rem % LL;
        int c0  = h*DK + lane*4;

        float w0[4], w1[4], w2[4], w3[4];
        *(float4*)w0 = *(const float4*)(W + (c0+0)*4);
        *(float4*)w1 = *(const float4*)(W + (c0+1)*4);
        *(float4*)w2 = *(const float4*)(W + (c0+2)*4);
        *(float4*)w3 = *(const float4*)(W + (c0+3)*4);

        float a[4] = {0.f, 0.f, 0.f, 0.f};
#pragma unroll
        for (int j = 0; j < 4; j++) {
            int tt = t - 3 + j;
            if (tt >= 0) {
                float4 xv = *(const float4*)(P + (size_t)(b*LL + tt)*NP + poff + c0);
                a[0] += xv.x * w0[j];
                a[1] += xv.y * w1[j];
                a[2] += xv.z * w2[j];
                a[3] += xv.w * w3[j];
            }
        }
#pragma unroll
        for (int i = 0; i < 4; i++) { float z = a[i]; a[i] = z / (1.f + expf(-z)); }
        float ss = a[0]*a[0] + a[1]*a[1] + a[2]*a[2] + a[3]*a[3];
#pragma unroll
        for (int off = 16; off; off >>= 1) ss += __shfl_xor_sync(0xffffffffu, ss, off);
        float r = rsqrtf(ss + 1e-12f) * qscale;
        float4 o = make_float4(a[0]*r, a[1]*r, a[2]*r, a[3]*r);
        *(float4*)(Out + ((size_t)(b*HH + h)*LL + t)*DK + lane*4) = o;
    } else {
        int idx = ((y - 2) * 1536 + blockIdx.x)*256 + threadIdx.x;
        int c4i = idx % (VD/4);
        int row = idx / (VD/4);
        int c0  = c4i*4;
        int b = row >> 10, t = row & 1023;

        float w0[4], w1[4], w2[4], w3[4];
        *(float4*)w0 = *(const float4*)(Wv + (c0+0)*4);
        *(float4*)w1 = *(const float4*)(Wv + (c0+1)*4);
        *(float4*)w2 = *(const float4*)(Wv + (c0+2)*4);
        *(float4*)w3 = *(const float4*)(Wv + (c0+3)*4);

        float a[4] = {0.f, 0.f, 0.f, 0.f};
#pragma unroll
        for (int j = 0; j < 4; j++) {
            int tt = t - 3 + j;
            if (tt >= 0) {
                float4 xv = *(const float4*)(P + (size_t)(b*LL + tt)*NP + 2*KD + c0);
                a[0] += xv.x * w0[j];
                a[1] += xv.y * w1[j];
                a[2] += xv.z * w2[j];
                a[3] += xv.w * w3[j];
            }
        }
#pragma unroll
        for (int i = 0; i < 4; i++) { float z = a[i]; a[i] = z / (1.f + expf(-z)); }
        int h  = c0 / DV;
        int dv = c0 % DV;
        float4 o = make_float4(a[0], a[1], a[2], a[3]);
        *(float4*)(g_vc + ((size_t)(b*HH + h)*LL + t)*DV + dv) = o;
    }
}

// ---------------- delta-rule scan: 2 interleaved columns per thread ----------
#define TCH 32
#define VPC 16
__global__ void __launch_bounds__(128) scan_kernel(float* __restrict__ sOut)
{
    __shared__ float sk[TCH][DK];
    __shared__ float sq[TCH][DK];
    __shared__ float sv[TCH][VPC];
    __shared__ float se[TCH], sbt[TCH];

    int tid  = threadIdx.x;
    int wid  = tid >> 5, lane = tid & 31;
    int bh   = blockIdx.x / (DV/VPC);
    int vblk = (blockIdx.x % (DV/VPC)) * VPC;
    int half = lane >> 4, l16 = lane & 15;
    int lpair = wid*4 + half*2;
    int ko   = l16 * 8;

    int b = bh / HH, h = bh % HH;
    const float* kb = g_kn + (size_t)bh*LL*DK;
    const float* qb = g_qn + (size_t)bh*LL*DK;
    const float* vb = g_vc + (size_t)bh*LL*DV;
    const float* eb = g_eg + (size_t)bh*LL;
    const float* bb = g_beta + (size_t)bh*LL;
    float* ob = g_o + (size_t)b*LL*VD + h*DV + vblk + lpair;

    float sA[8], sB[8];
#pragma unroll
    for (int j = 0; j < 8; j++) { sA[j] = 0.f; sB[j] = 0.f; }

    for (int ch = 0; ch < LL/TCH; ch++) {
        int t0 = ch * TCH;
        __syncthreads();
#pragma unroll
        for (int i = tid; i < TCH*DK/4; i += 128) {
            ((float4*)sk)[i] = ((const float4*)(kb + (size_t)t0*DK))[i];
            ((float4*)sq)[i] = ((const float4*)(qb + (size_t)t0*DK))[i];
        }
        {
            int i = tid;
            int tl = i / (VPC/4), vq = (i % (VPC/4)) * 4;
            *(float4*)&sv[tl][vq] = *(const float4*)(vb + (size_t)(t0+tl)*DV + vblk + vq);
        }
        if (tid < TCH) { se[tid] = eb[t0+tid]; sbt[tid] = bb[t0+tid]; }
        __syncthreads();

#pragma unroll 4
        for (int tl = 0; tl < TCH; tl++) {
            float4 k0 = *(float4*)&sk[tl][ko];
            float4 k1 = *(float4*)&sk[tl][ko+4];
            float eg = se[tl], bt = sbt[tl];
            float vA = sv[tl][lpair], vB = sv[tl][lpair+1];
#pragma unroll
            for (int j = 0; j < 8; j++) { sA[j] *= eg; sB[j] *= eg; }
            float cA = k0.x*sA[0] + k0.y*sA[1] + k0.z*sA[2] + k0.w*sA[3]
                     + k1.x*sA[4] + k1.y*sA[5] + k1.z*sA[6] + k1.w*sA[7];
            float cB = k0.x*sB[0] + k0.y*sB[1] + k0.z*sB[2] + k0.w*sB[3]
                     + k1.x*sB[4] + k1.y*sB[5] + k1.z*sB[6] + k1.w*sB[7];
#pragma unroll
            for (int off = 8; off; off >>= 1) {
                cA += __shfl_xor_sync(0xffffffffu, cA, off);
                cB += __shfl_xor_sync(0xffffffffu, cB, off);
            }
            float uA = (vA - cA) * bt;
            float uB = (vB - cB) * bt;
            sA[0] += k0.x*uA; sA[1] += k0.y*uA; sA[2] += k0.z*uA; sA[3] += k0.w*uA;
            sA[4] += k1.x*uA; sA[5] += k1.y*uA; sA[6] += k1.z*uA; sA[7] += k1.w*uA;
            sB[0] += k0.x*uB; sB[1] += k0.y*uB; sB[2] += k0.z*uB; sB[3] += k0.w*uB;
            sB[4] += k1.x*uB; sB[5] += k1.y*uB; sB[6] += k1.z*uB; sB[7] += k1.w*uB;
            float4 q0 = *(float4*)&sq[tl][ko];
            float4 q1 = *(float4*)&sq[tl][ko+4];
            float oA = q0.x*sA[0] + q0.y*sA[1] + q0.z*sA[2] + q0.w*sA[3]
                     + q1.x*sA[4] + q1.y*sA[5] + q1.z*sA[6] + q1.w*sA[7];
            float oB = q0.x*sB[0] + q0.y*sB[1] + q0.z*sB[2] + q0.w*sB[3]
                     + q1.x*sB[4] + q1.y*sB[5] + q1.z*sB[6] + q1.w*sB[7];
#pragma unroll
            for (int off = 8; off; off >>= 1) {
                oA += __shfl_xor_sync(0xffffffffu, oA, off);
                oB += __shfl_xor_sync(0xffffffffu, oB, off);
            }
            if (l16 == 0) {
                ob[(size_t)(t0+tl)*VD]     = oA;
                ob[(size_t)(t0+tl)*VD + 1] = oB;
            }
        }
    }

    if (sOut) {
        size_t base = (size_t)bh*DK*DV + vblk + lpair;
#pragma unroll
        for (int j = 0; j < 8; j++) {
            sOut[base + (size_t)(ko+j)*DV]     = sA[j];
            sOut[base + (size_t)(ko+j)*DV + 1] = sB[j];
        }
    }
}

// ---------------- gated RMS norm -> fp16 hi/lo -------------------------------
__global__ void __launch_bounds__(256) gate_kernel(
    const float* __restrict__ P, const float* __restrict__ norm_w)
{
    int gw   = blockIdx.x*8 + (threadIdx.x >> 5);
    int lane = threadIdx.x & 31;
    int row  = gw / HH;
    int h    = gw % HH;
    size_t base  = (size_t)row*VD + h*DV;
    size_t gbase = (size_t)row*NP + 2*KD + VD + h*DV;

    float4 o0 = *(float4*)(g_o + base + lane*4);
    float4 o1 = *(float4*)(g_o + base + 128 + lane*4);
    float ss = o0.x*o0.x + o0.y*o0.y + o0.z*o0.z + o0.w*o0.w
             + o1.x*o1.x + o1.y*o1.y + o1.z*o1.z + o1.w*o1.w;
#pragma unroll
    for (int off = 16; off; off >>= 1) ss += __shfl_xor_sync(0xffffffffu, ss, off);
    float r = rsqrtf(ss * (1.f/DV) + 1e-5f);

    float4 gt0 = *(const float4*)(P + gbase + lane*4);
    float4 gt1 = *(const float4*)(P + gbase + 128 + lane*4);
    float4 nw0 = *(const float4*)(norm_w + lane*4);
    float4 nw1 = *(const float4*)(norm_w + 128 + lane*4);

    float f[8];
    f[0] = o0.x * r * nw0.x * (gt0.x / (1.f + expf(-gt0.x)));
    f[1] = o0.y * r * nw0.y * (gt0.y / (1.f + expf(-gt0.y)));
    f[2] = o0.z * r * nw0.z * (gt0.z / (1.f + expf(-gt0.z)));
    f[3] = o0.w * r * nw0.w * (gt0.w / (1.f + expf(-gt0.w)));
    f[4] = o1.x * r * nw1.x * (gt1.x / (1.f + expf(-gt1.x)));
    f[5] = o1.y * r * nw1.y * (gt1.y / (1.f + expf(-gt1.y)));
    f[6] = o1.z * r * nw1.z * (gt1.z / (1.f + expf(-gt1.z)));
    f[7] = o1.w * r * nw1.w * (gt1.w / (1.f + expf(-gt1.w)));

#pragma unroll
    for (int hf = 0; hf < 2; hf++) {
        size_t off = base + hf*128 + lane*4;
        __half h0 = __float2half(f[hf*4+0]);
        __half h1 = __float2half(f[hf*4+1]);
        __half h2 = __float2half(f[hf*4+2]);
        __half h3 = __float2half(f[hf*4+3]);
        *(__half2*)(g_oh + off)     = __half2(h0, h1);
        *(__half2*)(g_oh + off + 2) = __half2(h2, h3);
        __half l0 = __float2half(f[hf*4+0] - __half2float(h0));
        __half l1 = __float2half(f[hf*4+1] - __half2float(h1));
        __half l2 = __float2half(f[hf*4+2] - __half2float(h2));
        __half l3 = __float2half(f[hf*4+3] - __half2float(h3));
        *(__half2*)(g_ol + off)     = __half2(l0, l1);
        *(__half2*)(g_ol + off + 2) = __half2(l2, l3);
    }
}

// ---------------- launcher ---------------------------------------------------
extern "C" void kernel_launch(void* const* d_in, const int* in_sizes, int n_in,
                              void* d_out, int out_size)
{
    const float* x       = (const float*)d_in[0];
    const float* Wq      = (const float*)d_in[1];
    const float* Wk      = (const float*)d_in[2];
    const float* Wv      = (const float*)d_in[3];
    const float* Wb      = (const float*)d_in[4];
    const float* Wa      = (const float*)d_in[5];
    const float* A_log   = (const float*)d_in[6];
    const float* dt_bias = (const float*)d_in[7];
    const float* conv_q  = (const float*)d_in[8];
    const float* conv_k  = (const float*)d_in[9];
    const float* conv_v  = (const float*)d_in[10];
    const float* Wg      = (const float*)d_in[11];
    const float* norm_w  = (const float*)d_in[12];
    const float* Wo      = (const float*)d_in[13];
    float* out = (float*)d_out;

    float *pproj, *pqn, *pkn;
    cudaGetSymbolAddress((void**)&pproj, g_proj);
    cudaGetSymbolAddress((void**)&pqn, g_qn);
    cudaGetSymbolAddress((void**)&pkn, g_kn);

    __half *xh, *xl, *wc, *wo, *oh, *ol;
    cudaGetSymbolAddress((void**)&xh, g_xh);  cudaGetSymbolAddress((void**)&xl, g_xl);
    cudaGetSymbolAddress((void**)&wc, g_wc);  cudaGetSymbolAddress((void**)&wo, g_wo);
    cudaGetSymbolAddress((void**)&oh, g_oh);  cudaGetSymbolAddress((void**)&ol, g_ol);

    const int GEMM_SMEM = 3 * 24576;
    cudaFuncSetAttribute(gemm_mma_fp16x2,
                         cudaFuncAttributeMaxDynamicSharedMemorySize, GEMM_SMEM);

    dim3 blk(256);
    splitx_kernel<<<TOK*DD/(256*4), blk>>>(x);
    wsplit_all<<<6144, blk>>>(Wq, Wk, Wv, Wg, Wo);
    gemm_mma_fp16x2<<<dim3(NP/128, TOK/128), blk, GEMM_SMEM>>>(xh, xl, wc, pproj, TOK, NP, DD);
    betag_kernel<<<TOK/8, blk>>>(x, Wb, Wa, A_log, dt_bias);
    conv_all<<<dim3(1536, 4), blk>>>(pproj, conv_q, conv_k, conv_v, pqn, pkn);
    float* sOut = (out_size >= TOK*DD + BB*HH*DK*DV) ? (out + (size_t)TOK*DD) : nullptr;
    scan_kernel<<<BB*HH*(DV/VPC), 128>>>(sOut);
    gate_kernel<<<TOK*HH/8, blk>>>(pproj, norm_w);
    gemm_mma_fp16x2<<<dim3(DD/128, TOK/128), blk, GEMM_SMEM>>>(oh, ol, wo, out, TOK, DD, VD);
}

// round 9
// speedup vs baseline: 2.6370x; 1.0367x over previous
#include <cuda_runtime.h>
#include <cuda_fp16.h>
#include <math.h>
#include <stdint.h>

#define BB 2
#define LL 1024
#define DD 1024
#define HH 6
#define DK 128
#define DV 256
#define KD 768
#define VD 1536
#define TOK (BB*LL)
#define NP 4608   // fused projection width: KD + KD + VD + VD

typedef unsigned long long u64;

// ---------------- device scratch ----------------
__device__ __align__(16) float g_proj[TOK*NP];      // [q | k | v | gate]
__device__ __align__(16) float g_qn[BB*HH*LL*DK];
__device__ __align__(16) float g_kn[BB*HH*LL*DK];
__device__ __align__(16) float g_vc[BB*HH*LL*DV];
__device__ __align__(16) float g_eg[BB*HH*LL];
__device__ __align__(16) float g_beta[BB*HH*LL];
__device__ __align__(16) float g_o[TOK*VD];

// fp16 buffers (A side: hi+lo split; B side: single fp16)
__device__ __align__(16) __half g_xh[TOK*DD], g_xl[TOK*DD];
__device__ __align__(16) __half g_wc[NP*DD];        // fused W^T fp16
__device__ __align__(16) __half g_wo[DD*VD];        // Wo^T fp16
__device__ __align__(16) __half g_oh[TOK*VD], g_ol[TOK*VD];

// ---------------- helpers ----------------
__device__ __forceinline__ uint32_t smem_u32(const void* p) {
    uint32_t a;
    asm("{ .reg .u64 t; cvta.to.shared.u64 t, %1; cvt.u32.u64 %0, t; }" : "=r"(a) : "l"(p));
    return a;
}

// packed fp32x2 ops (Blackwell) — two IEEE fp32 ops per instruction
__device__ __forceinline__ u64 pack2(float x, float y) {
    u64 r; asm("mov.b64 %0, {%1, %2};" : "=l"(r) : "f"(x), "f"(y)); return r;
}
__device__ __forceinline__ void unpack2(u64 v, float& x, float& y) {
    asm("mov.b64 {%0, %1}, %2;" : "=f"(x), "=f"(y) : "l"(v));
}
__device__ __forceinline__ u64 fma2(u64 a, u64 b, u64 c) {
    u64 d; asm("fma.rn.f32x2 %0, %1, %2, %3;" : "=l"(d) : "l"(a), "l"(b), "l"(c)); return d;
}
__device__ __forceinline__ u64 mul2(u64 a, u64 b) {
    u64 d; asm("mul.rn.f32x2 %0, %1, %2;" : "=l"(d) : "l"(a), "l"(b)); return d;
}

#define MMA_FP16(d, a, b0v, b1v) \
    asm volatile("mma.sync.aligned.m16n8k16.row.col.f32.f16.f16.f32 " \
        "{%0,%1,%2,%3},{%4,%5,%6,%7},{%8,%9},{%0,%1,%2,%3};" \
        : "+f"(d[0]), "+f"(d[1]), "+f"(d[2]), "+f"(d[3]) \
        : "r"(a[0]), "r"(a[1]), "r"(a[2]), "r"(a[3]), "r"(b0v), "r"(b1v))

#define LDMATRIX_X4(r0, r1, r2, r3, addr) \
    asm volatile("ldmatrix.sync.aligned.m8n8.x4.shared.b16 {%0,%1,%2,%3}, [%4];" \
        : "=r"(r0), "=r"(r1), "=r"(r2), "=r"(r3) : "r"(addr))

// One K-chunk (BK=32) of Ah/Al/B into stage (c%3). Stage = 3*8KB = 24KB.
__device__ __forceinline__ void issue_chunk3(
    int tid, int m0, int n0, int K, int c, uint32_t sb,
    const __half* Ah, const __half* Al, const __half* B)
{
    int k0 = c << 5;
    uint32_t bufo = (uint32_t)(c % 3) * 24576u;
#pragma unroll
    for (int it = 0; it < 6; it++) {
        const int buf = it >> 1;                 // 0:Ah 1:Al 2:B
        int idx = tid + (it << 8);
        int r   = (idx >> 2) & 127;
        int cc  = idx & 3;
        const __half* s = (buf == 0) ? Ah : (buf == 1) ? Al : B;
        int rowg = ((buf < 2) ? m0 : n0) + r;
        const void* g = s + (size_t)rowg * K + k0 + (cc << 3);
        uint32_t sa = sb + bufo + ((uint32_t)buf << 13)
                    + (uint32_t)(r * 64 + ((cc ^ (r & 3)) << 4));
        asm volatile("cp.async.cg.shared.global [%0], [%1], 16;" :: "r"(sa), "l"(g));
    }
    asm volatile("cp.async.commit_group;");
}

// ---------------- fp16x2 mma.sync GEMM: C[M,N] = A[M,K] @ Bt[N,K]^T ---------
__global__ void __launch_bounds__(256, 2) gemm_mma_fp16x2(
    const __half* __restrict__ Ah, const __half* __restrict__ Al,
    const __half* __restrict__ B, float* __restrict__ C, int M, int N, int K)
{
    extern __shared__ char smem[];
    uint32_t sb = smem_u32(smem);
    int tid = threadIdx.x, lane = tid & 31, wid = tid >> 5;
    int m0 = blockIdx.y * 128, n0 = blockIdx.x * 128;
    int wm = (wid >> 2) * 64, wn = (wid & 3) * 32;

    float acc[4][4][4];
#pragma unroll
    for (int i = 0; i < 4; i++)
#pragma unroll
        for (int j = 0; j < 4; j++)
#pragma unroll
            for (int r = 0; r < 4; r++) acc[i][j][r] = 0.f;

    const int nch = K >> 5;
    issue_chunk3(tid, m0, n0, K, 0, sb, Ah, Al, B);
    issue_chunk3(tid, m0, n0, K, 1, sb, Ah, Al, B);

    int a_row_l = lane & 15;
    int a_kh    = lane >> 4;
    int b_row_l = ((lane >> 4) << 3) + (lane & 7);
    int b_kh    = (lane >> 3) & 1;

    for (int c = 0; c < nch; c++) {
        if (c + 2 < nch) {
            issue_chunk3(tid, m0, n0, K, c + 2, sb, Ah, Al, B);
            asm volatile("cp.async.wait_group 2;");
        } else if (c + 1 < nch) {
            asm volatile("cp.async.wait_group 1;");
        } else {
            asm volatile("cp.async.wait_group 0;");
        }
        __syncthreads();

        uint32_t bufo = sb + (uint32_t)(c % 3) * 24576u;
#pragma unroll 1
        for (int ks = 0; ks < 2; ks++) {
            uint32_t ah[4][4], al[4][4], bf[2][4];
#pragma unroll
            for (int mf = 0; mf < 4; mf++) {
                int row = wm + mf * 16 + a_row_l;
                int ch  = (ks * 2 + a_kh) ^ (row & 3);
                uint32_t ad = bufo + (uint32_t)(row * 64 + ch * 16);
                LDMATRIX_X4(ah[mf][0], ah[mf][1], ah[mf][2], ah[mf][3], ad);
                LDMATRIX_X4(al[mf][0], al[mf][1], al[mf][2], al[mf][3], ad + 8192u);
            }
#pragma unroll
            for (int np = 0; np < 2; np++) {
                int row = wn + np * 16 + b_row_l;
                int ch  = (ks * 2 + b_kh) ^ (row & 3);
                uint32_t bd = bufo + 16384u + (uint32_t)(row * 64 + ch * 16);
                LDMATRIX_X4(bf[np][0], bf[np][1], bf[np][2], bf[np][3], bd);
            }
#pragma unroll
            for (int mf = 0; mf < 4; mf++)
#pragma unroll
                for (int nf = 0; nf < 4; nf++) {
                    int np = nf >> 1, wh = (nf & 1) * 2;
                    MMA_FP16(acc[mf][nf], ah[mf], bf[np][wh], bf[np][wh + 1]);
                    MMA_FP16(acc[mf][nf], al[mf], bf[np][wh], bf[np][wh + 1]);
                }
        }
        __syncthreads();
    }

#pragma unroll
    for (int mf = 0; mf < 4; mf++) {
        int row = m0 + wm + mf * 16 + (lane >> 2);
#pragma unroll
        for (int nf = 0; nf < 4; nf++) {
            int col = n0 + wn + nf * 8 + (lane & 3) * 2;
            *(float2*)(C + (size_t)row * N + col) =
                make_float2(acc[mf][nf][0], acc[mf][nf][1]);
            *(float2*)(C + (size_t)(row + 8) * N + col) =
                make_float2(acc[mf][nf][2], acc[mf][nf][3]);
        }
    }
}

// ---------------- split x into fp16 hi/lo -----------------------------------
__global__ void __launch_bounds__(256) splitx_kernel(const float* __restrict__ x)
{
    int i = (blockIdx.x * 256 + threadIdx.x) * 4;
    float4 v = *(const float4*)(x + i);
    __half h0 = __float2half(v.x), h1 = __float2half(v.y);
    __half h2 = __float2half(v.z), h3 = __float2half(v.w);
    __half l0 = __float2half(v.x - __half2float(h0));
    __half l1 = __float2half(v.y - __half2float(h1));
    __half l2 = __float2half(v.z - __half2float(h2));
    __half l3 = __float2half(v.w - __half2float(h3));
    *(__half2*)(g_xh + i)     = __half2(h0, h1);
    *(__half2*)(g_xh + i + 2) = __half2(h2, h3);
    *(__half2*)(g_xl + i)     = __half2(l0, l1);
    *(__half2*)(g_xl + i + 2) = __half2(l2, l3);
}

// ---------------- fused transpose of all 5 weights -> fp16 ------------------
__global__ void __launch_bounds__(256) wsplit_all(
    const float* __restrict__ Wq, const float* __restrict__ Wk,
    const float* __restrict__ Wv, const float* __restrict__ Wg,
    const float* __restrict__ Wo)
{
    int bid = blockIdx.x;
    const float* W; __half* T; int Kd, Nd, rowOff, lt;
    if (bid < 768)       { W = Wq; T = g_wc; Kd = 1024; Nd = 768;  rowOff = 0;        lt = bid; }
    else if (bid < 1536) { W = Wk; T = g_wc; Kd = 1024; Nd = 768;  rowOff = KD;       lt = bid - 768; }
    else if (bid < 3072) { W = Wv; T = g_wc; Kd = 1024; Nd = 1536; rowOff = 2*KD;     lt = bid - 1536; }
    else if (bid < 4608) { W = Wg; T = g_wc; Kd = 1024; Nd = 1536; rowOff = 2*KD+VD;  lt = bid - 3072; }
    else                 { W = Wo; T = g_wo; Kd = 1536; Nd = 1024; rowOff = 0;        lt = bid - 4608; }
    int ntx = Nd >> 5;
    int bx = lt % ntx, by = lt / ntx;

    __shared__ float tile[32][33];
    int tx = threadIdx.x & 31, ty = threadIdx.x >> 5;
    int n = bx*32 + tx;
    int k0 = by*32;
#pragma unroll
    for (int i = ty; i < 32; i += 8)
        tile[i][tx] = W[(size_t)(k0 + i) * Nd + n];
    __syncthreads();
#pragma unroll
    for (int i = ty; i < 32; i += 8) {
        int row = rowOff + bx*32 + i;
        T[(size_t)row * Kd + k0 + tx] = __float2half(tile[tx][i]);
    }
}

// ---------------- beta / decay: smem-staged W, 16 tokens per CTA -------------
__global__ void __launch_bounds__(512) betag_kernel(
    const float* __restrict__ x, const float* __restrict__ Wb,
    const float* __restrict__ Wa, const float* __restrict__ A_log,
    const float* __restrict__ dt_bias)
{
    __shared__ float swb[HH][DD];
    __shared__ float swa[HH][DD];
    int tid = threadIdx.x;
    for (int i = tid; i < DD*HH; i += 512) {
        swb[i % HH][i / HH] = Wb[i];
        swa[i % HH][i / HH] = Wa[i];
    }
    __syncthreads();

    int row  = blockIdx.x*16 + (tid >> 5);   // token
    int lane = tid & 31;
    const float* xr = x + (size_t)row*DD;

    float sb[HH], sa[HH];
#pragma unroll
    for (int h = 0; h < HH; h++) { sb[h] = 0.f; sa[h] = 0.f; }

#pragma unroll
    for (int it = 0; it < DD/128; it++) {
        int d = it*128 + lane*4;
        float4 xv = *(const float4*)(xr + d);
#pragma unroll
        for (int h = 0; h < HH; h++) {
            float4 wb = *(const float4*)&swb[h][d];
            float4 wa = *(const float4*)&swa[h][d];
            sb[h] += xv.x*wb.x + xv.y*wb.y + xv.z*wb.z + xv.w*wb.w;
            sa[h] += xv.x*wa.x + xv.y*wa.y + xv.z*wa.z + xv.w*wa.w;
        }
    }
#pragma unroll
    for (int off = 16; off; off >>= 1) {
#pragma unroll
        for (int h = 0; h < HH; h++) {
            sb[h] += __shfl_xor_sync(0xffffffffu, sb[h], off);
            sa[h] += __shfl_xor_sync(0xffffffffu, sa[h], off);
        }
    }
    if (lane < HH) {
        int h = lane;
        int b = row >> 10, t = row & 1023;
        float beta = 1.f / (1.f + expf(-sb[h]));
        float z = sa[h] + dt_bias[h];
        float sp = (z > 20.f) ? z : log1pf(expf(z));
        float eg = expf(-expf(A_log[h]) * sp);
        int idx = (b*HH + h)*LL + t;
        g_beta[idx] = beta;
        g_eg[idx]   = eg;
    }
}

// ---------------- fused conv: y=0 q, y=1 k, y=2/3 v --------------------------
__global__ void __launch_bounds__(256) conv_all(
    const float* __restrict__ P, const float* __restrict__ Wq,
    const float* __restrict__ Wk, const float* __restrict__ Wv,
    float* __restrict__ Oq, float* __restrict__ Ok)
{
    int y = blockIdx.y;
    if (y < 2) {
        int poff  = y * KD;
        const float* W = y ? Wk : Wq;
        float* Out = y ? Ok : Oq;
        float qscale = y ? 1.0f : 0.08838834764831845f;

        int gw   = blockIdx.x*8 + (threadIdx.x >> 5);
        int lane = threadIdx.x & 31;
        int b   = gw / (HH*LL);
        int rem = gw % (HH*LL);
        int h   = rem / LL;
        int t   = rem % LL;
        int c0  = h*DK + lane*4;

        float w0[4], w1[4], w2[4], w3[4];
        *(float4*)w0 = *(const float4*)(W + (c0+0)*4);
        *(float4*)w1 = *(const float4*)(W + (c0+1)*4);
        *(float4*)w2 = *(const float4*)(W + (c0+2)*4);
        *(float4*)w3 = *(const float4*)(W + (c0+3)*4);

        float a[4] = {0.f, 0.f, 0.f, 0.f};
#pragma unroll
        for (int j = 0; j < 4; j++) {
            int tt = t - 3 + j;
            if (tt >= 0) {
                float4 xv = *(const float4*)(P + (size_t)(b*LL + tt)*NP + poff + c0);
                a[0] += xv.x * w0[j];
                a[1] += xv.y * w1[j];
                a[2] += xv.z * w2[j];
                a[3] += xv.w * w3[j];
            }
        }
#pragma unroll
        for (int i = 0; i < 4; i++) { float z = a[i]; a[i] = z / (1.f + expf(-z)); }
        float ss = a[0]*a[0] + a[1]*a[1] + a[2]*a[2] + a[3]*a[3];
#pragma unroll
        for (int off = 16; off; off >>= 1) ss += __shfl_xor_sync(0xffffffffu, ss, off);
        float r = rsqrtf(ss + 1e-12f) * qscale;
        float4 o = make_float4(a[0]*r, a[1]*r, a[2]*r, a[3]*r);
        *(float4*)(Out + ((size_t)(b*HH + h)*LL + t)*DK + lane*4) = o;
    } else {
        int idx = ((y - 2) * 1536 + blockIdx.x)*256 + threadIdx.x;
        int c4i = idx % (VD/4);
        int row = idx / (VD/4);
        int c0  = c4i*4;
        int b = row >> 10, t = row & 1023;

        float w0[4], w1[4], w2[4], w3[4];
        *(float4*)w0 = *(const float4*)(Wv + (c0+0)*4);
        *(float4*)w1 = *(const float4*)(Wv + (c0+1)*4);
        *(float4*)w2 = *(const float4*)(Wv + (c0+2)*4);
        *(float4*)w3 = *(const float4*)(Wv + (c0+3)*4);

        float a[4] = {0.f, 0.f, 0.f, 0.f};
#pragma unroll
        for (int j = 0; j < 4; j++) {
            int tt = t - 3 + j;
            if (tt >= 0) {
                float4 xv = *(const float4*)(P + (size_t)(b*LL + tt)*NP + 2*KD + c0);
                a[0] += xv.x * w0[j];
                a[1] += xv.y * w1[j];
                a[2] += xv.z * w2[j];
                a[3] += xv.w * w3[j];
            }
        }
#pragma unroll
        for (int i = 0; i < 4; i++) { float z = a[i]; a[i] = z / (1.f + expf(-z)); }
        int h  = c0 / DV;
        int dv = c0 % DV;
        float4 o = make_float4(a[0], a[1], a[2], a[3]);
        *(float4*)(g_vc + ((size_t)(b*HH + h)*LL + t)*DV + dv) = o;
    }
}

// ---------------- delta-rule scan: f32x2-packed, 2 cols per thread -----------
#define TCH 32
#define VPC 16
__global__ void __launch_bounds__(128) scan_kernel(float* __restrict__ sOut)
{
    __shared__ float sk[TCH][DK];
    __shared__ float sq[TCH][DK];
    __shared__ float sv[TCH][VPC];
    __shared__ float se[TCH], sbt[TCH];

    int tid  = threadIdx.x;
    int wid  = tid >> 5, lane = tid & 31;
    int bh   = blockIdx.x / (DV/VPC);
    int vblk = (blockIdx.x % (DV/VPC)) * VPC;
    int half = lane >> 4, l16 = lane & 15;
    int lpair = wid*4 + half*2;
    int ko   = l16 * 8;

    int b = bh / HH, h = bh % HH;
    const float* kb = g_kn + (size_t)bh*LL*DK;
    const float* qb = g_qn + (size_t)bh*LL*DK;
    const float* vb = g_vc + (size_t)bh*LL*DV;
    const float* eb = g_eg + (size_t)bh*LL;
    const float* bb = g_beta + (size_t)bh*LL;
    float* ob = g_o + (size_t)b*LL*VD + h*DV + vblk + lpair;

    u64 sA[4], sB[4];
#pragma unroll
    for (int j = 0; j < 4; j++) { sA[j] = 0ull; sB[j] = 0ull; }

    for (int ch = 0; ch < LL/TCH; ch++) {
        int t0 = ch * TCH;
        __syncthreads();
#pragma unroll
        for (int i = tid; i < TCH*DK/4; i += 128) {
            ((float4*)sk)[i] = ((const float4*)(kb + (size_t)t0*DK))[i];
            ((float4*)sq)[i] = ((const float4*)(qb + (size_t)t0*DK))[i];
        }
        {
            int i = tid;
            int tl = i / (VPC/4), vq = (i % (VPC/4)) * 4;
            *(float4*)&sv[tl][vq] = *(const float4*)(vb + (size_t)(t0+tl)*DV + vblk + vq);
        }
        if (tid < TCH) { se[tid] = eb[t0+tid]; sbt[tid] = bb[t0+tid]; }
        __syncthreads();

#pragma unroll 4
        for (int tl = 0; tl < TCH; tl++) {
            const u64* kp = (const u64*)&sk[tl][ko];
            u64 k0 = kp[0], k1 = kp[1], k2 = kp[2], k3 = kp[3];
            float eg = se[tl], bt = sbt[tl];
            float vA = sv[tl][lpair], vB = sv[tl][lpair+1];
            u64 egp = pack2(eg, eg);
#pragma unroll
            for (int j = 0; j < 4; j++) { sA[j] = mul2(sA[j], egp); sB[j] = mul2(sB[j], egp); }

            u64 cap = mul2(k0, sA[0]); cap = fma2(k1, sA[1], cap);
            cap = fma2(k2, sA[2], cap); cap = fma2(k3, sA[3], cap);
            u64 cbp = mul2(k0, sB[0]); cbp = fma2(k1, sB[1], cbp);
            cbp = fma2(k2, sB[2], cbp); cbp = fma2(k3, sB[3], cbp);
            float cax, cay, cbx, cby;
            unpack2(cap, cax, cay); unpack2(cbp, cbx, cby);
            float cA = cax + cay, cB = cbx + cby;
#pragma unroll
            for (int off = 8; off; off >>= 1) {
                cA += __shfl_xor_sync(0xffffffffu, cA, off);
                cB += __shfl_xor_sync(0xffffffffu, cB, off);
            }
            float uA = (vA - cA) * bt;
            float uB = (vB - cB) * bt;
            u64 uap = pack2(uA, uA), ubp = pack2(uB, uB);
            sA[0] = fma2(k0, uap, sA[0]); sA[1] = fma2(k1, uap, sA[1]);
            sA[2] = fma2(k2, uap, sA[2]); sA[3] = fma2(k3, uap, sA[3]);
            sB[0] = fma2(k0, ubp, sB[0]); sB[1] = fma2(k1, ubp, sB[1]);
            sB[2] = fma2(k2, ubp, sB[2]); sB[3] = fma2(k3, ubp, sB[3]);

            const u64* qp = (const u64*)&sq[tl][ko];
            u64 q0 = qp[0], q1 = qp[1], q2 = qp[2], q3 = qp[3];
            u64 oap = mul2(q0, sA[0]); oap = fma2(q1, sA[1], oap);
            oap = fma2(q2, sA[2], oap); oap = fma2(q3, sA[3], oap);
            u64 obp = mul2(q0, sB[0]); obp = fma2(q1, sB[1], obp);
            obp = fma2(q2, sB[2], obp); obp = fma2(q3, sB[3], obp);
            float oax, oay, obx, oby;
            unpack2(oap, oax, oay); unpack2(obp, obx, oby);
            float oA = oax + oay, oB = obx + oby;
#pragma unroll
            for (int off = 8; off; off >>= 1) {
                oA += __shfl_xor_sync(0xffffffffu, oA, off);
                oB += __shfl_xor_sync(0xffffffffu, oB, off);
            }
            if (l16 == 0) {
                ob[(size_t)(t0+tl)*VD]     = oA;
                ob[(size_t)(t0+tl)*VD + 1] = oB;
            }
        }
    }

    if (sOut) {
        size_t base = (size_t)bh*DK*DV + vblk + lpair;
#pragma unroll
        for (int j = 0; j < 4; j++) {
            float a0, a1, b0, b1;
            unpack2(sA[j], a0, a1); unpack2(sB[j], b0, b1);
            sOut[base + (size_t)(ko+2*j)*DV]       = a0;
            sOut[base + (size_t)(ko+2*j+1)*DV]     = a1;
            sOut[base + (size_t)(ko+2*j)*DV + 1]   = b0;
            sOut[base + (size_t)(ko+2*j+1)*DV + 1] = b1;
        }
    }
}

// ---------------- gated RMS norm -> fp16 hi/lo -------------------------------
__global__ void __launch_bounds__(256) gate_kernel(
    const float* __restrict__ P, const float* __restrict__ norm_w)
{
    int gw   = blockIdx.x*8 + (threadIdx.x >> 5);
    int lane = threadIdx.x & 31;
    int row  = gw / HH;
    int h    = gw % HH;
    size_t base  = (size_t)row*VD + h*DV;
    size_t gbase = (size_t)row*NP + 2*KD + VD + h*DV;

    float4 o0 = *(float4*)(g_o + base + lane*4);
    float4 o1 = *(float4*)(g_o + base + 128 + lane*4);
    float ss = o0.x*o0.x + o0.y*o0.y + o0.z*o0.z + o0.w*o0.w
             + o1.x*o1.x + o1.y*o1.y + o1.z*o1.z + o1.w*o1.w;
#pragma unroll
    for (int off = 16; off; off >>= 1) ss += __shfl_xor_sync(0xffffffffu, ss, off);
    float r = rsqrtf(ss * (1.f/DV) + 1e-5f);

    float4 gt0 = *(const float4*)(P + gbase + lane*4);
    float4 gt1 = *(const float4*)(P + gbase + 128 + lane*4);
    float4 nw0 = *(const float4*)(norm_w + lane*4);
    float4 nw1 = *(const float4*)(norm_w + 128 + lane*4);

    float f[8];
    f[0] = o0.x * r * nw0.x * (gt0.x / (1.f + expf(-gt0.x)));
    f[1] = o0.y * r * nw0.y * (gt0.y / (1.f + expf(-gt0.y)));
    f[2] = o0.z * r * nw0.z * (gt0.z / (1.f + expf(-gt0.z)));
    f[3] = o0.w * r * nw0.w * (gt0.w / (1.f + expf(-gt0.w)));
    f[4] = o1.x * r * nw1.x * (gt1.x / (1.f + expf(-gt1.x)));
    f[5] = o1.y * r * nw1.y * (gt1.y / (1.f + expf(-gt1.y)));
    f[6] = o1.z * r * nw1.z * (gt1.z / (1.f + expf(-gt1.z)));
    f[7] = o1.w * r * nw1.w * (gt1.w / (1.f + expf(-gt1.w)));

#pragma unroll
    for (int hf = 0; hf < 2; hf++) {
        size_t off = base + hf*128 + lane*4;
        __half h0 = __float2half(f[hf*4+0]);
        __half h1 = __float2half(f[hf*4+1]);
        __half h2 = __float2half(f[hf*4+2]);
        __half h3 = __float2half(f[hf*4+3]);
        *(__half2*)(g_oh + off)     = __half2(h0, h1);
        *(__half2*)(g_oh + off + 2) = __half2(h2, h3);
        __half l0 = __float2half(f[hf*4+0] - __half2float(h0));
        __half l1 = __float2half(f[hf*4+1] - __half2float(h1));
        __half l2 = __float2half(f[hf*4+2] - __half2float(h2));
        __half l3 = __float2half(f[hf*4+3] - __half2float(h3));
        *(__half2*)(g_ol + off)     = __half2(l0, l1);
        *(__half2*)(g_ol + off + 2) = __half2(l2, l3);
    }
}

// ---------------- launcher ---------------------------------------------------
extern "C" void kernel_launch(void* const* d_in, const int* in_sizes, int n_in,
                              void* d_out, int out_size)
{
    const float* x       = (const float*)d_in[0];
    const float* Wq      = (const float*)d_in[1];
    const float* Wk      = (const float*)d_in[2];
    const float* Wv      = (const float*)d_in[3];
    const float* Wb      = (const float*)d_in[4];
    const float* Wa      = (const float*)d_in[5];
    const float* A_log   = (const float*)d_in[6];
    const float* dt_bias = (const float*)d_in[7];
    const float* conv_q  = (const float*)d_in[8];
    const float* conv_k  = (const float*)d_in[9];
    const float* conv_v  = (const float*)d_in[10];
    const float* Wg      = (const float*)d_in[11];
    const float* norm_w  = (const float*)d_in[12];
    const float* Wo      = (const float*)d_in[13];
    float* out = (float*)d_out;

    float *pproj, *pqn, *pkn;
    cudaGetSymbolAddress((void**)&pproj, g_proj);
    cudaGetSymbolAddress((void**)&pqn, g_qn);
    cudaGetSymbolAddress((void**)&pkn, g_kn);

    __half *xh, *xl, *wc, *wo, *oh, *ol;
    cudaGetSymbolAddress((void**)&xh, g_xh);  cudaGetSymbolAddress((void**)&xl, g_xl);
    cudaGetSymbolAddress((void**)&wc, g_wc);  cudaGetSymbolAddress((void**)&wo, g_wo);
    cudaGetSymbolAddress((void**)&oh, g_oh);  cudaGetSymbolAddress((void**)&ol, g_ol);

    const int GEMM_SMEM = 3 * 24576;
    cudaFuncSetAttribute(gemm_mma_fp16x2,
                         cudaFuncAttributeMaxDynamicSharedMemorySize, GEMM_SMEM);

    dim3 blk(256);
    splitx_kernel<<<TOK*DD/(256*4), blk>>>(x);
    wsplit_all<<<6144, blk>>>(Wq, Wk, Wv, Wg, Wo);
    betag_kernel<<<TOK/16, 512>>>(x, Wb, Wa, A_log, dt_bias);   // moved up: 4th launch = GEMM
    gemm_mma_fp16x2<<<dim3(NP/128, TOK/128), blk, GEMM_SMEM>>>(xh, xl, wc, pproj, TOK, NP, DD);
    conv_all<<<dim3(1536, 4), blk>>>(pproj, conv_q, conv_k, conv_v, pqn, pkn);
    float* sOut = (out_size >= TOK*DD + BB*HH*DK*DV) ? (out + (size_t)TOK*DD) : nullptr;
    scan_kernel<<<BB*HH*(DV/VPC), 128>>>(sOut);
    gate_kernel<<<TOK*HH/8, blk>>>(pproj, norm_w);
    gemm_mma_fp16x2<<<dim3(DD/128, TOK/128), blk, GEMM_SMEM>>>(oh, ol, wo, out, TOK, DD, VD);
}

// round 10
// speedup vs baseline: 2.6938x; 1.0216x over previous
#include <cuda_runtime.h>
#include <cuda_fp16.h>
#include <math.h>
#include <stdint.h>

#define BB 2
#define LL 1024
#define DD 1024
#define HH 6
#define DK 128
#define DV 256
#define KD 768
#define VD 1536
#define TOK (BB*LL)
#define NP 4608

typedef unsigned long long u64;

// ---------------- device scratch ----------------
__device__ __align__(16) float g_proj[TOK*NP];
__device__ __align__(16) float g_qn[BB*HH*LL*DK];
__device__ __align__(16) float g_kn[BB*HH*LL*DK];
__device__ __align__(16) float g_vc[BB*HH*LL*DV];
__device__ __align__(16) float g_eg[BB*HH*LL];
__device__ __align__(16) float g_beta[BB*HH*LL];
__device__ __align__(16) float g_o[TOK*VD];

__device__ __align__(16) __half g_xh[TOK*DD], g_xl[TOK*DD];
__device__ __align__(16) __half g_wc[NP*DD];
__device__ __align__(16) __half g_wo[DD*VD];
__device__ __align__(16) __half g_oh[TOK*VD], g_ol[TOK*VD];

// ---------------- helpers ----------------
__device__ __forceinline__ uint32_t smem_u32(const void* p) {
    uint32_t a;
    asm("{ .reg .u64 t; cvta.to.shared.u64 t, %1; cvt.u32.u64 %0, t; }" : "=r"(a) : "l"(p));
    return a;
}
__device__ __forceinline__ u64 pack2(float x, float y) {
    u64 r; asm("mov.b64 %0, {%1, %2};" : "=l"(r) : "f"(x), "f"(y)); return r;
}
__device__ __forceinline__ void unpack2(u64 v, float& x, float& y) {
    asm("mov.b64 {%0, %1}, %2;" : "=f"(x), "=f"(y) : "l"(v));
}
__device__ __forceinline__ u64 fma2(u64 a, u64 b, u64 c) {
    u64 d; asm("fma.rn.f32x2 %0, %1, %2, %3;" : "=l"(d) : "l"(a), "l"(b), "l"(c)); return d;
}
__device__ __forceinline__ u64 mul2(u64 a, u64 b) {
    u64 d; asm("mul.rn.f32x2 %0, %1, %2;" : "=l"(d) : "l"(a), "l"(b)); return d;
}

#define MMA_FP16(d, a, b0v, b1v) \
    asm volatile("mma.sync.aligned.m16n8k16.row.col.f32.f16.f16.f32 " \
        "{%0,%1,%2,%3},{%4,%5,%6,%7},{%8,%9},{%0,%1,%2,%3};" \
        : "+f"(d[0]), "+f"(d[1]), "+f"(d[2]), "+f"(d[3]) \
        : "r"(a[0]), "r"(a[1]), "r"(a[2]), "r"(a[3]), "r"(b0v), "r"(b1v))

#define LDMATRIX_X4(r0, r1, r2, r3, addr) \
    asm volatile("ldmatrix.sync.aligned.m8n8.x4.shared.b16 {%0,%1,%2,%3}, [%4];" \
        : "=r"(r0), "=r"(r1), "=r"(r2), "=r"(r3) : "r"(addr))

// ============ narrow GEMM (128x128 CTA) — used for output projection ========
__device__ __forceinline__ void issue_chunk3(
    int tid, int m0, int n0, int K, int c, uint32_t sb,
    const __half* Ah, const __half* Al, const __half* B)
{
    int k0 = c << 5;
    uint32_t bufo = (uint32_t)(c % 3) * 24576u;
#pragma unroll
    for (int it = 0; it < 6; it++) {
        const int buf = it >> 1;
        int idx = tid + (it << 8);
        int r   = (idx >> 2) & 127;
        int cc  = idx & 3;
        const __half* s = (buf == 0) ? Ah : (buf == 1) ? Al : B;
        int rowg = ((buf < 2) ? m0 : n0) + r;
        const void* g = s + (size_t)rowg * K + k0 + (cc << 3);
        uint32_t sa = sb + bufo + ((uint32_t)buf << 13)
                    + (uint32_t)(r * 64 + ((cc ^ (r & 3)) << 4));
        asm volatile("cp.async.cg.shared.global [%0], [%1], 16;" :: "r"(sa), "l"(g));
    }
    asm volatile("cp.async.commit_group;");
}

__global__ void __launch_bounds__(256, 2) gemm_mma_fp16x2(
    const __half* __restrict__ Ah, const __half* __restrict__ Al,
    const __half* __restrict__ B, float* __restrict__ C, int M, int N, int K)
{
    extern __shared__ char smem[];
    uint32_t sb = smem_u32(smem);
    int tid = threadIdx.x, lane = tid & 31, wid = tid >> 5;
    int m0 = blockIdx.y * 128, n0 = blockIdx.x * 128;
    int wm = (wid >> 2) * 64, wn = (wid & 3) * 32;

    float acc[4][4][4];
#pragma unroll
    for (int i = 0; i < 4; i++)
#pragma unroll
        for (int j = 0; j < 4; j++)
#pragma unroll
            for (int r = 0; r < 4; r++) acc[i][j][r] = 0.f;

    const int nch = K >> 5;
    issue_chunk3(tid, m0, n0, K, 0, sb, Ah, Al, B);
    issue_chunk3(tid, m0, n0, K, 1, sb, Ah, Al, B);

    int a_row_l = lane & 15;
    int a_kh    = lane >> 4;
    int b_row_l = ((lane >> 4) << 3) + (lane & 7);
    int b_kh    = (lane >> 3) & 1;

    for (int c = 0; c < nch; c++) {
        if (c + 2 < nch) {
            issue_chunk3(tid, m0, n0, K, c + 2, sb, Ah, Al, B);
            asm volatile("cp.async.wait_group 2;");
        } else if (c + 1 < nch) {
            asm volatile("cp.async.wait_group 1;");
        } else {
            asm volatile("cp.async.wait_group 0;");
        }
        __syncthreads();

        uint32_t bufo = sb + (uint32_t)(c % 3) * 24576u;
#pragma unroll 1
        for (int ks = 0; ks < 2; ks++) {
            uint32_t ah[4][4], al[4][4], bf[2][4];
#pragma unroll
            for (int mf = 0; mf < 4; mf++) {
                int row = wm + mf * 16 + a_row_l;
                int ch  = (ks * 2 + a_kh) ^ (row & 3);
                uint32_t ad = bufo + (uint32_t)(row * 64 + ch * 16);
                LDMATRIX_X4(ah[mf][0], ah[mf][1], ah[mf][2], ah[mf][3], ad);
                LDMATRIX_X4(al[mf][0], al[mf][1], al[mf][2], al[mf][3], ad + 8192u);
            }
#pragma unroll
            for (int np = 0; np < 2; np++) {
                int row = wn + np * 16 + b_row_l;
                int ch  = (ks * 2 + b_kh) ^ (row & 3);
                uint32_t bd = bufo + 16384u + (uint32_t)(row * 64 + ch * 16);
                LDMATRIX_X4(bf[np][0], bf[np][1], bf[np][2], bf[np][3], bd);
            }
#pragma unroll
            for (int mf = 0; mf < 4; mf++)
#pragma unroll
                for (int nf = 0; nf < 4; nf++) {
                    int np = nf >> 1, wh = (nf & 1) * 2;
                    MMA_FP16(acc[mf][nf], ah[mf], bf[np][wh], bf[np][wh + 1]);
                    MMA_FP16(acc[mf][nf], al[mf], bf[np][wh], bf[np][wh + 1]);
                }
        }
        __syncthreads();
    }

#pragma unroll
    for (int mf = 0; mf < 4; mf++) {
        int row = m0 + wm + mf * 16 + (lane >> 2);
#pragma unroll
        for (int nf = 0; nf < 4; nf++) {
            int col = n0 + wn + nf * 8 + (lane & 3) * 2;
            *(float2*)(C + (size_t)row * N + col) =
                make_float2(acc[mf][nf][0], acc[mf][nf][1]);
            *(float2*)(C + (size_t)(row + 8) * N + col) =
                make_float2(acc[mf][nf][2], acc[mf][nf][3]);
        }
    }
}

// ============ wide GEMM (128x256 CTA, warp 64x64, 1 CTA/SM) ==================
// Stage = Ah 8KB | Al 8KB | B 16KB = 32KB; 3 stages = 96KB.
__device__ __forceinline__ void issue_chunk_w(
    int tid, int m0, int n0, int K, int c, uint32_t sb,
    const __half* Ah, const __half* Al, const __half* B)
{
    int k0 = c << 5;
    uint32_t bufo = (uint32_t)(c % 3) * 32768u;
#pragma unroll
    for (int it = 0; it < 8; it++) {
        int idx = tid + (it << 8);
        const void* g;
        uint32_t sa;
        if (it < 4) {                       // Ah (it 0,1) / Al (it 2,3)
            const __half* s = (it < 2) ? Ah : Al;
            int r  = (idx >> 2) & 127;
            int cc = idx & 3;
            g  = s + (size_t)(m0 + r) * K + k0 + (cc << 3);
            sa = sb + bufo + ((it < 2) ? 0u : 8192u)
               + (uint32_t)(r * 64 + ((cc ^ (r & 3)) << 4));
        } else {                            // B rows 0..255
            int lidx = idx - 1024;
            int r  = lidx >> 2;
            int cc = lidx & 3;
            g  = B + (size_t)(n0 + r) * K + k0 + (cc << 3);
            sa = sb + bufo + 16384u
               + (uint32_t)(r * 64 + ((cc ^ (r & 3)) << 4));
        }
        asm volatile("cp.async.cg.shared.global [%0], [%1], 16;" :: "r"(sa), "l"(g));
    }
    asm volatile("cp.async.commit_group;");
}

__global__ void __launch_bounds__(256, 1) gemm_mma_fp16x2_wide(
    const __half* __restrict__ Ah, const __half* __restrict__ Al,
    const __half* __restrict__ B, float* __restrict__ C, int M, int N, int K)
{
    extern __shared__ char smem[];
    uint32_t sb = smem_u32(smem);
    int tid = threadIdx.x, lane = tid & 31, wid = tid >> 5;
    int m0 = blockIdx.y * 128, n0 = blockIdx.x * 256;
    int wm = (wid >> 2) * 64, wn = (wid & 3) * 64;

    float acc[4][8][4];
#pragma unroll
    for (int i = 0; i < 4; i++)
#pragma unroll
        for (int j = 0; j < 8; j++)
#pragma unroll
            for (int r = 0; r < 4; r++) acc[i][j][r] = 0.f;

    const int nch = K >> 5;
    issue_chunk_w(tid, m0, n0, K, 0, sb, Ah, Al, B);
    issue_chunk_w(tid, m0, n0, K, 1, sb, Ah, Al, B);

    int a_row_l = lane & 15;
    int a_kh    = lane >> 4;
    int b_row_l = ((lane >> 4) << 3) + (lane & 7);
    int b_kh    = (lane >> 3) & 1;

    for (int c = 0; c < nch; c++) {
        if (c + 2 < nch) {
            issue_chunk_w(tid, m0, n0, K, c + 2, sb, Ah, Al, B);
            asm volatile("cp.async.wait_group 2;");
        } else if (c + 1 < nch) {
            asm volatile("cp.async.wait_group 1;");
        } else {
            asm volatile("cp.async.wait_group 0;");
        }
        __syncthreads();

        uint32_t bufo = sb + (uint32_t)(c % 3) * 32768u;
#pragma unroll 1
        for (int ks = 0; ks < 2; ks++) {
            uint32_t ah[4][4], al[4][4], bf[4][4];
#pragma unroll
            for (int mf = 0; mf < 4; mf++) {
                int row = wm + mf * 16 + a_row_l;
                int ch  = (ks * 2 + a_kh) ^ (row & 3);
                uint32_t ad = bufo + (uint32_t)(row * 64 + ch * 16);
                LDMATRIX_X4(ah[mf][0], ah[mf][1], ah[mf][2], ah[mf][3], ad);
                LDMATRIX_X4(al[mf][0], al[mf][1], al[mf][2], al[mf][3], ad + 8192u);
            }
#pragma unroll
            for (int np = 0; np < 4; np++) {
                int row = wn + np * 16 + b_row_l;
                int ch  = (ks * 2 + b_kh) ^ (row & 3);
                uint32_t bd = bufo + 16384u + (uint32_t)(row * 64 + ch * 16);
                LDMATRIX_X4(bf[np][0], bf[np][1], bf[np][2], bf[np][3], bd);
            }
#pragma unroll
            for (int mf = 0; mf < 4; mf++)
#pragma unroll
                for (int nf = 0; nf < 8; nf++) {
                    int np = nf >> 1, wh = (nf & 1) * 2;
                    MMA_FP16(acc[mf][nf], ah[mf], bf[np][wh], bf[np][wh + 1]);
                    MMA_FP16(acc[mf][nf], al[mf], bf[np][wh], bf[np][wh + 1]);
                }
        }
        __syncthreads();
    }

#pragma unroll
    for (int mf = 0; mf < 4; mf++) {
        int row = m0 + wm + mf * 16 + (lane >> 2);
#pragma unroll
        for (int nf = 0; nf < 8; nf++) {
            int col = n0 + wn + nf * 8 + (lane & 3) * 2;
            *(float2*)(C + (size_t)row * N + col) =
                make_float2(acc[mf][nf][0], acc[mf][nf][1]);
            *(float2*)(C + (size_t)(row + 8) * N + col) =
                make_float2(acc[mf][nf][2], acc[mf][nf][3]);
        }
    }
}

// ---------------- split x into fp16 hi/lo -----------------------------------
__global__ void __launch_bounds__(256) splitx_kernel(const float* __restrict__ x)
{
    int i = (blockIdx.x * 256 + threadIdx.x) * 4;
    float4 v = *(const float4*)(x + i);
    __half h0 = __float2half(v.x), h1 = __float2half(v.y);
    __half h2 = __float2half(v.z), h3 = __float2half(v.w);
    __half l0 = __float2half(v.x - __half2float(h0));
    __half l1 = __float2half(v.y - __half2float(h1));
    __half l2 = __float2half(v.z - __half2float(h2));
    __half l3 = __float2half(v.w - __half2float(h3));
    *(__half2*)(g_xh + i)     = __half2(h0, h1);
    *(__half2*)(g_xh + i + 2) = __half2(h2, h3);
    *(__half2*)(g_xl + i)     = __half2(l0, l1);
    *(__half2*)(g_xl + i + 2) = __half2(l2, l3);
}

// ---------------- fused transpose of all 5 weights -> fp16 ------------------
__global__ void __launch_bounds__(256) wsplit_all(
    const float* __restrict__ Wq, const float* __restrict__ Wk,
    const float* __restrict__ Wv, const float* __restrict__ Wg,
    const float* __restrict__ Wo)
{
    int bid = blockIdx.x;
    const float* W; __half* T; int Kd, Nd, rowOff, lt;
    if (bid < 768)       { W = Wq; T = g_wc; Kd = 1024; Nd = 768;  rowOff = 0;        lt = bid; }
    else if (bid < 1536) { W = Wk; T = g_wc; Kd = 1024; Nd = 768;  rowOff = KD;       lt = bid - 768; }
    else if (bid < 3072) { W = Wv; T = g_wc; Kd = 1024; Nd = 1536; rowOff = 2*KD;     lt = bid - 1536; }
    else if (bid < 4608) { W = Wg; T = g_wc; Kd = 1024; Nd = 1536; rowOff = 2*KD+VD;  lt = bid - 3072; }
    else                 { W = Wo; T = g_wo; Kd = 1536; Nd = 1024; rowOff = 0;        lt = bid - 4608; }
    int ntx = Nd >> 5;
    int bx = lt % ntx, by = lt / ntx;

    __shared__ float tile[32][33];
    int tx = threadIdx.x & 31, ty = threadIdx.x >> 5;
    int n = bx*32 + tx;
    int k0 = by*32;
#pragma unroll
    for (int i = ty; i < 32; i += 8)
        tile[i][tx] = W[(size_t)(k0 + i) * Nd + n];
    __syncthreads();
#pragma unroll
    for (int i = ty; i < 32; i += 8) {
        int row = rowOff + bx*32 + i;
        T[(size_t)row * Kd + k0 + tx] = __float2half(tile[tx][i]);
    }
}

// ---------------- beta / decay: smem-staged W, 16 tokens per CTA -------------
__global__ void __launch_bounds__(512) betag_kernel(
    const float* __restrict__ x, const float* __restrict__ Wb,
    const float* __restrict__ Wa, const float* __restrict__ A_log,
    const float* __restrict__ dt_bias)
{
    __shared__ float swb[HH][DD];
    __shared__ float swa[HH][DD];
    int tid = threadIdx.x;
    for (int i = tid; i < DD*HH; i += 512) {
        swb[i % HH][i / HH] = Wb[i];
        swa[i % HH][i / HH] = Wa[i];
    }
    __syncthreads();

    int row  = blockIdx.x*16 + (tid >> 5);
    int lane = tid & 31;
    const float* xr = x + (size_t)row*DD;

    float sb[HH], sa[HH];
#pragma unroll
    for (int h = 0; h < HH; h++) { sb[h] = 0.f; sa[h] = 0.f; }

#pragma unroll
    for (int it = 0; it < DD/128; it++) {
        int d = it*128 + lane*4;
        float4 xv = *(const float4*)(xr + d);
#pragma unroll
        for (int h = 0; h < HH; h++) {
            float4 wb = *(const float4*)&swb[h][d];
            float4 wa = *(const float4*)&swa[h][d];
            sb[h] += xv.x*wb.x + xv.y*wb.y + xv.z*wb.z + xv.w*wb.w;
            sa[h] += xv.x*wa.x + xv.y*wa.y + xv.z*wa.z + xv.w*wa.w;
        }
    }
#pragma unroll
    for (int off = 16; off; off >>= 1) {
#pragma unroll
        for (int h = 0; h < HH; h++) {
            sb[h] += __shfl_xor_sync(0xffffffffu, sb[h], off);
            sa[h] += __shfl_xor_sync(0xffffffffu, sa[h], off);
        }
    }
    if (lane < HH) {
        int h = lane;
        int b = row >> 10, t = row & 1023;
        float beta = 1.f / (1.f + expf(-sb[h]));
        float z = sa[h] + dt_bias[h];
        float sp = (z > 20.f) ? z : log1pf(expf(z));
        float eg = expf(-expf(A_log[h]) * sp);
        int idx = (b*HH + h)*LL + t;
        g_beta[idx] = beta;
        g_eg[idx]   = eg;
    }
}

// ---------------- fused conv: y=0 q, y=1 k, y=2/3 v --------------------------
__global__ void __launch_bounds__(256) conv_all(
    const float* __restrict__ P, const float* __restrict__ Wq,
    const float* __restrict__ Wk, const float* __restrict__ Wv,
    float* __restrict__ Oq, float* __restrict__ Ok)
{
    int y = blockIdx.y;
    if (y < 2) {
        int poff  = y * KD;
        const float* W = y ? Wk : Wq;
        float* Out = y ? Ok : Oq;
        float qscale = y ? 1.0f : 0.08838834764831845f;

        int gw   = blockIdx.x*8 + (threadIdx.x >> 5);
        int lane = threadIdx.x & 31;
        int b   = gw / (HH*LL);
        int rem = gw % (HH*LL);
        int h   = rem / LL;
        int t   = rem % LL;
        int c0  = h*DK + lane*4;

        float w0[4], w1[4], w2[4], w3[4];
        *(float4*)w0 = *(const float4*)(W + (c0+0)*4);
        *(float4*)w1 = *(const float4*)(W + (c0+1)*4);
        *(float4*)w2 = *(const float4*)(W + (c0+2)*4);
        *(float4*)w3 = *(const float4*)(W + (c0+3)*4);

        float a[4] = {0.f, 0.f, 0.f, 0.f};
#pragma unroll
        for (int j = 0; j < 4; j++) {
            int tt = t - 3 + j;
            if (tt >= 0) {
                float4 xv = *(const float4*)(P + (size_t)(b*LL + tt)*NP + poff + c0);
                a[0] += xv.x * w0[j];
                a[1] += xv.y * w1[j];
                a[2] += xv.z * w2[j];
                a[3] += xv.w * w3[j];
            }
        }
#pragma unroll
        for (int i = 0; i < 4; i++) { float z = a[i]; a[i] = z / (1.f + expf(-z)); }
        float ss = a[0]*a[0] + a[1]*a[1] + a[2]*a[2] + a[3]*a[3];
#pragma unroll
        for (int off = 16; off; off >>= 1) ss += __shfl_xor_sync(0xffffffffu, ss, off);
        float r = rsqrtf(ss + 1e-12f) * qscale;
        float4 o = make_float4(a[0]*r, a[1]*r, a[2]*r, a[3]*r);
        *(float4*)(Out + ((size_t)(b*HH + h)*LL + t)*DK + lane*4) = o;
    } else {
        int idx = ((y - 2) * 1536 + blockIdx.x)*256 + threadIdx.x;
        int c4i = idx % (VD/4);
        int row = idx / (VD/4);
        int c0  = c4i*4;
        int b = row >> 10, t = row & 1023;

        float w0[4], w1[4], w2[4], w3[4];
        *(float4*)w0 = *(const float4*)(Wv + (c0+0)*4);
        *(float4*)w1 = *(const float4*)(Wv + (c0+1)*4);
        *(float4*)w2 = *(const float4*)(Wv + (c0+2)*4);
        *(float4*)w3 = *(const float4*)(Wv + (c0+3)*4);

        float a[4] = {0.f, 0.f, 0.f, 0.f};
#pragma unroll
        for (int j = 0; j < 4; j++) {
            int tt = t - 3 + j;
            if (tt >= 0) {
                float4 xv = *(const float4*)(P + (size_t)(b*LL + tt)*NP + 2*KD + c0);
                a[0] += xv.x * w0[j];
                a[1] += xv.y * w1[j];
                a[2] += xv.z * w2[j];
                a[3] += xv.w * w3[j];
            }
        }
#pragma unroll
        for (int i = 0; i < 4; i++) { float z = a[i]; a[i] = z / (1.f + expf(-z)); }
        int h  = c0 / DV;
        int dv = c0 % DV;
        float4 o = make_float4(a[0], a[1], a[2], a[3]);
        *(float4*)(g_vc + ((size_t)(b*HH + h)*LL + t)*DV + dv) = o;
    }
}

// ---------------- delta-rule scan: f32x2-packed, 2 cols per thread -----------
#define TCH 32
#define VPC 16
__global__ void __launch_bounds__(128) scan_kernel(float* __restrict__ sOut)
{
    __shared__ float sk[TCH][DK];
    __shared__ float sq[TCH][DK];
    __shared__ float sv[TCH][VPC];
    __shared__ float se[TCH], sbt[TCH];

    int tid  = threadIdx.x;
    int wid  = tid >> 5, lane = tid & 31;
    int bh   = blockIdx.x / (DV/VPC);
    int vblk = (blockIdx.x % (DV/VPC)) * VPC;
    int half = lane >> 4, l16 = lane & 15;
    int lpair = wid*4 + half*2;
    int ko   = l16 * 8;

    int b = bh / HH, h = bh % HH;
    const float* kb = g_kn + (size_t)bh*LL*DK;
    const float* qb = g_qn + (size_t)bh*LL*DK;
    const float* vb = g_vc + (size_t)bh*LL*DV;
    const float* eb = g_eg + (size_t)bh*LL;
    const float* bb = g_beta + (size_t)bh*LL;
    float* ob = g_o + (size_t)b*LL*VD + h*DV + vblk + lpair;

    u64 sA[4], sB[4];
#pragma unroll
    for (int j = 0; j < 4; j++) { sA[j] = 0ull; sB[j] = 0ull; }

    for (int ch = 0; ch < LL/TCH; ch++) {
        int t0 = ch * TCH;
        __syncthreads();
#pragma unroll
        for (int i = tid; i < TCH*DK/4; i += 128) {
            ((float4*)sk)[i] = ((const float4*)(kb + (size_t)t0*DK))[i];
            ((float4*)sq)[i] = ((const float4*)(qb + (size_t)t0*DK))[i];
        }
        {
            int i = tid;
            int tl = i / (VPC/4), vq = (i % (VPC/4)) * 4;
            *(float4*)&sv[tl][vq] = *(const float4*)(vb + (size_t)(t0+tl)*DV + vblk + vq);
        }
        if (tid < TCH) { se[tid] = eb[t0+tid]; sbt[tid] = bb[t0+tid]; }
        __syncthreads();

#pragma unroll 4
        for (int tl = 0; tl < TCH; tl++) {
            const u64* kp = (const u64*)&sk[tl][ko];
            u64 k0 = kp[0], k1 = kp[1], k2 = kp[2], k3 = kp[3];
            float eg = se[tl], bt = sbt[tl];
            float vA = sv[tl][lpair], vB = sv[tl][lpair+1];
            u64 egp = pack2(eg, eg);
#pragma unroll
            for (int j = 0; j < 4; j++) { sA[j] = mul2(sA[j], egp); sB[j] = mul2(sB[j], egp); }

            u64 cap = mul2(k0, sA[0]); cap = fma2(k1, sA[1], cap);
            cap = fma2(k2, sA[2], cap); cap = fma2(k3, sA[3], cap);
            u64 cbp = mul2(k0, sB[0]); cbp = fma2(k1, sB[1], cbp);
            cbp = fma2(k2, sB[2], cbp); cbp = fma2(k3, sB[3], cbp);
            float cax, cay, cbx, cby;
            unpack2(cap, cax, cay); unpack2(cbp, cbx, cby);
            float cA = cax + cay, cB = cbx + cby;
#pragma unroll
            for (int off = 8; off; off >>= 1) {
                cA += __shfl_xor_sync(0xffffffffu, cA, off);
                cB += __shfl_xor_sync(0xffffffffu, cB, off);
            }
            float uA = (vA - cA) * bt;
            float uB = (vB - cB) * bt;
            u64 uap = pack2(uA, uA), ubp = pack2(uB, uB);
            sA[0] = fma2(k0, uap, sA[0]); sA[1] = fma2(k1, uap, sA[1]);
            sA[2] = fma2(k2, uap, sA[2]); sA[3] = fma2(k3, uap, sA[3]);
            sB[0] = fma2(k0, ubp, sB[0]); sB[1] = fma2(k1, ubp, sB[1]);
            sB[2] = fma2(k2, ubp, sB[2]); sB[3] = fma2(k3, ubp, sB[3]);

            const u64* qp = (const u64*)&sq[tl][ko];
            u64 q0 = qp[0], q1 = qp[1], q2 = qp[2], q3 = qp[3];
            u64 oap = mul2(q0, sA[0]); oap = fma2(q1, sA[1], oap);
            oap = fma2(q2, sA[2], oap); oap = fma2(q3, sA[3], oap);
            u64 obp = mul2(q0, sB[0]); obp = fma2(q1, sB[1], obp);
            obp = fma2(q2, sB[2], obp); obp = fma2(q3, sB[3], obp);
            float oax, oay, obx, oby;
            unpack2(oap, oax, oay); unpack2(obp, obx, oby);
            float oA = oax + oay, oB = obx + oby;
#pragma unroll
            for (int off = 8; off; off >>= 1) {
                oA += __shfl_xor_sync(0xffffffffu, oA, off);
                oB += __shfl_xor_sync(0xffffffffu, oB, off);
            }
            if (l16 == 0) {
                ob[(size_t)(t0+tl)*VD]     = oA;
                ob[(size_t)(t0+tl)*VD + 1] = oB;
            }
        }
    }

    if (sOut) {
        size_t base = (size_t)bh*DK*DV + vblk + lpair;
#pragma unroll
        for (int j = 0; j < 4; j++) {
            float a0, a1, b0, b1;
            unpack2(sA[j], a0, a1); unpack2(sB[j], b0, b1);
            sOut[base + (size_t)(ko+2*j)*DV]       = a0;
            sOut[base + (size_t)(ko+2*j+1)*DV]     = a1;
            sOut[base + (size_t)(ko+2*j)*DV + 1]   = b0;
            sOut[base + (size_t)(ko+2*j+1)*DV + 1] = b1;
        }
    }
}

// ---------------- gated RMS norm -> fp16 hi/lo -------------------------------
__global__ void __launch_bounds__(256) gate_kernel(
    const float* __restrict__ P, const float* __restrict__ norm_w)
{
    int gw   = blockIdx.x*8 + (threadIdx.x >> 5);
    int lane = threadIdx.x & 31;
    int row  = gw / HH;
    int h    = gw % HH;
    size_t base  = (size_t)row*VD + h*DV;
    size_t gbase = (size_t)row*NP + 2*KD + VD + h*DV;

    float4 o0 = *(float4*)(g_o + base + lane*4);
    float4 o1 = *(float4*)(g_o + base + 128 + lane*4);
    float ss = o0.x*o0.x + o0.y*o0.y + o0.z*o0.z + o0.w*o0.w
             + o1.x*o1.x + o1.y*o1.y + o1.z*o1.z + o1.w*o1.w;
#pragma unroll
    for (int off = 16; off; off >>= 1) ss += __shfl_xor_sync(0xffffffffu, ss, off);
    float r = rsqrtf(ss * (1.f/DV) + 1e-5f);

    float4 gt0 = *(const float4*)(P + gbase + lane*4);
    float4 gt1 = *(const float4*)(P + gbase + 128 + lane*4);
    float4 nw0 = *(const float4*)(norm_w + lane*4);
    float4 nw1 = *(const float4*)(norm_w + 128 + lane*4);

    float f[8];
    f[0] = o0.x * r * nw0.x * (gt0.x / (1.f + expf(-gt0.x)));
    f[1] = o0.y * r * nw0.y * (gt0.y / (1.f + expf(-gt0.y)));
    f[2] = o0.z * r * nw0.z * (gt0.z / (1.f + expf(-gt0.z)));
    f[3] = o0.w * r * nw0.w * (gt0.w / (1.f + expf(-gt0.w)));
    f[4] = o1.x * r * nw1.x * (gt1.x / (1.f + expf(-gt1.x)));
    f[5] = o1.y * r * nw1.y * (gt1.y / (1.f + expf(-gt1.y)));
    f[6] = o1.z * r * nw1.z * (gt1.z / (1.f + expf(-gt1.z)));
    f[7] = o1.w * r * nw1.w * (gt1.w / (1.f + expf(-gt1.w)));

#pragma unroll
    for (int hf = 0; hf < 2; hf++) {
        size_t off = base + hf*128 + lane*4;
        __half h0 = __float2half(f[hf*4+0]);
        __half h1 = __float2half(f[hf*4+1]);
        __half h2 = __float2half(f[hf*4+2]);
        __half h3 = __float2half(f[hf*4+3]);
        *(__half2*)(g_oh + off)     = __half2(h0, h1);
        *(__half2*)(g_oh + off + 2) = __half2(h2, h3);
        __half l0 = __float2half(f[hf*4+0] - __half2float(h0));
        __half l1 = __float2half(f[hf*4+1] - __half2float(h1));
        __half l2 = __float2half(f[hf*4+2] - __half2float(h2));
        __half l3 = __float2half(f[hf*4+3] - __half2float(h3));
        *(__half2*)(g_ol + off)     = __half2(l0, l1);
        *(__half2*)(g_ol + off + 2) = __half2(l2, l3);
    }
}

// ---------------- launcher ---------------------------------------------------
extern "C" void kernel_launch(void* const* d_in, const int* in_sizes, int n_in,
                              void* d_out, int out_size)
{
    const float* x       = (const float*)d_in[0];
    const float* Wq      = (const float*)d_in[1];
    const float* Wk      = (const float*)d_in[2];
    const float* Wv      = (const float*)d_in[3];
    const float* Wb      = (const float*)d_in[4];
    const float* Wa      = (const float*)d_in[5];
    const float* A_log   = (const float*)d_in[6];
    const float* dt_bias = (const float*)d_in[7];
    const float* conv_q  = (const float*)d_in[8];
    const float* conv_k  = (const float*)d_in[9];
    const float* conv_v  = (const float*)d_in[10];
    const float* Wg      = (const float*)d_in[11];
    const float* norm_w  = (const float*)d_in[12];
    const float* Wo      = (const float*)d_in[13];
    float* out = (float*)d_out;

    float *pproj, *pqn, *pkn;
    cudaGetSymbolAddress((void**)&pproj, g_proj);
    cudaGetSymbolAddress((void**)&pqn, g_qn);
    cudaGetSymbolAddress((void**)&pkn, g_kn);

    __half *xh, *xl, *wc, *wo, *oh, *ol;
    cudaGetSymbolAddress((void**)&xh, g_xh);  cudaGetSymbolAddress((void**)&xl, g_xl);
    cudaGetSymbolAddress((void**)&wc, g_wc);  cudaGetSymbolAddress((void**)&wo, g_wo);
    cudaGetSymbolAddress((void**)&oh, g_oh);  cudaGetSymbolAddress((void**)&ol, g_ol);

    const int GEMM_SMEM  = 3 * 24576;
    const int GEMM_SMEMW = 3 * 32768;
    cudaFuncSetAttribute(gemm_mma_fp16x2,
                         cudaFuncAttributeMaxDynamicSharedMemorySize, GEMM_SMEM);
    cudaFuncSetAttribute(gemm_mma_fp16x2_wide,
                         cudaFuncAttributeMaxDynamicSharedMemorySize, GEMM_SMEMW);

    dim3 blk(256);
    splitx_kernel<<<TOK*DD/(256*4), blk>>>(x);
    wsplit_all<<<6144, blk>>>(Wq, Wk, Wv, Wg, Wo);
    betag_kernel<<<TOK/16, 512>>>(x, Wb, Wa, A_log, dt_bias);
    // fused projection GEMM on wide tiles (4th launch — profiler target)
    gemm_mma_fp16x2_wide<<<dim3(NP/256, TOK/128), blk, GEMM_SMEMW>>>(xh, xl, wc, pproj, TOK, NP, DD);
    conv_all<<<dim3(1536, 4), blk>>>(pproj, conv_q, conv_k, conv_v, pqn, pkn);
    float* sOut = (out_size >= TOK*DD + BB*HH*DK*DV) ? (out + (size_t)TOK*DD) : nullptr;
    scan_kernel<<<BB*HH*(DV/VPC), 128>>>(sOut);
    gate_kernel<<<TOK*HH/8, blk>>>(pproj, norm_w);
    gemm_mma_fp16x2<<<dim3(DD/128, TOK/128), blk, GEMM_SMEM>>>(oh, ol, wo, out, TOK, DD, VD);
}